// round 1
// baseline (speedup 1.0000x reference)
#include <cuda_runtime.h>
#include <math.h>

#define B_   2
#define S_   2048
#define HID_ 2048
#define NH_  32
#define G_   4
#define HD_  64
#define HKV_ 8
#define NQK_ 512   // HKV_*HD_

// Scratch (device globals: no allocation allowed)
__device__ float g_Q[(size_t)B_*S_*NQK_];
__device__ float g_K[(size_t)B_*S_*NQK_];
__device__ float g_V[(size_t)B_*S_*HID_];

// ---------------------------------------------------------------------------
// Tiled FP32 GEMM: C[M,N] = A[M,K] @ B[K,N].  BM=BN=128, BK=8, 8x8 microtile.
// ---------------------------------------------------------------------------
__global__ __launch_bounds__(256)
void gemm128_kernel(const float* __restrict__ A, const float* __restrict__ Bm,
                    float* __restrict__ C, int M, int N, int K) {
    const int BM = 128, BN = 128, BK = 8, TM = 8, TN = 8;
    __shared__ float As[BK * BM];  // transposed: As[k][m]
    __shared__ float Bs[BK * BN];  // Bs[k][n]

    const int tid = threadIdx.x;
    const int ty  = tid / (BN / TN);   // 0..15
    const int tx  = tid % (BN / TN);   // 0..15
    const int bm0 = blockIdx.y * BM;
    const int bn0 = blockIdx.x * BN;

    float acc[TM][TN];
    #pragma unroll
    for (int i = 0; i < TM; i++)
        #pragma unroll
        for (int j = 0; j < TN; j++) acc[i][j] = 0.f;

    for (int k0 = 0; k0 < K; k0 += BK) {
        // Load A tile (BM x BK), store transposed
        #pragma unroll
        for (int i = 0; i < (BM * BK) / 256; i++) {
            int idx = tid + i * 256;
            int row = idx / BK, col = idx % BK;
            As[col * BM + row] = A[(size_t)(bm0 + row) * K + k0 + col];
        }
        // Load B tile (BK x BN)
        #pragma unroll
        for (int i = 0; i < (BK * BN) / 256; i++) {
            int idx = tid + i * 256;
            int kk = idx / BN, n = idx % BN;
            Bs[kk * BN + n] = Bm[(size_t)(k0 + kk) * N + bn0 + n];
        }
        __syncthreads();

        #pragma unroll
        for (int kk = 0; kk < BK; kk++) {
            float rA[TM], rB[TN];
            #pragma unroll
            for (int i = 0; i < TM; i++) rA[i] = As[kk * BM + ty * TM + i];
            #pragma unroll
            for (int j = 0; j < TN; j++) rB[j] = Bs[kk * BN + tx * TN + j];
            #pragma unroll
            for (int i = 0; i < TM; i++)
                #pragma unroll
                for (int j = 0; j < TN; j++)
                    acc[i][j] += rA[i] * rB[j];
        }
        __syncthreads();
    }

    #pragma unroll
    for (int i = 0; i < TM; i++) {
        size_t rowbase = (size_t)(bm0 + ty * TM + i) * N + bn0 + tx * TN;
        #pragma unroll
        for (int j = 0; j < TN; j += 4) {
            float4 v = make_float4(acc[i][j], acc[i][j+1], acc[i][j+2], acc[i][j+3]);
            *reinterpret_cast<float4*>(&C[rowbase + j]) = v;
        }
    }
}

// ---------------------------------------------------------------------------
// RoPE applied in place to g_Q / g_K  ([B*S, HKV*64] layout)
// out[d]    = x[d]*cos - x[d+32]*sin
// out[d+32] = x[d+32]*cos + x[d]*sin,  cos/sin of pos * theta^(-d/32)
// ---------------------------------------------------------------------------
__global__ void rope_kernel(float* __restrict__ Q, float* __restrict__ K,
                            const int* __restrict__ pos_ids) {
    int idx = blockIdx.x * blockDim.x + threadIdx.x;     // B*S*HKV*32 total
    if (idx >= B_ * S_ * HKV_ * 32) return;
    int d   = idx & 31;
    int h   = (idx >> 5) & (HKV_ - 1);
    int row = idx >> 8;                                  // b*S + s
    float p    = (float)pos_ids[row];
    float invf = powf(10000.0f, -(float)d * (1.0f / 32.0f));
    float a = p * invf;
    float sn, cs;
    sincosf(a, &sn, &cs);
    size_t base = (size_t)row * NQK_ + h * HD_;
    float q0 = Q[base + d], q1 = Q[base + d + 32];
    Q[base + d]      = q0 * cs - q1 * sn;
    Q[base + d + 32] = q1 * cs + q0 * sn;
    float k0 = K[base + d], k1 = K[base + d + 32];
    K[base + d]      = k0 * cs - k1 * sn;
    K[base + d + 32] = k1 * cs + k0 * sn;
}

// ---------------------------------------------------------------------------
// Causal flash attention. One block per (q-tile of 64 rows, kv-head h, batch b).
// Probs shared across G=4 groups; PV accumulates the 4 group V-heads (256 cols).
// ---------------------------------------------------------------------------
#define PIT 65
#define ATTN_SMEM_FLOATS (3 * 64 * PIT + 64 * 256 + 3 * 64)

__global__ __launch_bounds__(256, 1)
void attn_kernel(const float* __restrict__ Q, const float* __restrict__ K,
                 const float* __restrict__ V, float* __restrict__ Out) {
    extern __shared__ float sm[];
    float* Qs   = sm;                 // 64 x PIT
    float* Ks   = Qs + 64 * PIT;      // 64 x PIT
    float* Ps   = Ks + 64 * PIT;      // 64 x PIT (scores -> probs)
    float* Vs   = Ps + 64 * PIT;      // 64 x 256
    float* mrow = Vs + 64 * 256;      // 64
    float* lrow = mrow + 64;          // 64
    float* sfac = lrow + 64;          // 64

    const int tid = threadIdx.x;
    const int b  = blockIdx.z;
    const int h  = blockIdx.y;
    const int qb = blockIdx.x;
    const int q0 = qb * 64;

    // Load Q tile (pre-scaled by 1/sqrt(64) = 0.125 exactly)
    #pragma unroll
    for (int i = 0; i < 16; i++) {
        int idx = tid + i * 256;
        int r = idx >> 6, d = idx & 63;
        Qs[r * PIT + d] = Q[((size_t)(b * S_ + q0 + r)) * NQK_ + h * HD_ + d] * 0.125f;
    }
    if (tid < 64) { mrow[tid] = -INFINITY; lrow[tid] = 0.f; }

    const int r  = tid & 63;   // output row owned by this thread
    const int cg = tid >> 6;   // which 64-col group of the 256 PV cols
    float acc[64];
    #pragma unroll
    for (int i = 0; i < 64; i++) acc[i] = 0.f;

    const float4* V4 = reinterpret_cast<const float4*>(V);
    float4* Vs4 = reinterpret_cast<float4*>(Vs);

    for (int kt = 0; kt <= qb; kt++) {
        const int k0 = kt * 64;
        __syncthreads();   // prior-iter Ps/Vs consumers done (also covers Q load)

        // Load K tile
        #pragma unroll
        for (int i = 0; i < 16; i++) {
            int idx = tid + i * 256;
            int kk = idx >> 6, d = idx & 63;
            Ks[kk * PIT + d] = K[((size_t)(b * S_ + k0 + kk)) * NQK_ + h * HD_ + d];
        }
        // Load V tile: Vs[kk][g*64+d] = V[b, k0+kk, g*8+h, d]   (float4)
        #pragma unroll
        for (int i = 0; i < 16; i++) {
            int idx = tid + i * 256;        // 0..4095 (float4 units)
            int kk = idx >> 6;
            int c4 = idx & 63;              // float4 col 0..63
            int g  = c4 >> 4, d4 = c4 & 15;
            Vs4[kk * 64 + c4] =
                V4[((size_t)(b * S_ + k0 + kk)) * (HID_ / 4) + g * (NQK_ / 4) + h * (HD_ / 4) + d4];
        }
        __syncthreads();

        // Scores: Ps[r][k] = Qs[r] . Ks[k]   (4x4 microtile per thread)
        {
            const int sty = tid >> 4, stx = tid & 15;
            float sa[4][4];
            #pragma unroll
            for (int i = 0; i < 4; i++)
                #pragma unroll
                for (int j = 0; j < 4; j++) sa[i][j] = 0.f;
            #pragma unroll
            for (int d = 0; d < 64; d++) {
                float qa[4], kb[4];
                #pragma unroll
                for (int i = 0; i < 4; i++) qa[i] = Qs[(sty * 4 + i) * PIT + d];
                #pragma unroll
                for (int j = 0; j < 4; j++) kb[j] = Ks[(stx * 4 + j) * PIT + d];
                #pragma unroll
                for (int i = 0; i < 4; i++)
                    #pragma unroll
                    for (int j = 0; j < 4; j++)
                        sa[i][j] += qa[i] * kb[j];
            }
            #pragma unroll
            for (int i = 0; i < 4; i++)
                #pragma unroll
                for (int j = 0; j < 4; j++)
                    Ps[(sty * 4 + i) * PIT + stx * 4 + j] = sa[i][j];
        }
        __syncthreads();

        // Online softmax update (one thread per row)
        if (tid < 64) {
            const int row = tid;
            const int kmax = (kt == qb) ? row : 63;   // causal: k0+k <= q0+row
            float m_old = mrow[row];
            float mx = m_old;
            for (int k = 0; k <= kmax; k++) mx = fmaxf(mx, Ps[row * PIT + k]);
            float sum = 0.f;
            for (int k = 0; k < 64; k++) {
                float p = (k <= kmax) ? expf(Ps[row * PIT + k] - mx) : 0.f;
                Ps[row * PIT + k] = p;
                sum += p;
            }
            float f = expf(m_old - mx);   // 0 on first tile (m_old = -inf)
            sfac[row] = f;
            lrow[row] = lrow[row] * f + sum;
            mrow[row] = mx;
        }
        __syncthreads();

        // Rescale + PV accumulate: acc[c] += sum_k P[r][k] * Vs[k][cg*64 + c]
        {
            float f = sfac[r];
            #pragma unroll
            for (int i = 0; i < 64; i++) acc[i] *= f;
            #pragma unroll 4
            for (int k = 0; k < 64; k++) {
                float p = Ps[r * PIT + k];
                #pragma unroll
                for (int d4 = 0; d4 < 16; d4++) {
                    float4 v = Vs4[k * 64 + cg * 16 + d4];   // warp-broadcast address
                    acc[d4 * 4 + 0] += p * v.x;
                    acc[d4 * 4 + 1] += p * v.y;
                    acc[d4 * 4 + 2] += p * v.z;
                    acc[d4 * 4 + 3] += p * v.w;
                }
            }
        }
    }
    __syncthreads();

    // Normalize and write: out[b, q0+r, cg*8+h, :]
    const float invl = 1.f / lrow[r];
    size_t obase = ((size_t)(b * S_ + q0 + r)) * HID_ + (cg * HKV_ + h) * HD_;
    #pragma unroll
    for (int d4 = 0; d4 < 16; d4++) {
        float4 o = make_float4(acc[d4*4+0]*invl, acc[d4*4+1]*invl,
                               acc[d4*4+2]*invl, acc[d4*4+3]*invl);
        *reinterpret_cast<float4*>(&Out[obase + d4 * 4]) = o;
    }
}

// ---------------------------------------------------------------------------
extern "C" void kernel_launch(void* const* d_in, const int* in_sizes, int n_in,
                              void* d_out, int out_size) {
    const float* X   = (const float*)d_in[0];   // [B,S,HID]
    const int*   pid = (const int*)  d_in[1];   // [B,S]
    const float* Wq  = (const float*)d_in[2];   // [HID, 512]
    const float* Wk  = (const float*)d_in[3];   // [HID, 512]
    const float* Wv  = (const float*)d_in[4];   // [HID, 2048]
    float* Out = (float*)d_out;

    float *dQ, *dK, *dV;
    cudaGetSymbolAddress((void**)&dQ, g_Q);
    cudaGetSymbolAddress((void**)&dK, g_K);
    cudaGetSymbolAddress((void**)&dV, g_V);

    const int M = B_ * S_;   // 4096

    // Projections
    {
        dim3 blk(256);
        dim3 grdQ(NQK_ / 128, M / 128);
        gemm128_kernel<<<grdQ, blk>>>(X, Wq, dQ, M, NQK_, HID_);
        gemm128_kernel<<<grdQ, blk>>>(X, Wk, dK, M, NQK_, HID_);
        dim3 grdV(HID_ / 128, M / 128);
        gemm128_kernel<<<grdV, blk>>>(X, Wv, dV, M, HID_, HID_);
    }

    // RoPE on Q and K
    {
        int total = B_ * S_ * HKV_ * 32;
        rope_kernel<<<(total + 255) / 256, 256>>>(dQ, dK, pid);
    }

    // Attention
    {
        size_t smem = ATTN_SMEM_FLOATS * sizeof(float);
        cudaFuncSetAttribute(attn_kernel, cudaFuncAttributeMaxDynamicSharedMemorySize,
                             (int)smem);
        dim3 grd(S_ / 64, HKV_, B_);
        attn_kernel<<<grd, 256, smem>>>(dQ, dK, dV, Out);
    }
}

// round 3
// speedup vs baseline: 1.7251x; 1.7251x over previous
#include <cuda_runtime.h>
#include <cuda_bf16.h>
#include <math.h>
#include <stdint.h>

#define B_   2
#define S_   2048
#define HID_ 2048
#define NH_  32
#define G_   4
#define HD_  64
#define HKV_ 8
#define NQK_ 512   // HKV_*HD_

// Scratch (device globals: no allocation allowed)
__device__ float g_Q[(size_t)B_*S_*NQK_];
__device__ float g_K[(size_t)B_*S_*NQK_];
__device__ float g_V[(size_t)B_*S_*HID_];

// ===========================================================================
// helpers
// ===========================================================================
__device__ __forceinline__ uint32_t smem_to_u32(const void* smem_ptr) {
    uint32_t addr;
    asm("{ .reg .u64 tmp; cvta.to.shared.u64 tmp, %1; cvt.u32.u64 %0, tmp; }"
        : "=r"(addr) : "l"(smem_ptr));
    return addr;
}

// pack two f32 -> bf16x2 (lo = a, hi = b), round-to-nearest
__device__ __forceinline__ uint32_t pack_bf2(float a, float b) {
    uint32_t r;
    asm("cvt.rn.bf16x2.f32 %0, %1, %2;" : "=r"(r) : "f"(b), "f"(a));
    return r;
}
__device__ __forceinline__ float bf_lo_f32(uint32_t h) { return __uint_as_float(h << 16); }
__device__ __forceinline__ float bf_hi_f32(uint32_t h) { return __uint_as_float(h & 0xFFFF0000u); }

__device__ __forceinline__ void ldmx4(uint32_t r[4], uint32_t addr) {
    asm volatile("ldmatrix.sync.aligned.m8n8.x4.shared.b16 {%0,%1,%2,%3}, [%4];"
        : "=r"(r[0]), "=r"(r[1]), "=r"(r[2]), "=r"(r[3]) : "r"(addr));
}
__device__ __forceinline__ void ldmx2t(uint32_t r[2], uint32_t addr) {
    asm volatile("ldmatrix.sync.aligned.m8n8.x2.trans.shared.b16 {%0,%1}, [%2];"
        : "=r"(r[0]), "=r"(r[1]) : "r"(addr));
}
__device__ __forceinline__ void mma16816(float d[4], const uint32_t a[4],
                                         const uint32_t b[2]) {
    asm volatile(
        "mma.sync.aligned.m16n8k16.row.col.f32.bf16.bf16.f32 "
        "{%0,%1,%2,%3}, {%4,%5,%6,%7}, {%8,%9}, {%0,%1,%2,%3};"
        : "+f"(d[0]), "+f"(d[1]), "+f"(d[2]), "+f"(d[3])
        : "r"(a[0]), "r"(a[1]), "r"(a[2]), "r"(a[3]), "r"(b[0]), "r"(b[1]));
}

// ===========================================================================
// mma.sync GEMM: C[M,N] = A[M,K] @ W[K,N], fp32 in/out, split-bf16 3x.
// CTA tile 128x128, K-chunk 32, 8 warps (4m x 2n), warp tile 32x64.
// As: [128][SA] bf16 (row m, col k), Bs: [32][SB] bf16 (row k, col n).
// ===========================================================================
#define SA 40    // padded stride (bf16 elems): 80B -> conflict-free ldmatrix
#define SB 136   // padded stride: 272B -> conflict-free ldmatrix
#define AHI_OFF 0
#define ALO_OFF (128 * SA * 2)                  // 10240
#define BHI_OFF (2 * 128 * SA * 2)              // 20480
#define BLO_OFF (2 * 128 * SA * 2 + 32 * SB * 2) // 29184
#define GEMM_SMEM (2 * 128 * SA * 2 + 2 * 32 * SB * 2)  // 37888

__global__ __launch_bounds__(256, 2)
void gemm_mma_kernel(const float* __restrict__ A, const float* __restrict__ W,
                     float* __restrict__ C, int M, int N, int K) {
    extern __shared__ char sm[];
    const uint32_t smb = smem_to_u32(sm);
    const int tid = threadIdx.x, lane = tid & 31, wid = tid >> 5;
    const int wm = wid >> 1, wn = wid & 1;
    const int m0 = blockIdx.y * 128, n0 = blockIdx.x * 128;

    float acc[2][8][4];
    #pragma unroll
    for (int i = 0; i < 2; i++)
        #pragma unroll
        for (int j = 0; j < 8; j++)
            #pragma unroll
            for (int t = 0; t < 4; t++) acc[i][j][t] = 0.f;

    // ldmatrix lane addressing
    const uint32_t aRow  = lane & 15;            // m row within 16
    const uint32_t aColH = (lane >> 4) * 8;      // k half
    const uint32_t bRow  = lane & 15;            // k row within 16

    const int nch = K >> 5;
    for (int c = 0; c < nch; c++) {
        const int k0 = c << 5;
        __syncthreads();   // previous chunk's compute done

        // ---- A tile: 128 x 32 fp32 -> bf16 hi/lo ----
        #pragma unroll
        for (int i = 0; i < 4; i++) {
            int idx = tid + (i << 8);
            int row = idx >> 3, c4 = idx & 7;
            float4 v = *reinterpret_cast<const float4*>(
                A + (size_t)(m0 + row) * K + k0 + (c4 << 2));
            uint32_t h0 = pack_bf2(v.x, v.y), h1 = pack_bf2(v.z, v.w);
            uint32_t l0 = pack_bf2(v.x - bf_lo_f32(h0), v.y - bf_hi_f32(h0));
            uint32_t l1 = pack_bf2(v.z - bf_lo_f32(h1), v.w - bf_hi_f32(h1));
            uint32_t off = (row * SA + (c4 << 2)) * 2;
            *reinterpret_cast<uint2*>(sm + AHI_OFF + off) = make_uint2(h0, h1);
            *reinterpret_cast<uint2*>(sm + ALO_OFF + off) = make_uint2(l0, l1);
        }
        // ---- B tile: 32 x 128 fp32 -> bf16 hi/lo (kept [k][n]) ----
        #pragma unroll
        for (int i = 0; i < 4; i++) {
            int idx = tid + (i << 8);
            int kr = idx >> 5, nf4 = idx & 31;
            float4 v = *reinterpret_cast<const float4*>(
                W + (size_t)(k0 + kr) * N + n0 + (nf4 << 2));
            uint32_t h0 = pack_bf2(v.x, v.y), h1 = pack_bf2(v.z, v.w);
            uint32_t l0 = pack_bf2(v.x - bf_lo_f32(h0), v.y - bf_hi_f32(h0));
            uint32_t l1 = pack_bf2(v.z - bf_lo_f32(h1), v.w - bf_hi_f32(h1));
            uint32_t off = (kr * SB + (nf4 << 2)) * 2;
            *reinterpret_cast<uint2*>(sm + BHI_OFF + off) = make_uint2(h0, h1);
            *reinterpret_cast<uint2*>(sm + BLO_OFF + off) = make_uint2(l0, l1);
        }
        __syncthreads();

        // ---- compute: 2 k-steps of 16 ----
        #pragma unroll
        for (int ks = 0; ks < 2; ks++) {
            uint32_t aH[2][4], aL[2][4];
            #pragma unroll
            for (int mf = 0; mf < 2; mf++) {
                uint32_t ao = ((wm * 32 + mf * 16 + aRow) * SA + ks * 16 + aColH) * 2;
                ldmx4(aH[mf], smb + AHI_OFF + ao);
                ldmx4(aL[mf], smb + ALO_OFF + ao);
            }
            #pragma unroll
            for (int nf = 0; nf < 8; nf++) {
                uint32_t bH[2], bL[2];
                uint32_t bo = ((ks * 16 + bRow) * SB + wn * 64 + nf * 8) * 2;
                ldmx2t(bH, smb + BHI_OFF + bo);
                ldmx2t(bL, smb + BLO_OFF + bo);
                #pragma unroll
                for (int mf = 0; mf < 2; mf++) {
                    mma16816(acc[mf][nf], aH[mf], bH);
                    mma16816(acc[mf][nf], aL[mf], bH);
                    mma16816(acc[mf][nf], aH[mf], bL);
                }
            }
        }
    }

    // ---- epilogue: direct float2 stores ----
    #pragma unroll
    for (int mf = 0; mf < 2; mf++) {
        int row = m0 + wm * 32 + mf * 16 + (lane >> 2);
        #pragma unroll
        for (int nf = 0; nf < 8; nf++) {
            int col = n0 + wn * 64 + nf * 8 + (lane & 3) * 2;
            *reinterpret_cast<float2*>(C + (size_t)row * N + col) =
                make_float2(acc[mf][nf][0], acc[mf][nf][1]);
            *reinterpret_cast<float2*>(C + (size_t)(row + 8) * N + col) =
                make_float2(acc[mf][nf][2], acc[mf][nf][3]);
        }
    }
}

// ---------------------------------------------------------------------------
// RoPE applied in place to g_Q / g_K  ([B*S, HKV*64] layout)
// ---------------------------------------------------------------------------
__global__ void rope_kernel(float* __restrict__ Q, float* __restrict__ K,
                            const int* __restrict__ pos_ids) {
    int idx = blockIdx.x * blockDim.x + threadIdx.x;     // B*S*HKV*32 total
    if (idx >= B_ * S_ * HKV_ * 32) return;
    int d   = idx & 31;
    int h   = (idx >> 5) & (HKV_ - 1);
    int row = idx >> 8;                                  // b*S + s
    float p    = (float)pos_ids[row];
    float invf = powf(10000.0f, -(float)d * (1.0f / 32.0f));
    float a = p * invf;
    float sn, cs;
    sincosf(a, &sn, &cs);
    size_t base = (size_t)row * NQK_ + h * HD_;
    float q0 = Q[base + d], q1 = Q[base + d + 32];
    Q[base + d]      = q0 * cs - q1 * sn;
    Q[base + d + 32] = q1 * cs + q0 * sn;
    float k0 = K[base + d], k1 = K[base + d + 32];
    K[base + d]      = k0 * cs - k1 * sn;
    K[base + d + 32] = k1 * cs + k0 * sn;
}

// ---------------------------------------------------------------------------
// Causal flash attention (unchanged). One block per (q-tile, kv-head, b).
// ---------------------------------------------------------------------------
#define PIT 65
#define ATTN_SMEM_FLOATS (3 * 64 * PIT + 64 * 256 + 3 * 64)

__global__ __launch_bounds__(256, 1)
void attn_kernel(const float* __restrict__ Q, const float* __restrict__ K,
                 const float* __restrict__ V, float* __restrict__ Out) {
    extern __shared__ float smf[];
    float* Qs   = smf;
    float* Ks   = Qs + 64 * PIT;
    float* Ps   = Ks + 64 * PIT;
    float* Vs   = Ps + 64 * PIT;
    float* mrow = Vs + 64 * 256;
    float* lrow = mrow + 64;
    float* sfac = lrow + 64;

    const int tid = threadIdx.x;
    const int b  = blockIdx.z;
    const int h  = blockIdx.y;
    const int qb = blockIdx.x;
    const int q0 = qb * 64;

    #pragma unroll
    for (int i = 0; i < 16; i++) {
        int idx = tid + i * 256;
        int r = idx >> 6, d = idx & 63;
        Qs[r * PIT + d] = Q[((size_t)(b * S_ + q0 + r)) * NQK_ + h * HD_ + d] * 0.125f;
    }
    if (tid < 64) { mrow[tid] = -INFINITY; lrow[tid] = 0.f; }

    const int r  = tid & 63;
    const int cg = tid >> 6;
    float acc[64];
    #pragma unroll
    for (int i = 0; i < 64; i++) acc[i] = 0.f;

    const float4* V4 = reinterpret_cast<const float4*>(V);
    float4* Vs4 = reinterpret_cast<float4*>(Vs);

    for (int kt = 0; kt <= qb; kt++) {
        const int k0 = kt * 64;
        __syncthreads();

        #pragma unroll
        for (int i = 0; i < 16; i++) {
            int idx = tid + i * 256;
            int kk = idx >> 6, d = idx & 63;
            Ks[kk * PIT + d] = K[((size_t)(b * S_ + k0 + kk)) * NQK_ + h * HD_ + d];
        }
        #pragma unroll
        for (int i = 0; i < 16; i++) {
            int idx = tid + i * 256;
            int kk = idx >> 6;
            int c4 = idx & 63;
            int g  = c4 >> 4, d4 = c4 & 15;
            Vs4[kk * 64 + c4] =
                V4[((size_t)(b * S_ + k0 + kk)) * (HID_ / 4) + g * (NQK_ / 4) + h * (HD_ / 4) + d4];
        }
        __syncthreads();

        {
            const int sty = tid >> 4, stx = tid & 15;
            float sa[4][4];
            #pragma unroll
            for (int i = 0; i < 4; i++)
                #pragma unroll
                for (int j = 0; j < 4; j++) sa[i][j] = 0.f;
            #pragma unroll
            for (int d = 0; d < 64; d++) {
                float qa[4], kb[4];
                #pragma unroll
                for (int i = 0; i < 4; i++) qa[i] = Qs[(sty * 4 + i) * PIT + d];
                #pragma unroll
                for (int j = 0; j < 4; j++) kb[j] = Ks[(stx * 4 + j) * PIT + d];
                #pragma unroll
                for (int i = 0; i < 4; i++)
                    #pragma unroll
                    for (int j = 0; j < 4; j++)
                        sa[i][j] += qa[i] * kb[j];
            }
            #pragma unroll
            for (int i = 0; i < 4; i++)
                #pragma unroll
                for (int j = 0; j < 4; j++)
                    Ps[(sty * 4 + i) * PIT + stx * 4 + j] = sa[i][j];
        }
        __syncthreads();

        if (tid < 64) {
            const int row = tid;
            const int kmax = (kt == qb) ? row : 63;
            float m_old = mrow[row];
            float mx = m_old;
            for (int k = 0; k <= kmax; k++) mx = fmaxf(mx, Ps[row * PIT + k]);
            float sum = 0.f;
            for (int k = 0; k < 64; k++) {
                float p = (k <= kmax) ? expf(Ps[row * PIT + k] - mx) : 0.f;
                Ps[row * PIT + k] = p;
                sum += p;
            }
            float f = expf(m_old - mx);
            sfac[row] = f;
            lrow[row] = lrow[row] * f + sum;
            mrow[row] = mx;
        }
        __syncthreads();

        {
            float f = sfac[r];
            #pragma unroll
            for (int i = 0; i < 64; i++) acc[i] *= f;
            #pragma unroll 4
            for (int k = 0; k < 64; k++) {
                float p = Ps[r * PIT + k];
                #pragma unroll
                for (int d4 = 0; d4 < 16; d4++) {
                    float4 v = Vs4[k * 64 + cg * 16 + d4];
                    acc[d4 * 4 + 0] += p * v.x;
                    acc[d4 * 4 + 1] += p * v.y;
                    acc[d4 * 4 + 2] += p * v.z;
                    acc[d4 * 4 + 3] += p * v.w;
                }
            }
        }
    }
    __syncthreads();

    const float invl = 1.f / lrow[r];
    size_t obase = ((size_t)(b * S_ + q0 + r)) * HID_ + (cg * HKV_ + h) * HD_;
    #pragma unroll
    for (int d4 = 0; d4 < 16; d4++) {
        float4 o = make_float4(acc[d4*4+0]*invl, acc[d4*4+1]*invl,
                               acc[d4*4+2]*invl, acc[d4*4+3]*invl);
        *reinterpret_cast<float4*>(&Out[obase + d4 * 4]) = o;
    }
}

// ---------------------------------------------------------------------------
extern "C" void kernel_launch(void* const* d_in, const int* in_sizes, int n_in,
                              void* d_out, int out_size) {
    const float* X   = (const float*)d_in[0];   // [B,S,HID]
    const int*   pid = (const int*)  d_in[1];   // [B,S]
    const float* Wq  = (const float*)d_in[2];   // [HID, 512]
    const float* Wk  = (const float*)d_in[3];   // [HID, 512]
    const float* Wv  = (const float*)d_in[4];   // [HID, 2048]
    float* Out = (float*)d_out;

    float *dQ, *dK, *dV;
    cudaGetSymbolAddress((void**)&dQ, g_Q);
    cudaGetSymbolAddress((void**)&dK, g_K);
    cudaGetSymbolAddress((void**)&dV, g_V);

    const int M = B_ * S_;   // 4096

    // Projections on mma.sync bf16 (split-bf16 3x)
    {
        cudaFuncSetAttribute(gemm_mma_kernel,
                             cudaFuncAttributeMaxDynamicSharedMemorySize, GEMM_SMEM);
        dim3 blk(256);
        dim3 grdQ(NQK_ / 128, M / 128);
        gemm_mma_kernel<<<grdQ, blk, GEMM_SMEM>>>(X, Wq, dQ, M, NQK_, HID_);
        gemm_mma_kernel<<<grdQ, blk, GEMM_SMEM>>>(X, Wk, dK, M, NQK_, HID_);
        dim3 grdV(HID_ / 128, M / 128);
        gemm_mma_kernel<<<grdV, blk, GEMM_SMEM>>>(X, Wv, dV, M, HID_, HID_);
    }

    // RoPE on Q and K
    {
        int total = B_ * S_ * HKV_ * 32;
        rope_kernel<<<(total + 255) / 256, 256>>>(dQ, dK, pid);
    }

    // Attention
    {
        size_t smem = ATTN_SMEM_FLOATS * sizeof(float);
        cudaFuncSetAttribute(attn_kernel, cudaFuncAttributeMaxDynamicSharedMemorySize,
                             (int)smem);
        dim3 grd(S_ / 64, HKV_, B_);
        attn_kernel<<<grd, 256, smem>>>(dQ, dK, dV, Out);
    }
}

// round 4
// speedup vs baseline: 2.6484x; 1.5352x over previous
#include <cuda_runtime.h>
#include <cuda_bf16.h>
#include <math.h>
#include <stdint.h>

#define B_   2
#define S_   2048
#define HID_ 2048
#define NH_  32
#define G_   4
#define HD_  64
#define HKV_ 8
#define NQK_ 512   // HKV_*HD_

// Scratch (device globals: no allocation allowed)
__device__ float g_Q[(size_t)B_*S_*NQK_];
__device__ float g_K[(size_t)B_*S_*NQK_];
__device__ float g_V[(size_t)B_*S_*HID_];

// ===========================================================================
// helpers
// ===========================================================================
__device__ __forceinline__ uint32_t smem_to_u32(const void* smem_ptr) {
    uint32_t addr;
    asm("{ .reg .u64 tmp; cvta.to.shared.u64 tmp, %1; cvt.u32.u64 %0, tmp; }"
        : "=r"(addr) : "l"(smem_ptr));
    return addr;
}
// pack two f32 -> bf16x2 (lo = a, hi = b), round-to-nearest
__device__ __forceinline__ uint32_t pack_bf2(float a, float b) {
    uint32_t r;
    asm("cvt.rn.bf16x2.f32 %0, %1, %2;" : "=r"(r) : "f"(b), "f"(a));
    return r;
}
__device__ __forceinline__ float bf_lo_f32(uint32_t h) { return __uint_as_float(h << 16); }
__device__ __forceinline__ float bf_hi_f32(uint32_t h) { return __uint_as_float(h & 0xFFFF0000u); }

__device__ __forceinline__ void ldmx4(uint32_t r[4], uint32_t addr) {
    asm volatile("ldmatrix.sync.aligned.m8n8.x4.shared.b16 {%0,%1,%2,%3}, [%4];"
        : "=r"(r[0]), "=r"(r[1]), "=r"(r[2]), "=r"(r[3]) : "r"(addr));
}
__device__ __forceinline__ void ldmx4t(uint32_t r[4], uint32_t addr) {
    asm volatile("ldmatrix.sync.aligned.m8n8.x4.trans.shared.b16 {%0,%1,%2,%3}, [%4];"
        : "=r"(r[0]), "=r"(r[1]), "=r"(r[2]), "=r"(r[3]) : "r"(addr));
}
__device__ __forceinline__ void ldmx2t(uint32_t r[2], uint32_t addr) {
    asm volatile("ldmatrix.sync.aligned.m8n8.x2.trans.shared.b16 {%0,%1}, [%2];"
        : "=r"(r[0]), "=r"(r[1]) : "r"(addr));
}
__device__ __forceinline__ void mma16816(float d[4], const uint32_t a[4],
                                         const uint32_t b[2]) {
    asm volatile(
        "mma.sync.aligned.m16n8k16.row.col.f32.bf16.bf16.f32 "
        "{%0,%1,%2,%3}, {%4,%5,%6,%7}, {%8,%9}, {%0,%1,%2,%3};"
        : "+f"(d[0]), "+f"(d[1]), "+f"(d[2]), "+f"(d[3])
        : "r"(a[0]), "r"(a[1]), "r"(a[2]), "r"(a[3]), "r"(b[0]), "r"(b[1]));
}

// ===========================================================================
// mma.sync GEMM (unchanged from R3): C[M,N] = A[M,K] @ W[K,N]
// ===========================================================================
#define SAg 40
#define SBg 136
#define AHI_OFF 0
#define ALO_OFF (128 * SAg * 2)
#define BHI_OFF (2 * 128 * SAg * 2)
#define BLO_OFF (2 * 128 * SAg * 2 + 32 * SBg * 2)
#define GEMM_SMEM (2 * 128 * SAg * 2 + 2 * 32 * SBg * 2)

__global__ __launch_bounds__(256, 2)
void gemm_mma_kernel(const float* __restrict__ A, const float* __restrict__ W,
                     float* __restrict__ C, int M, int N, int K) {
    extern __shared__ char sm[];
    const uint32_t smb = smem_to_u32(sm);
    const int tid = threadIdx.x, lane = tid & 31, wid = tid >> 5;
    const int wm = wid >> 1, wn = wid & 1;
    const int m0 = blockIdx.y * 128, n0 = blockIdx.x * 128;

    float acc[2][8][4];
    #pragma unroll
    for (int i = 0; i < 2; i++)
        #pragma unroll
        for (int j = 0; j < 8; j++)
            #pragma unroll
            for (int t = 0; t < 4; t++) acc[i][j][t] = 0.f;

    const uint32_t aRow  = lane & 15;
    const uint32_t aColH = (lane >> 4) * 8;
    const uint32_t bRow  = lane & 15;

    const int nch = K >> 5;
    for (int c = 0; c < nch; c++) {
        const int k0 = c << 5;
        __syncthreads();

        #pragma unroll
        for (int i = 0; i < 4; i++) {
            int idx = tid + (i << 8);
            int row = idx >> 3, c4 = idx & 7;
            float4 v = *reinterpret_cast<const float4*>(
                A + (size_t)(m0 + row) * K + k0 + (c4 << 2));
            uint32_t h0 = pack_bf2(v.x, v.y), h1 = pack_bf2(v.z, v.w);
            uint32_t l0 = pack_bf2(v.x - bf_lo_f32(h0), v.y - bf_hi_f32(h0));
            uint32_t l1 = pack_bf2(v.z - bf_lo_f32(h1), v.w - bf_hi_f32(h1));
            uint32_t off = (row * SAg + (c4 << 2)) * 2;
            *reinterpret_cast<uint2*>(sm + AHI_OFF + off) = make_uint2(h0, h1);
            *reinterpret_cast<uint2*>(sm + ALO_OFF + off) = make_uint2(l0, l1);
        }
        #pragma unroll
        for (int i = 0; i < 4; i++) {
            int idx = tid + (i << 8);
            int kr = idx >> 5, nf4 = idx & 31;
            float4 v = *reinterpret_cast<const float4*>(
                W + (size_t)(k0 + kr) * N + n0 + (nf4 << 2));
            uint32_t h0 = pack_bf2(v.x, v.y), h1 = pack_bf2(v.z, v.w);
            uint32_t l0 = pack_bf2(v.x - bf_lo_f32(h0), v.y - bf_hi_f32(h0));
            uint32_t l1 = pack_bf2(v.z - bf_lo_f32(h1), v.w - bf_hi_f32(h1));
            uint32_t off = (kr * SBg + (nf4 << 2)) * 2;
            *reinterpret_cast<uint2*>(sm + BHI_OFF + off) = make_uint2(h0, h1);
            *reinterpret_cast<uint2*>(sm + BLO_OFF + off) = make_uint2(l0, l1);
        }
        __syncthreads();

        #pragma unroll
        for (int ks = 0; ks < 2; ks++) {
            uint32_t aH[2][4], aL[2][4];
            #pragma unroll
            for (int mf = 0; mf < 2; mf++) {
                uint32_t ao = ((wm * 32 + mf * 16 + aRow) * SAg + ks * 16 + aColH) * 2;
                ldmx4(aH[mf], smb + AHI_OFF + ao);
                ldmx4(aL[mf], smb + ALO_OFF + ao);
            }
            #pragma unroll
            for (int nf = 0; nf < 8; nf++) {
                uint32_t bH[2], bL[2];
                uint32_t bo = ((ks * 16 + bRow) * SBg + wn * 64 + nf * 8) * 2;
                ldmx2t(bH, smb + BHI_OFF + bo);
                ldmx2t(bL, smb + BLO_OFF + bo);
                #pragma unroll
                for (int mf = 0; mf < 2; mf++) {
                    mma16816(acc[mf][nf], aH[mf], bH);
                    mma16816(acc[mf][nf], aL[mf], bH);
                    mma16816(acc[mf][nf], aH[mf], bL);
                }
            }
        }
    }

    #pragma unroll
    for (int mf = 0; mf < 2; mf++) {
        int row = m0 + wm * 32 + mf * 16 + (lane >> 2);
        #pragma unroll
        for (int nf = 0; nf < 8; nf++) {
            int col = n0 + wn * 64 + nf * 8 + (lane & 3) * 2;
            *reinterpret_cast<float2*>(C + (size_t)row * N + col) =
                make_float2(acc[mf][nf][0], acc[mf][nf][1]);
            *reinterpret_cast<float2*>(C + (size_t)(row + 8) * N + col) =
                make_float2(acc[mf][nf][2], acc[mf][nf][3]);
        }
    }
}

// ---------------------------------------------------------------------------
// RoPE (unchanged)
// ---------------------------------------------------------------------------
__global__ void rope_kernel(float* __restrict__ Q, float* __restrict__ K,
                            const int* __restrict__ pos_ids) {
    int idx = blockIdx.x * blockDim.x + threadIdx.x;
    if (idx >= B_ * S_ * HKV_ * 32) return;
    int d   = idx & 31;
    int h   = (idx >> 5) & (HKV_ - 1);
    int row = idx >> 8;
    float p    = (float)pos_ids[row];
    float invf = powf(10000.0f, -(float)d * (1.0f / 32.0f));
    float a = p * invf;
    float sn, cs;
    sincosf(a, &sn, &cs);
    size_t base = (size_t)row * NQK_ + h * HD_;
    float q0 = Q[base + d], q1 = Q[base + d + 32];
    Q[base + d]      = q0 * cs - q1 * sn;
    Q[base + d + 32] = q1 * cs + q0 * sn;
    float k0 = K[base + d], k1 = K[base + d + 32];
    K[base + d]      = k0 * cs - k1 * sn;
    K[base + d + 32] = k1 * cs + k0 * sn;
}

// ===========================================================================
// Flash attention on mma.sync, split-bf16 for QK and PV.
// Block = (q-tile 64, kv-head h, batch b); 8 warps 4m x 2n.
// ===========================================================================
#define SK   72      // bf16 row stride for Q/K/P tiles (64 + 8 pad)
#define SV   264     // bf16 row stride for V tile (256 + 8 pad)
#define PITX 66      // f32 row stride for score tile
#define QHI_O 0
#define QLO_O 9216
#define KHI_O 18432
#define KLO_O 27648
#define VHI_O 36864
#define VLO_O 70656
#define PS_O  104448
#define PHI_O 121344
#define PLO_O 130560
#define MR_O  139776
#define LR_O  140032
#define SF_O  140288
#define ATTN_SMEM 140544

__global__ __launch_bounds__(256, 1)
void attn_mma_kernel(const float* __restrict__ Q, const float* __restrict__ K,
                     const float* __restrict__ V, float* __restrict__ Out) {
    extern __shared__ char sm[];
    const uint32_t smb = smem_to_u32(sm);
    float* Ps   = reinterpret_cast<float*>(sm + PS_O);
    float* mrow = reinterpret_cast<float*>(sm + MR_O);
    float* lrow = reinterpret_cast<float*>(sm + LR_O);
    float* sfac = reinterpret_cast<float*>(sm + SF_O);

    const int tid = threadIdx.x, lane = tid & 31, wid = tid >> 5;
    const int wm = wid >> 1, wn = wid & 1;
    const int b  = blockIdx.z;
    const int h  = blockIdx.y;
    const int qb = blockIdx.x;
    const int q0 = qb * 64;

    // ---- load Q tile (scaled 0.125) -> bf16 hi/lo ----
    #pragma unroll
    for (int i = 0; i < 4; i++) {
        int idx = tid + (i << 8);
        int r = idx >> 4, c4 = idx & 15;
        float4 v = *reinterpret_cast<const float4*>(
            Q + ((size_t)(b * S_ + q0 + r)) * NQK_ + h * HD_ + (c4 << 2));
        v.x *= 0.125f; v.y *= 0.125f; v.z *= 0.125f; v.w *= 0.125f;
        uint32_t h0 = pack_bf2(v.x, v.y), h1 = pack_bf2(v.z, v.w);
        uint32_t l0 = pack_bf2(v.x - bf_lo_f32(h0), v.y - bf_hi_f32(h0));
        uint32_t l1 = pack_bf2(v.z - bf_lo_f32(h1), v.w - bf_hi_f32(h1));
        uint32_t off = (r * SK + (c4 << 2)) * 2;
        *reinterpret_cast<uint2*>(sm + QHI_O + off) = make_uint2(h0, h1);
        *reinterpret_cast<uint2*>(sm + QLO_O + off) = make_uint2(l0, l1);
    }
    if (tid < 64) { mrow[tid] = -INFINITY; lrow[tid] = 0.f; }

    float acc[16][4];
    #pragma unroll
    for (int i = 0; i < 16; i++)
        #pragma unroll
        for (int t = 0; t < 4; t++) acc[i][t] = 0.f;

    const float4* V4 = reinterpret_cast<const float4*>(V);

    // ldmatrix lane addressing
    const uint32_t aRow  = lane & 15;
    const uint32_t aColH = (lane >> 4) * 8;
    // QK B (non-trans x4 on K[key][dim]):
    const uint32_t kbRow = (lane & 7) + ((lane >> 4) & 1) * 8;  // key within 16
    const uint32_t kbCol = ((lane >> 3) & 1) * 8;               // k offset
    // PV B (trans x4 on V[key][col]):
    const uint32_t vbRow = (lane & 7) + ((lane >> 3) & 1) * 8;  // key within 16
    const uint32_t vbCol = ((lane >> 4) & 1) * 8;               // col offset

    for (int kt = 0; kt <= qb; kt++) {
        const int k0 = kt * 64;
        __syncthreads();   // prior-iter consumers of K/V/P smem done

        // ---- load K tile -> bf16 hi/lo [key][dim] ----
        #pragma unroll
        for (int i = 0; i < 4; i++) {
            int idx = tid + (i << 8);
            int kk = idx >> 4, c4 = idx & 15;
            float4 v = *reinterpret_cast<const float4*>(
                K + ((size_t)(b * S_ + k0 + kk)) * NQK_ + h * HD_ + (c4 << 2));
            uint32_t h0 = pack_bf2(v.x, v.y), h1 = pack_bf2(v.z, v.w);
            uint32_t l0 = pack_bf2(v.x - bf_lo_f32(h0), v.y - bf_hi_f32(h0));
            uint32_t l1 = pack_bf2(v.z - bf_lo_f32(h1), v.w - bf_hi_f32(h1));
            uint32_t off = (kk * SK + (c4 << 2)) * 2;
            *reinterpret_cast<uint2*>(sm + KHI_O + off) = make_uint2(h0, h1);
            *reinterpret_cast<uint2*>(sm + KLO_O + off) = make_uint2(l0, l1);
        }
        // ---- load V tile -> bf16 hi/lo [key][256 cols] ----
        #pragma unroll
        for (int i = 0; i < 16; i++) {
            int idx = tid + (i << 8);
            int kk = idx >> 6;
            int c4 = idx & 63;
            int g  = c4 >> 4, d4 = c4 & 15;
            float4 v = V4[((size_t)(b * S_ + k0 + kk)) * (HID_ / 4)
                          + g * (NQK_ / 4) + h * (HD_ / 4) + d4];
            uint32_t h0 = pack_bf2(v.x, v.y), h1 = pack_bf2(v.z, v.w);
            uint32_t l0 = pack_bf2(v.x - bf_lo_f32(h0), v.y - bf_hi_f32(h0));
            uint32_t l1 = pack_bf2(v.z - bf_lo_f32(h1), v.w - bf_hi_f32(h1));
            uint32_t off = (kk * SV + (c4 << 2)) * 2;
            *reinterpret_cast<uint2*>(sm + VHI_O + off) = make_uint2(h0, h1);
            *reinterpret_cast<uint2*>(sm + VLO_O + off) = make_uint2(l0, l1);
        }
        __syncthreads();

        // ---- QK^T: S[64x64], warp tile 16x32 ----
        {
            float sfr[4][4];
            #pragma unroll
            for (int i = 0; i < 4; i++)
                #pragma unroll
                for (int t = 0; t < 4; t++) sfr[i][t] = 0.f;

            #pragma unroll
            for (int ks = 0; ks < 4; ks++) {
                uint32_t aH[4], aL[4];
                uint32_t ao = ((wm * 16 + aRow) * SK + ks * 16 + aColH) * 2;
                ldmx4(aH, smb + QHI_O + ao);
                ldmx4(aL, smb + QLO_O + ao);
                #pragma unroll
                for (int np = 0; np < 2; np++) {
                    uint32_t bH[4], bL[4];
                    uint32_t nb = wn * 32 + np * 16;
                    uint32_t bo = ((nb + kbRow) * SK + ks * 16 + kbCol) * 2;
                    ldmx4(bH, smb + KHI_O + bo);
                    ldmx4(bL, smb + KLO_O + bo);
                    mma16816(sfr[np*2+0], aH, bH);
                    mma16816(sfr[np*2+0], aL, bH);
                    mma16816(sfr[np*2+0], aH, bL);
                    mma16816(sfr[np*2+1], aH, bH + 2);
                    mma16816(sfr[np*2+1], aL, bH + 2);
                    mma16816(sfr[np*2+1], aH, bL + 2);
                }
            }
            // write S to smem
            int r0 = wm * 16 + (lane >> 2);
            #pragma unroll
            for (int nf = 0; nf < 4; nf++) {
                int cb = wn * 32 + nf * 8 + (lane & 3) * 2;
                *reinterpret_cast<float2*>(&Ps[r0 * PITX + cb]) =
                    make_float2(sfr[nf][0], sfr[nf][1]);
                *reinterpret_cast<float2*>(&Ps[(r0 + 8) * PITX + cb]) =
                    make_float2(sfr[nf][2], sfr[nf][3]);
            }
        }
        __syncthreads();

        // ---- online softmax (one thread per row) ----
        if (tid < 64) {
            const int row = tid;
            const int kmax = (kt == qb) ? row : 63;
            float m_old = mrow[row];
            float mx = m_old;
            for (int k = 0; k <= kmax; k++) mx = fmaxf(mx, Ps[row * PITX + k]);
            float sum = 0.f;
            for (int k = 0; k < 64; k++) {
                float p = (k <= kmax) ? expf(Ps[row * PITX + k] - mx) : 0.f;
                Ps[row * PITX + k] = p;
                sum += p;
            }
            float f = expf(m_old - mx);
            sfac[row] = f;
            lrow[row] = lrow[row] * f + sum;
            mrow[row] = mx;
        }
        __syncthreads();

        // ---- convert P -> bf16 hi/lo (parallel) ----
        {
            int row = tid >> 2;
            int cb  = (tid & 3) * 16;
            #pragma unroll
            for (int j = 0; j < 8; j++) {
                float p0 = Ps[row * PITX + cb + 2*j];
                float p1 = Ps[row * PITX + cb + 2*j + 1];
                uint32_t ph = pack_bf2(p0, p1);
                uint32_t pl = pack_bf2(p0 - bf_lo_f32(ph), p1 - bf_hi_f32(ph));
                uint32_t off = (row * SK + cb + 2*j) * 2;
                *reinterpret_cast<uint32_t*>(sm + PHI_O + off) = ph;
                *reinterpret_cast<uint32_t*>(sm + PLO_O + off) = pl;
            }
        }
        __syncthreads();

        // ---- PV: acc(16x128 per warp) = rescale + P @ V ----
        {
            float f0 = sfac[wm * 16 + (lane >> 2)];
            float f1 = sfac[wm * 16 + (lane >> 2) + 8];
            #pragma unroll
            for (int i = 0; i < 16; i++) {
                acc[i][0] *= f0; acc[i][1] *= f0;
                acc[i][2] *= f1; acc[i][3] *= f1;
            }
            #pragma unroll
            for (int ks = 0; ks < 4; ks++) {
                uint32_t pH[4], pL[4];
                uint32_t ao = ((wm * 16 + aRow) * SK + ks * 16 + aColH) * 2;
                ldmx4(pH, smb + PHI_O + ao);
                ldmx4(pL, smb + PLO_O + ao);
                #pragma unroll
                for (int np = 0; np < 8; np++) {
                    uint32_t vH[4], vL[4];
                    uint32_t nb = wn * 128 + np * 16;
                    uint32_t bo = ((ks * 16 + vbRow) * SV + nb + vbCol) * 2;
                    ldmx4t(vH, smb + VHI_O + bo);
                    ldmx4t(vL, smb + VLO_O + bo);
                    mma16816(acc[np*2+0], pH, vH);
                    mma16816(acc[np*2+0], pL, vH);
                    mma16816(acc[np*2+0], pH, vL);
                    mma16816(acc[np*2+1], pH, vH + 2);
                    mma16816(acc[np*2+1], pL, vH + 2);
                    mma16816(acc[np*2+1], pH, vL + 2);
                }
            }
        }
    }
    __syncthreads();

    // ---- normalize + store ----
    {
        int r0 = wm * 16 + (lane >> 2);
        float invl0 = 1.f / lrow[r0];
        float invl1 = 1.f / lrow[r0 + 8];
        #pragma unroll
        for (int nf = 0; nf < 16; nf++) {
            int cl = wn * 128 + nf * 8 + (lane & 3) * 2;   // local col 0..255
            int g  = cl >> 6, d = cl & 63;
            size_t ob0 = ((size_t)(b * S_ + q0 + r0)) * HID_ + (g * HKV_ + h) * HD_ + d;
            size_t ob1 = ((size_t)(b * S_ + q0 + r0 + 8)) * HID_ + (g * HKV_ + h) * HD_ + d;
            *reinterpret_cast<float2*>(&Out[ob0]) =
                make_float2(acc[nf][0] * invl0, acc[nf][1] * invl0);
            *reinterpret_cast<float2*>(&Out[ob1]) =
                make_float2(acc[nf][2] * invl1, acc[nf][3] * invl1);
        }
    }
}

// ---------------------------------------------------------------------------
extern "C" void kernel_launch(void* const* d_in, const int* in_sizes, int n_in,
                              void* d_out, int out_size) {
    const float* X   = (const float*)d_in[0];
    const int*   pid = (const int*)  d_in[1];
    const float* Wq  = (const float*)d_in[2];
    const float* Wk  = (const float*)d_in[3];
    const float* Wv  = (const float*)d_in[4];
    float* Out = (float*)d_out;

    float *dQ, *dK, *dV;
    cudaGetSymbolAddress((void**)&dQ, g_Q);
    cudaGetSymbolAddress((void**)&dK, g_K);
    cudaGetSymbolAddress((void**)&dV, g_V);

    const int M = B_ * S_;

    {
        cudaFuncSetAttribute(gemm_mma_kernel,
                             cudaFuncAttributeMaxDynamicSharedMemorySize, GEMM_SMEM);
        dim3 blk(256);
        dim3 grdQ(NQK_ / 128, M / 128);
        gemm_mma_kernel<<<grdQ, blk, GEMM_SMEM>>>(X, Wq, dQ, M, NQK_, HID_);
        gemm_mma_kernel<<<grdQ, blk, GEMM_SMEM>>>(X, Wk, dK, M, NQK_, HID_);
        dim3 grdV(HID_ / 128, M / 128);
        gemm_mma_kernel<<<grdV, blk, GEMM_SMEM>>>(X, Wv, dV, M, HID_, HID_);
    }
    {
        int total = B_ * S_ * HKV_ * 32;
        rope_kernel<<<(total + 255) / 256, 256>>>(dQ, dK, pid);
    }
    {
        cudaFuncSetAttribute(attn_mma_kernel,
                             cudaFuncAttributeMaxDynamicSharedMemorySize, ATTN_SMEM);
        dim3 grd(S_ / 64, HKV_, B_);
        attn_mma_kernel<<<grd, 256, ATTN_SMEM>>>(dQ, dK, dV, Out);
    }
}

// round 5
// speedup vs baseline: 2.7814x; 1.0502x over previous
#include <cuda_runtime.h>
#include <cuda_bf16.h>
#include <math.h>
#include <stdint.h>

#define B_   2
#define S_   2048
#define HID_ 2048
#define NH_  32
#define G_   4
#define HD_  64
#define HKV_ 8
#define NQK_ 512   // HKV_*HD_
#define M_   (B_ * S_)   // 4096

// Scratch (device globals: no allocation allowed)
__device__ float g_Q[(size_t)M_*NQK_];
__device__ float g_K[(size_t)M_*NQK_];
__device__ float g_V[(size_t)M_*HID_];
// bf16 hi/lo pre-converted operands (stored as uint2 = 4 bf16)
__device__ uint2 g_Xh[(size_t)M_*HID_/4],  g_Xl[(size_t)M_*HID_/4];
__device__ uint2 g_Wqh[(size_t)HID_*NQK_/4], g_Wql[(size_t)HID_*NQK_/4];
__device__ uint2 g_Wkh[(size_t)HID_*NQK_/4], g_Wkl[(size_t)HID_*NQK_/4];
__device__ uint2 g_Wvh[(size_t)HID_*HID_/4], g_Wvl[(size_t)HID_*HID_/4];

// ===========================================================================
// helpers
// ===========================================================================
__device__ __forceinline__ uint32_t smem_to_u32(const void* smem_ptr) {
    uint32_t addr;
    asm("{ .reg .u64 tmp; cvta.to.shared.u64 tmp, %1; cvt.u32.u64 %0, tmp; }"
        : "=r"(addr) : "l"(smem_ptr));
    return addr;
}
__device__ __forceinline__ uint32_t pack_bf2(float a, float b) {
    uint32_t r;
    asm("cvt.rn.bf16x2.f32 %0, %1, %2;" : "=r"(r) : "f"(b), "f"(a));
    return r;
}
__device__ __forceinline__ float bf_lo_f32(uint32_t h) { return __uint_as_float(h << 16); }
__device__ __forceinline__ float bf_hi_f32(uint32_t h) { return __uint_as_float(h & 0xFFFF0000u); }

__device__ __forceinline__ void ldmx4(uint32_t r[4], uint32_t addr) {
    asm volatile("ldmatrix.sync.aligned.m8n8.x4.shared.b16 {%0,%1,%2,%3}, [%4];"
        : "=r"(r[0]), "=r"(r[1]), "=r"(r[2]), "=r"(r[3]) : "r"(addr));
}
__device__ __forceinline__ void ldmx4t(uint32_t r[4], uint32_t addr) {
    asm volatile("ldmatrix.sync.aligned.m8n8.x4.trans.shared.b16 {%0,%1,%2,%3}, [%4];"
        : "=r"(r[0]), "=r"(r[1]), "=r"(r[2]), "=r"(r[3]) : "r"(addr));
}
__device__ __forceinline__ void ldmx2t(uint32_t r[2], uint32_t addr) {
    asm volatile("ldmatrix.sync.aligned.m8n8.x2.trans.shared.b16 {%0,%1}, [%2];"
        : "=r"(r[0]), "=r"(r[1]) : "r"(addr));
}
__device__ __forceinline__ void mma16816(float d[4], const uint32_t a[4],
                                         const uint32_t b[2]) {
    asm volatile(
        "mma.sync.aligned.m16n8k16.row.col.f32.bf16.bf16.f32 "
        "{%0,%1,%2,%3}, {%4,%5,%6,%7}, {%8,%9}, {%0,%1,%2,%3};"
        : "+f"(d[0]), "+f"(d[1]), "+f"(d[2]), "+f"(d[3])
        : "r"(a[0]), "r"(a[1]), "r"(a[2]), "r"(a[3]), "r"(b[0]), "r"(b[1]));
}
__device__ __forceinline__ void cp16(uint32_t dst, const void* src) {
    asm volatile("cp.async.cg.shared.global [%0], [%1], 16;"
                 :: "r"(dst), "l"(src));
}
__device__ __forceinline__ void cp_commit() {
    asm volatile("cp.async.commit_group;" ::: "memory");
}
template <int N>
__device__ __forceinline__ void cp_wait() {
    asm volatile("cp.async.wait_group %0;" :: "n"(N) : "memory");
}

// ===========================================================================
// Pre-convert fp32 -> bf16 hi/lo
// ===========================================================================
__global__ void cvt_hilo_kernel(const float4* __restrict__ src,
                                uint2* __restrict__ hi, uint2* __restrict__ lo,
                                int n4) {
    int i = blockIdx.x * blockDim.x + threadIdx.x;
    if (i >= n4) return;
    float4 v = src[i];
    uint32_t h0 = pack_bf2(v.x, v.y), h1 = pack_bf2(v.z, v.w);
    uint32_t l0 = pack_bf2(v.x - bf_lo_f32(h0), v.y - bf_hi_f32(h0));
    uint32_t l1 = pack_bf2(v.z - bf_lo_f32(h1), v.w - bf_hi_f32(h1));
    hi[i] = make_uint2(h0, h1);
    lo[i] = make_uint2(l0, l1);
}

// ===========================================================================
// cp.async double-buffered bf16 GEMM: C[M,N] = A[M,K] @ B[K,N]
// A hi/lo, B hi/lo pre-converted. CTA tile 128x128, K-chunk 32, 2 stages.
// blockIdx.z selects operand set (fused Q/K launch).
// ===========================================================================
#define SA 40       // A row stride (bf16 elems): 80 B = 5x16
#define SB 136      // B row stride: 272 B = 17x16
#define A_HI 0
#define A_LO 10240
#define B_HI 20480
#define B_LO 29184
#define STGSZ 37888
#define GEMM_SMEM (2 * STGSZ)   // 75776

struct GemmOps { const void *Ah, *Al, *Bh, *Bl; float* C; };

__global__ __launch_bounds__(256, 2)
void gemm_pipe_kernel(const void* __restrict__ Ah, const void* __restrict__ Al,
                      const void* __restrict__ Bh0, const void* __restrict__ Bl0,
                      float* __restrict__ C0,
                      const void* __restrict__ Bh1, const void* __restrict__ Bl1,
                      float* __restrict__ C1,
                      int N, int K) {
    extern __shared__ char sm[];
    const uint32_t smb = smem_to_u32(sm);
    const int tid = threadIdx.x, lane = tid & 31, wid = tid >> 5;
    const int wm = wid >> 1, wn = wid & 1;
    const int m0 = blockIdx.y * 128, n0 = blockIdx.x * 128;

    const char* Bh = (const char*)(blockIdx.z ? Bh1 : Bh0);
    const char* Bl = (const char*)(blockIdx.z ? Bl1 : Bl0);
    float* C = blockIdx.z ? C1 : C0;
    const char* Ahc = (const char*)Ah;
    const char* Alc = (const char*)Al;

    float acc[2][8][4];
    #pragma unroll
    for (int i = 0; i < 2; i++)
        #pragma unroll
        for (int j = 0; j < 8; j++)
            #pragma unroll
            for (int t = 0; t < 4; t++) acc[i][j][t] = 0.f;

    const uint32_t aRow  = lane & 15;
    const uint32_t aColH = (lane >> 4) * 8;
    const uint32_t bRow  = lane & 15;
    const int nch = K >> 5;

    // stage issue: 8 cp.asyncs per thread
    auto issue = [&](int s, int k0) {
        uint32_t sb = smb + s * STGSZ;
        #pragma unroll
        for (int i = 0; i < 2; i++) {
            int idx = tid + (i << 8);
            int row = idx >> 2, seg = idx & 3;
            size_t go = ((size_t)(m0 + row) * K + k0 + seg * 8) * 2;
            uint32_t so = row * 80 + seg * 16;
            cp16(sb + A_HI + so, Ahc + go);
            cp16(sb + A_LO + so, Alc + go);
        }
        #pragma unroll
        for (int i = 0; i < 2; i++) {
            int idx = tid + (i << 8);
            int row = idx >> 4, seg = idx & 15;
            size_t go = ((size_t)(k0 + row) * N + n0 + seg * 8) * 2;
            uint32_t so = row * 272 + seg * 16;
            cp16(sb + B_HI + so, Bh + go);
            cp16(sb + B_LO + so, Bl + go);
        }
        cp_commit();
    };

    issue(0, 0);
    for (int c = 0; c < nch; c++) {
        if (c + 1 < nch) { issue((c + 1) & 1, (c + 1) << 5); cp_wait<1>(); }
        else             { cp_wait<0>(); }
        __syncthreads();

        const uint32_t sb = smb + (c & 1) * STGSZ;
        #pragma unroll
        for (int ks = 0; ks < 2; ks++) {
            uint32_t aH[2][4], aL[2][4];
            #pragma unroll
            for (int mf = 0; mf < 2; mf++) {
                uint32_t ao = ((wm * 32 + mf * 16 + aRow) * SA + ks * 16 + aColH) * 2;
                ldmx4(aH[mf], sb + A_HI + ao);
                ldmx4(aL[mf], sb + A_LO + ao);
            }
            #pragma unroll
            for (int nf = 0; nf < 8; nf++) {
                uint32_t bH[2], bL[2];
                uint32_t bo = ((ks * 16 + bRow) * SB + wn * 64 + nf * 8) * 2;
                ldmx2t(bH, sb + B_HI + bo);
                ldmx2t(bL, sb + B_LO + bo);
                #pragma unroll
                for (int mf = 0; mf < 2; mf++) {
                    mma16816(acc[mf][nf], aH[mf], bH);
                    mma16816(acc[mf][nf], aL[mf], bH);
                    mma16816(acc[mf][nf], aH[mf], bL);
                }
            }
        }
        __syncthreads();
    }

    #pragma unroll
    for (int mf = 0; mf < 2; mf++) {
        int row = m0 + wm * 32 + mf * 16 + (lane >> 2);
        #pragma unroll
        for (int nf = 0; nf < 8; nf++) {
            int col = n0 + wn * 64 + nf * 8 + (lane & 3) * 2;
            *reinterpret_cast<float2*>(C + (size_t)row * N + col) =
                make_float2(acc[mf][nf][0], acc[mf][nf][1]);
            *reinterpret_cast<float2*>(C + (size_t)(row + 8) * N + col) =
                make_float2(acc[mf][nf][2], acc[mf][nf][3]);
        }
    }
}

// ---------------------------------------------------------------------------
// RoPE (unchanged)
// ---------------------------------------------------------------------------
__global__ void rope_kernel(float* __restrict__ Q, float* __restrict__ K,
                            const int* __restrict__ pos_ids) {
    int idx = blockIdx.x * blockDim.x + threadIdx.x;
    if (idx >= B_ * S_ * HKV_ * 32) return;
    int d   = idx & 31;
    int h   = (idx >> 5) & (HKV_ - 1);
    int row = idx >> 8;
    float p    = (float)pos_ids[row];
    float invf = powf(10000.0f, -(float)d * (1.0f / 32.0f));
    float a = p * invf;
    float sn, cs;
    sincosf(a, &sn, &cs);
    size_t base = (size_t)row * NQK_ + h * HD_;
    float q0 = Q[base + d], q1 = Q[base + d + 32];
    Q[base + d]      = q0 * cs - q1 * sn;
    Q[base + d + 32] = q1 * cs + q0 * sn;
    float k0 = K[base + d], k1 = K[base + d + 32];
    K[base + d]      = k0 * cs - k1 * sn;
    K[base + d + 32] = k1 * cs + k0 * sn;
}

// ===========================================================================
// Flash attention on mma.sync (unchanged from R4)
// ===========================================================================
#define SK   72
#define SV   264
#define PITX 66
#define QHI_O 0
#define QLO_O 9216
#define KHI_O 18432
#define KLO_O 27648
#define VHI_O 36864
#define VLO_O 70656
#define PS_O  104448
#define PHI_O 121344
#define PLO_O 130560
#define MR_O  139776
#define LR_O  140032
#define SF_O  140288
#define ATTN_SMEM 140544

__global__ __launch_bounds__(256, 1)
void attn_mma_kernel(const float* __restrict__ Q, const float* __restrict__ K,
                     const float* __restrict__ V, float* __restrict__ Out) {
    extern __shared__ char sm[];
    const uint32_t smb = smem_to_u32(sm);
    float* Ps   = reinterpret_cast<float*>(sm + PS_O);
    float* mrow = reinterpret_cast<float*>(sm + MR_O);
    float* lrow = reinterpret_cast<float*>(sm + LR_O);
    float* sfac = reinterpret_cast<float*>(sm + SF_O);

    const int tid = threadIdx.x, lane = tid & 31, wid = tid >> 5;
    const int wm = wid >> 1, wn = wid & 1;
    const int b  = blockIdx.z;
    const int h  = blockIdx.y;
    const int qb = blockIdx.x;
    const int q0 = qb * 64;

    #pragma unroll
    for (int i = 0; i < 4; i++) {
        int idx = tid + (i << 8);
        int r = idx >> 4, c4 = idx & 15;
        float4 v = *reinterpret_cast<const float4*>(
            Q + ((size_t)(b * S_ + q0 + r)) * NQK_ + h * HD_ + (c4 << 2));
        v.x *= 0.125f; v.y *= 0.125f; v.z *= 0.125f; v.w *= 0.125f;
        uint32_t h0 = pack_bf2(v.x, v.y), h1 = pack_bf2(v.z, v.w);
        uint32_t l0 = pack_bf2(v.x - bf_lo_f32(h0), v.y - bf_hi_f32(h0));
        uint32_t l1 = pack_bf2(v.z - bf_lo_f32(h1), v.w - bf_hi_f32(h1));
        uint32_t off = (r * SK + (c4 << 2)) * 2;
        *reinterpret_cast<uint2*>(sm + QHI_O + off) = make_uint2(h0, h1);
        *reinterpret_cast<uint2*>(sm + QLO_O + off) = make_uint2(l0, l1);
    }
    if (tid < 64) { mrow[tid] = -INFINITY; lrow[tid] = 0.f; }

    float acc[16][4];
    #pragma unroll
    for (int i = 0; i < 16; i++)
        #pragma unroll
        for (int t = 0; t < 4; t++) acc[i][t] = 0.f;

    const float4* V4 = reinterpret_cast<const float4*>(V);

    const uint32_t aRow  = lane & 15;
    const uint32_t aColH = (lane >> 4) * 8;
    const uint32_t kbRow = (lane & 7) + ((lane >> 4) & 1) * 8;
    const uint32_t kbCol = ((lane >> 3) & 1) * 8;
    const uint32_t vbRow = (lane & 7) + ((lane >> 3) & 1) * 8;
    const uint32_t vbCol = ((lane >> 4) & 1) * 8;

    for (int kt = 0; kt <= qb; kt++) {
        const int k0 = kt * 64;
        __syncthreads();

        #pragma unroll
        for (int i = 0; i < 4; i++) {
            int idx = tid + (i << 8);
            int kk = idx >> 4, c4 = idx & 15;
            float4 v = *reinterpret_cast<const float4*>(
                K + ((size_t)(b * S_ + k0 + kk)) * NQK_ + h * HD_ + (c4 << 2));
            uint32_t h0 = pack_bf2(v.x, v.y), h1 = pack_bf2(v.z, v.w);
            uint32_t l0 = pack_bf2(v.x - bf_lo_f32(h0), v.y - bf_hi_f32(h0));
            uint32_t l1 = pack_bf2(v.z - bf_lo_f32(h1), v.w - bf_hi_f32(h1));
            uint32_t off = (kk * SK + (c4 << 2)) * 2;
            *reinterpret_cast<uint2*>(sm + KHI_O + off) = make_uint2(h0, h1);
            *reinterpret_cast<uint2*>(sm + KLO_O + off) = make_uint2(l0, l1);
        }
        #pragma unroll
        for (int i = 0; i < 16; i++) {
            int idx = tid + (i << 8);
            int kk = idx >> 6;
            int c4 = idx & 63;
            int g  = c4 >> 4, d4 = c4 & 15;
            float4 v = V4[((size_t)(b * S_ + k0 + kk)) * (HID_ / 4)
                          + g * (NQK_ / 4) + h * (HD_ / 4) + d4];
            uint32_t h0 = pack_bf2(v.x, v.y), h1 = pack_bf2(v.z, v.w);
            uint32_t l0 = pack_bf2(v.x - bf_lo_f32(h0), v.y - bf_hi_f32(h0));
            uint32_t l1 = pack_bf2(v.z - bf_lo_f32(h1), v.w - bf_hi_f32(h1));
            uint32_t off = (kk * SV + (c4 << 2)) * 2;
            *reinterpret_cast<uint2*>(sm + VHI_O + off) = make_uint2(h0, h1);
            *reinterpret_cast<uint2*>(sm + VLO_O + off) = make_uint2(l0, l1);
        }
        __syncthreads();

        {
            float sfr[4][4];
            #pragma unroll
            for (int i = 0; i < 4; i++)
                #pragma unroll
                for (int t = 0; t < 4; t++) sfr[i][t] = 0.f;

            #pragma unroll
            for (int ks = 0; ks < 4; ks++) {
                uint32_t aH[4], aL[4];
                uint32_t ao = ((wm * 16 + aRow) * SK + ks * 16 + aColH) * 2;
                ldmx4(aH, smb + QHI_O + ao);
                ldmx4(aL, smb + QLO_O + ao);
                #pragma unroll
                for (int np = 0; np < 2; np++) {
                    uint32_t bH[4], bL[4];
                    uint32_t nb = wn * 32 + np * 16;
                    uint32_t bo = ((nb + kbRow) * SK + ks * 16 + kbCol) * 2;
                    ldmx4(bH, smb + KHI_O + bo);
                    ldmx4(bL, smb + KLO_O + bo);
                    mma16816(sfr[np*2+0], aH, bH);
                    mma16816(sfr[np*2+0], aL, bH);
                    mma16816(sfr[np*2+0], aH, bL);
                    mma16816(sfr[np*2+1], aH, bH + 2);
                    mma16816(sfr[np*2+1], aL, bH + 2);
                    mma16816(sfr[np*2+1], aH, bL + 2);
                }
            }
            int r0 = wm * 16 + (lane >> 2);
            #pragma unroll
            for (int nf = 0; nf < 4; nf++) {
                int cb = wn * 32 + nf * 8 + (lane & 3) * 2;
                *reinterpret_cast<float2*>(&Ps[r0 * PITX + cb]) =
                    make_float2(sfr[nf][0], sfr[nf][1]);
                *reinterpret_cast<float2*>(&Ps[(r0 + 8) * PITX + cb]) =
                    make_float2(sfr[nf][2], sfr[nf][3]);
            }
        }
        __syncthreads();

        if (tid < 64) {
            const int row = tid;
            const int kmax = (kt == qb) ? row : 63;
            float m_old = mrow[row];
            float mx = m_old;
            for (int k = 0; k <= kmax; k++) mx = fmaxf(mx, Ps[row * PITX + k]);
            float sum = 0.f;
            for (int k = 0; k < 64; k++) {
                float p = (k <= kmax) ? expf(Ps[row * PITX + k] - mx) : 0.f;
                Ps[row * PITX + k] = p;
                sum += p;
            }
            float f = expf(m_old - mx);
            sfac[row] = f;
            lrow[row] = lrow[row] * f + sum;
            mrow[row] = mx;
        }
        __syncthreads();

        {
            int row = tid >> 2;
            int cb  = (tid & 3) * 16;
            #pragma unroll
            for (int j = 0; j < 8; j++) {
                float p0 = Ps[row * PITX + cb + 2*j];
                float p1 = Ps[row * PITX + cb + 2*j + 1];
                uint32_t ph = pack_bf2(p0, p1);
                uint32_t pl = pack_bf2(p0 - bf_lo_f32(ph), p1 - bf_hi_f32(ph));
                uint32_t off = (row * SK + cb + 2*j) * 2;
                *reinterpret_cast<uint32_t*>(sm + PHI_O + off) = ph;
                *reinterpret_cast<uint32_t*>(sm + PLO_O + off) = pl;
            }
        }
        __syncthreads();

        {
            float f0 = sfac[wm * 16 + (lane >> 2)];
            float f1 = sfac[wm * 16 + (lane >> 2) + 8];
            #pragma unroll
            for (int i = 0; i < 16; i++) {
                acc[i][0] *= f0; acc[i][1] *= f0;
                acc[i][2] *= f1; acc[i][3] *= f1;
            }
            #pragma unroll
            for (int ks = 0; ks < 4; ks++) {
                uint32_t pH[4], pL[4];
                uint32_t ao = ((wm * 16 + aRow) * SK + ks * 16 + aColH) * 2;
                ldmx4(pH, smb + PHI_O + ao);
                ldmx4(pL, smb + PLO_O + ao);
                #pragma unroll
                for (int np = 0; np < 8; np++) {
                    uint32_t vH[4], vL[4];
                    uint32_t nb = wn * 128 + np * 16;
                    uint32_t bo = ((ks * 16 + vbRow) * SV + nb + vbCol) * 2;
                    ldmx4t(vH, smb + VHI_O + bo);
                    ldmx4t(vL, smb + VLO_O + bo);
                    mma16816(acc[np*2+0], pH, vH);
                    mma16816(acc[np*2+0], pL, vH);
                    mma16816(acc[np*2+0], pH, vL);
                    mma16816(acc[np*2+1], pH, vH + 2);
                    mma16816(acc[np*2+1], pL, vH + 2);
                    mma16816(acc[np*2+1], pH, vL + 2);
                }
            }
        }
    }
    __syncthreads();

    {
        int r0 = wm * 16 + (lane >> 2);
        float invl0 = 1.f / lrow[r0];
        float invl1 = 1.f / lrow[r0 + 8];
        #pragma unroll
        for (int nf = 0; nf < 16; nf++) {
            int cl = wn * 128 + nf * 8 + (lane & 3) * 2;
            int g  = cl >> 6, d = cl & 63;
            size_t ob0 = ((size_t)(b * S_ + q0 + r0)) * HID_ + (g * HKV_ + h) * HD_ + d;
            size_t ob1 = ((size_t)(b * S_ + q0 + r0 + 8)) * HID_ + (g * HKV_ + h) * HD_ + d;
            *reinterpret_cast<float2*>(&Out[ob0]) =
                make_float2(acc[nf][0] * invl0, acc[nf][1] * invl0);
            *reinterpret_cast<float2*>(&Out[ob1]) =
                make_float2(acc[nf][2] * invl1, acc[nf][3] * invl1);
        }
    }
}

// ---------------------------------------------------------------------------
extern "C" void kernel_launch(void* const* d_in, const int* in_sizes, int n_in,
                              void* d_out, int out_size) {
    const float* X   = (const float*)d_in[0];
    const int*   pid = (const int*)  d_in[1];
    const float* Wq  = (const float*)d_in[2];
    const float* Wk  = (const float*)d_in[3];
    const float* Wv  = (const float*)d_in[4];
    float* Out = (float*)d_out;

    float *dQ, *dK, *dV;
    cudaGetSymbolAddress((void**)&dQ, g_Q);
    cudaGetSymbolAddress((void**)&dK, g_K);
    cudaGetSymbolAddress((void**)&dV, g_V);
    uint2 *xh, *xl, *wqh, *wql, *wkh, *wkl, *wvh, *wvl;
    cudaGetSymbolAddress((void**)&xh,  g_Xh);  cudaGetSymbolAddress((void**)&xl,  g_Xl);
    cudaGetSymbolAddress((void**)&wqh, g_Wqh); cudaGetSymbolAddress((void**)&wql, g_Wql);
    cudaGetSymbolAddress((void**)&wkh, g_Wkh); cudaGetSymbolAddress((void**)&wkl, g_Wkl);
    cudaGetSymbolAddress((void**)&wvh, g_Wvh); cudaGetSymbolAddress((void**)&wvl, g_Wvl);

    // Pre-convert operands to bf16 hi/lo
    {
        int nX = M_ * HID_ / 4, nWqk = HID_ * NQK_ / 4, nWv = HID_ * HID_ / 4;
        cvt_hilo_kernel<<<(nX + 255) / 256, 256>>>((const float4*)X, xh, xl, nX);
        cvt_hilo_kernel<<<(nWqk + 255) / 256, 256>>>((const float4*)Wq, wqh, wql, nWqk);
        cvt_hilo_kernel<<<(nWqk + 255) / 256, 256>>>((const float4*)Wk, wkh, wkl, nWqk);
        cvt_hilo_kernel<<<(nWv + 255) / 256, 256>>>((const float4*)Wv, wvh, wvl, nWv);
    }

    // Projections: fused Q/K launch + V launch
    {
        cudaFuncSetAttribute(gemm_pipe_kernel,
                             cudaFuncAttributeMaxDynamicSharedMemorySize, GEMM_SMEM);
        dim3 blk(256);
        dim3 grdQK(NQK_ / 128, M_ / 128, 2);
        gemm_pipe_kernel<<<grdQK, blk, GEMM_SMEM>>>(xh, xl, wqh, wql, dQ,
                                                    wkh, wkl, dK, NQK_, HID_);
        dim3 grdV(HID_ / 128, M_ / 128, 1);
        gemm_pipe_kernel<<<grdV, blk, GEMM_SMEM>>>(xh, xl, wvh, wvl, dV,
                                                   wvh, wvl, dV, HID_, HID_);
    }
    {
        int total = B_ * S_ * HKV_ * 32;
        rope_kernel<<<(total + 255) / 256, 256>>>(dQ, dK, pid);
    }
    {
        cudaFuncSetAttribute(attn_mma_kernel,
                             cudaFuncAttributeMaxDynamicSharedMemorySize, ATTN_SMEM);
        dim3 grd(S_ / 64, HKV_, B_);
        attn_mma_kernel<<<grd, 256, ATTN_SMEM>>>(dQ, dK, dV, Out);
    }
}

// round 6
// speedup vs baseline: 3.0034x; 1.0798x over previous
#include <cuda_runtime.h>
#include <cuda_bf16.h>
#include <math.h>
#include <stdint.h>

#define B_   2
#define S_   2048
#define HID_ 2048
#define NH_  32
#define G_   4
#define HD_  64
#define HKV_ 8
#define NQK_ 512   // HKV_*HD_
#define M_   (B_ * S_)   // 4096

// Scratch (device globals: no allocation allowed)
__device__ float g_Q[(size_t)M_*NQK_];
__device__ float g_K[(size_t)M_*NQK_];
__device__ float g_V[(size_t)M_*HID_];
// bf16 hi/lo pre-converted operands (stored as uint2 = 4 bf16)
__device__ uint2 g_Xh[(size_t)M_*HID_/4],  g_Xl[(size_t)M_*HID_/4];
__device__ uint2 g_Wqh[(size_t)HID_*NQK_/4], g_Wql[(size_t)HID_*NQK_/4];
__device__ uint2 g_Wkh[(size_t)HID_*NQK_/4], g_Wkl[(size_t)HID_*NQK_/4];
__device__ uint2 g_Wvh[(size_t)HID_*HID_/4], g_Wvl[(size_t)HID_*HID_/4];

// ===========================================================================
// helpers
// ===========================================================================
__device__ __forceinline__ uint32_t smem_to_u32(const void* smem_ptr) {
    uint32_t addr;
    asm("{ .reg .u64 tmp; cvta.to.shared.u64 tmp, %1; cvt.u32.u64 %0, tmp; }"
        : "=r"(addr) : "l"(smem_ptr));
    return addr;
}
__device__ __forceinline__ uint32_t pack_bf2(float a, float b) {
    uint32_t r;
    asm("cvt.rn.bf16x2.f32 %0, %1, %2;" : "=r"(r) : "f"(b), "f"(a));
    return r;
}
__device__ __forceinline__ float bf_lo_f32(uint32_t h) { return __uint_as_float(h << 16); }
__device__ __forceinline__ float bf_hi_f32(uint32_t h) { return __uint_as_float(h & 0xFFFF0000u); }

__device__ __forceinline__ void ldmx4(uint32_t r[4], uint32_t addr) {
    asm volatile("ldmatrix.sync.aligned.m8n8.x4.shared.b16 {%0,%1,%2,%3}, [%4];"
        : "=r"(r[0]), "=r"(r[1]), "=r"(r[2]), "=r"(r[3]) : "r"(addr));
}
__device__ __forceinline__ void ldmx4t(uint32_t r[4], uint32_t addr) {
    asm volatile("ldmatrix.sync.aligned.m8n8.x4.trans.shared.b16 {%0,%1,%2,%3}, [%4];"
        : "=r"(r[0]), "=r"(r[1]), "=r"(r[2]), "=r"(r[3]) : "r"(addr));
}
__device__ __forceinline__ void mma16816(float d[4], const uint32_t a[4],
                                         const uint32_t b[2]) {
    asm volatile(
        "mma.sync.aligned.m16n8k16.row.col.f32.bf16.bf16.f32 "
        "{%0,%1,%2,%3}, {%4,%5,%6,%7}, {%8,%9}, {%0,%1,%2,%3};"
        : "+f"(d[0]), "+f"(d[1]), "+f"(d[2]), "+f"(d[3])
        : "r"(a[0]), "r"(a[1]), "r"(a[2]), "r"(a[3]), "r"(b[0]), "r"(b[1]));
}
__device__ __forceinline__ void cp16(uint32_t dst, const void* src) {
    asm volatile("cp.async.cg.shared.global [%0], [%1], 16;"
                 :: "r"(dst), "l"(src));
}
__device__ __forceinline__ void cp_commit() {
    asm volatile("cp.async.commit_group;" ::: "memory");
}
template <int N>
__device__ __forceinline__ void cp_wait() {
    asm volatile("cp.async.wait_group %0;" :: "n"(N) : "memory");
}

// ===========================================================================
// Pre-convert fp32 -> bf16 hi/lo
// ===========================================================================
__global__ void cvt_hilo_kernel(const float4* __restrict__ src,
                                uint2* __restrict__ hi, uint2* __restrict__ lo,
                                int n4) {
    int i = blockIdx.x * blockDim.x + threadIdx.x;
    if (i >= n4) return;
    float4 v = src[i];
    uint32_t h0 = pack_bf2(v.x, v.y), h1 = pack_bf2(v.z, v.w);
    uint32_t l0 = pack_bf2(v.x - bf_lo_f32(h0), v.y - bf_hi_f32(h0));
    uint32_t l1 = pack_bf2(v.z - bf_lo_f32(h1), v.w - bf_hi_f32(h1));
    hi[i] = make_uint2(h0, h1);
    lo[i] = make_uint2(l0, l1);
}

// ===========================================================================
// 4-stage cp.async bf16 GEMM: C[M,N] = A[M,K] @ B[K,N]
// CTA tile 128x256, warp tile 64x64 (8 warps 2m x 4n), K-chunk 32, occ 1.
// One __syncthreads per chunk (prefetch distance 2 protects buffer reuse).
// ===========================================================================
#define SAe 40      // A row stride (bf16): 80 B
#define SBe 264     // B row stride (bf16): 528 B
#define ST_AHI 0
#define ST_ALO 10240
#define ST_BHI 20480
#define ST_BLO 37376
#define ST_SZ  54272
#define NSTG 4
#define GEMM_SMEM (NSTG * ST_SZ)   // 217088

__global__ __launch_bounds__(256, 1)
void gemm_pipe_kernel(const void* __restrict__ Ah, const void* __restrict__ Al,
                      const void* __restrict__ Bh0, const void* __restrict__ Bl0,
                      float* __restrict__ C0,
                      const void* __restrict__ Bh1, const void* __restrict__ Bl1,
                      float* __restrict__ C1,
                      int N, int K) {
    extern __shared__ char sm[];
    const uint32_t smb = smem_to_u32(sm);
    const int tid = threadIdx.x, lane = tid & 31, wid = tid >> 5;
    const int wm = wid >> 2, wn = wid & 3;       // 2m x 4n
    const int m0 = blockIdx.y * 128, n0 = blockIdx.x * 256;

    const char* Bh = (const char*)(blockIdx.z ? Bh1 : Bh0);
    const char* Bl = (const char*)(blockIdx.z ? Bl1 : Bl0);
    float* C = blockIdx.z ? C1 : C0;
    const char* Ahc = (const char*)Ah;
    const char* Alc = (const char*)Al;

    float acc[4][8][4];
    #pragma unroll
    for (int i = 0; i < 4; i++)
        #pragma unroll
        for (int j = 0; j < 8; j++)
            #pragma unroll
            for (int t = 0; t < 4; t++) acc[i][j][t] = 0.f;

    // ldmatrix lane addressing
    const uint32_t aRow  = lane & 15;
    const uint32_t aColH = (lane >> 4) * 8;
    const uint32_t bRow  = (lane & 7) + ((lane >> 3) & 1) * 8;   // k within 16
    const uint32_t bCol  = ((lane >> 4) & 1) * 8;                // col offset
    const int nch = K >> 5;

    // stage issue: 12 cp.asyncs per thread (A 4, B 8)
    auto issue = [&](int s, int k0) {
        uint32_t sb = smb + s * ST_SZ;
        #pragma unroll
        for (int i = 0; i < 2; i++) {
            int idx = tid + (i << 8);
            int row = idx >> 2, seg = idx & 3;
            size_t go = ((size_t)(m0 + row) * K + k0 + seg * 8) * 2;
            uint32_t so = row * 80 + seg * 16;
            cp16(sb + ST_AHI + so, Ahc + go);
            cp16(sb + ST_ALO + so, Alc + go);
        }
        #pragma unroll
        for (int i = 0; i < 4; i++) {
            int idx = tid + (i << 8);
            int row = idx >> 5, seg = idx & 31;
            size_t go = ((size_t)(k0 + row) * N + n0 + seg * 8) * 2;
            uint32_t so = row * 528 + seg * 16;
            cp16(sb + ST_BHI + so, Bh + go);
            cp16(sb + ST_BLO + so, Bl + go);
        }
        cp_commit();
    };

    issue(0, 0);
    issue(1, 32);
    for (int c = 0; c < nch; c++) {
        if (c + 2 < nch) issue((c + 2) & (NSTG - 1), (c + 2) << 5);
        else             cp_commit();
        cp_wait<2>();          // chunk c's group complete
        __syncthreads();       // visibility + (distance-2) buffer-reuse guard

        const uint32_t sb = smb + (c & (NSTG - 1)) * ST_SZ;
        #pragma unroll
        for (int ks = 0; ks < 2; ks++) {
            uint32_t aH[4][4], aL[4][4];
            #pragma unroll
            for (int mf = 0; mf < 4; mf++) {
                uint32_t ao = ((wm * 64 + mf * 16 + aRow) * SAe + ks * 16 + aColH) * 2;
                ldmx4(aH[mf], sb + ST_AHI + ao);
                ldmx4(aL[mf], sb + ST_ALO + ao);
            }
            uint32_t bH[4][4], bL[4][4];
            #pragma unroll
            for (int ng = 0; ng < 4; ng++) {
                uint32_t bo = ((ks * 16 + bRow) * SBe + wn * 64 + ng * 16 + bCol) * 2;
                ldmx4t(bH[ng], sb + ST_BHI + bo);
                ldmx4t(bL[ng], sb + ST_BLO + bo);
            }
            #pragma unroll
            for (int mf = 0; mf < 4; mf++)
                #pragma unroll
                for (int ng = 0; ng < 4; ng++) {
                    mma16816(acc[mf][ng*2+0], aH[mf], bH[ng]);
                    mma16816(acc[mf][ng*2+0], aL[mf], bH[ng]);
                    mma16816(acc[mf][ng*2+0], aH[mf], bL[ng]);
                    mma16816(acc[mf][ng*2+1], aH[mf], bH[ng] + 2);
                    mma16816(acc[mf][ng*2+1], aL[mf], bH[ng] + 2);
                    mma16816(acc[mf][ng*2+1], aH[mf], bL[ng] + 2);
                }
        }
    }

    // epilogue: direct float2 stores
    #pragma unroll
    for (int mf = 0; mf < 4; mf++) {
        int row = m0 + wm * 64 + mf * 16 + (lane >> 2);
        #pragma unroll
        for (int nf = 0; nf < 8; nf++) {
            int col = n0 + wn * 64 + nf * 8 + (lane & 3) * 2;
            *reinterpret_cast<float2*>(C + (size_t)row * N + col) =
                make_float2(acc[mf][nf][0], acc[mf][nf][1]);
            *reinterpret_cast<float2*>(C + (size_t)(row + 8) * N + col) =
                make_float2(acc[mf][nf][2], acc[mf][nf][3]);
        }
    }
}

// ---------------------------------------------------------------------------
// RoPE (unchanged)
// ---------------------------------------------------------------------------
__global__ void rope_kernel(float* __restrict__ Q, float* __restrict__ K,
                            const int* __restrict__ pos_ids) {
    int idx = blockIdx.x * blockDim.x + threadIdx.x;
    if (idx >= B_ * S_ * HKV_ * 32) return;
    int d   = idx & 31;
    int h   = (idx >> 5) & (HKV_ - 1);
    int row = idx >> 8;
    float p    = (float)pos_ids[row];
    float invf = powf(10000.0f, -(float)d * (1.0f / 32.0f));
    float a = p * invf;
    float sn, cs;
    sincosf(a, &sn, &cs);
    size_t base = (size_t)row * NQK_ + h * HD_;
    float q0 = Q[base + d], q1 = Q[base + d + 32];
    Q[base + d]      = q0 * cs - q1 * sn;
    Q[base + d + 32] = q1 * cs + q0 * sn;
    float k0 = K[base + d], k1 = K[base + d + 32];
    K[base + d]      = k0 * cs - k1 * sn;
    K[base + d + 32] = k1 * cs + k0 * sn;
}

// ===========================================================================
// Flash attention on mma.sync (unchanged from R4)
// ===========================================================================
#define SK   72
#define SV   264
#define PITX 66
#define QHI_O 0
#define QLO_O 9216
#define KHI_O 18432
#define KLO_O 27648
#define VHI_O 36864
#define VLO_O 70656
#define PS_O  104448
#define PHI_O 121344
#define PLO_O 130560
#define MR_O  139776
#define LR_O  140032
#define SF_O  140288
#define ATTN_SMEM 140544

__global__ __launch_bounds__(256, 1)
void attn_mma_kernel(const float* __restrict__ Q, const float* __restrict__ K,
                     const float* __restrict__ V, float* __restrict__ Out) {
    extern __shared__ char sm[];
    const uint32_t smb = smem_to_u32(sm);
    float* Ps   = reinterpret_cast<float*>(sm + PS_O);
    float* mrow = reinterpret_cast<float*>(sm + MR_O);
    float* lrow = reinterpret_cast<float*>(sm + LR_O);
    float* sfac = reinterpret_cast<float*>(sm + SF_O);

    const int tid = threadIdx.x, lane = tid & 31, wid = tid >> 5;
    const int wm = wid >> 1, wn = wid & 1;
    const int b  = blockIdx.z;
    const int h  = blockIdx.y;
    const int qb = blockIdx.x;
    const int q0 = qb * 64;

    #pragma unroll
    for (int i = 0; i < 4; i++) {
        int idx = tid + (i << 8);
        int r = idx >> 4, c4 = idx & 15;
        float4 v = *reinterpret_cast<const float4*>(
            Q + ((size_t)(b * S_ + q0 + r)) * NQK_ + h * HD_ + (c4 << 2));
        v.x *= 0.125f; v.y *= 0.125f; v.z *= 0.125f; v.w *= 0.125f;
        uint32_t h0 = pack_bf2(v.x, v.y), h1 = pack_bf2(v.z, v.w);
        uint32_t l0 = pack_bf2(v.x - bf_lo_f32(h0), v.y - bf_hi_f32(h0));
        uint32_t l1 = pack_bf2(v.z - bf_lo_f32(h1), v.w - bf_hi_f32(h1));
        uint32_t off = (r * SK + (c4 << 2)) * 2;
        *reinterpret_cast<uint2*>(sm + QHI_O + off) = make_uint2(h0, h1);
        *reinterpret_cast<uint2*>(sm + QLO_O + off) = make_uint2(l0, l1);
    }
    if (tid < 64) { mrow[tid] = -INFINITY; lrow[tid] = 0.f; }

    float acc[16][4];
    #pragma unroll
    for (int i = 0; i < 16; i++)
        #pragma unroll
        for (int t = 0; t < 4; t++) acc[i][t] = 0.f;

    const float4* V4 = reinterpret_cast<const float4*>(V);

    const uint32_t aRow  = lane & 15;
    const uint32_t aColH = (lane >> 4) * 8;
    const uint32_t kbRow = (lane & 7) + ((lane >> 4) & 1) * 8;
    const uint32_t kbCol = ((lane >> 3) & 1) * 8;
    const uint32_t vbRow = (lane & 7) + ((lane >> 3) & 1) * 8;
    const uint32_t vbCol = ((lane >> 4) & 1) * 8;

    for (int kt = 0; kt <= qb; kt++) {
        const int k0 = kt * 64;
        __syncthreads();

        #pragma unroll
        for (int i = 0; i < 4; i++) {
            int idx = tid + (i << 8);
            int kk = idx >> 4, c4 = idx & 15;
            float4 v = *reinterpret_cast<const float4*>(
                K + ((size_t)(b * S_ + k0 + kk)) * NQK_ + h * HD_ + (c4 << 2));
            uint32_t h0 = pack_bf2(v.x, v.y), h1 = pack_bf2(v.z, v.w);
            uint32_t l0 = pack_bf2(v.x - bf_lo_f32(h0), v.y - bf_hi_f32(h0));
            uint32_t l1 = pack_bf2(v.z - bf_lo_f32(h1), v.w - bf_hi_f32(h1));
            uint32_t off = (kk * SK + (c4 << 2)) * 2;
            *reinterpret_cast<uint2*>(sm + KHI_O + off) = make_uint2(h0, h1);
            *reinterpret_cast<uint2*>(sm + KLO_O + off) = make_uint2(l0, l1);
        }
        #pragma unroll
        for (int i = 0; i < 16; i++) {
            int idx = tid + (i << 8);
            int kk = idx >> 6;
            int c4 = idx & 63;
            int g  = c4 >> 4, d4 = c4 & 15;
            float4 v = V4[((size_t)(b * S_ + k0 + kk)) * (HID_ / 4)
                          + g * (NQK_ / 4) + h * (HD_ / 4) + d4];
            uint32_t h0 = pack_bf2(v.x, v.y), h1 = pack_bf2(v.z, v.w);
            uint32_t l0 = pack_bf2(v.x - bf_lo_f32(h0), v.y - bf_hi_f32(h0));
            uint32_t l1 = pack_bf2(v.z - bf_lo_f32(h1), v.w - bf_hi_f32(h1));
            uint32_t off = (kk * SV + (c4 << 2)) * 2;
            *reinterpret_cast<uint2*>(sm + VHI_O + off) = make_uint2(h0, h1);
            *reinterpret_cast<uint2*>(sm + VLO_O + off) = make_uint2(l0, l1);
        }
        __syncthreads();

        {
            float sfr[4][4];
            #pragma unroll
            for (int i = 0; i < 4; i++)
                #pragma unroll
                for (int t = 0; t < 4; t++) sfr[i][t] = 0.f;

            #pragma unroll
            for (int ks = 0; ks < 4; ks++) {
                uint32_t aH[4], aL[4];
                uint32_t ao = ((wm * 16 + aRow) * SK + ks * 16 + aColH) * 2;
                ldmx4(aH, smb + QHI_O + ao);
                ldmx4(aL, smb + QLO_O + ao);
                #pragma unroll
                for (int np = 0; np < 2; np++) {
                    uint32_t bH[4], bL[4];
                    uint32_t nb = wn * 32 + np * 16;
                    uint32_t bo = ((nb + kbRow) * SK + ks * 16 + kbCol) * 2;
                    ldmx4(bH, smb + KHI_O + bo);
                    ldmx4(bL, smb + KLO_O + bo);
                    mma16816(sfr[np*2+0], aH, bH);
                    mma16816(sfr[np*2+0], aL, bH);
                    mma16816(sfr[np*2+0], aH, bL);
                    mma16816(sfr[np*2+1], aH, bH + 2);
                    mma16816(sfr[np*2+1], aL, bH + 2);
                    mma16816(sfr[np*2+1], aH, bL + 2);
                }
            }
            int r0 = wm * 16 + (lane >> 2);
            #pragma unroll
            for (int nf = 0; nf < 4; nf++) {
                int cb = wn * 32 + nf * 8 + (lane & 3) * 2;
                *reinterpret_cast<float2*>(&Ps[r0 * PITX + cb]) =
                    make_float2(sfr[nf][0], sfr[nf][1]);
                *reinterpret_cast<float2*>(&Ps[(r0 + 8) * PITX + cb]) =
                    make_float2(sfr[nf][2], sfr[nf][3]);
            }
        }
        __syncthreads();

        if (tid < 64) {
            const int row = tid;
            const int kmax = (kt == qb) ? row : 63;
            float m_old = mrow[row];
            float mx = m_old;
            for (int k = 0; k <= kmax; k++) mx = fmaxf(mx, Ps[row * PITX + k]);
            float sum = 0.f;
            for (int k = 0; k < 64; k++) {
                float p = (k <= kmax) ? expf(Ps[row * PITX + k] - mx) : 0.f;
                Ps[row * PITX + k] = p;
                sum += p;
            }
            float f = expf(m_old - mx);
            sfac[row] = f;
            lrow[row] = lrow[row] * f + sum;
            mrow[row] = mx;
        }
        __syncthreads();

        {
            int row = tid >> 2;
            int cb  = (tid & 3) * 16;
            #pragma unroll
            for (int j = 0; j < 8; j++) {
                float p0 = Ps[row * PITX + cb + 2*j];
                float p1 = Ps[row * PITX + cb + 2*j + 1];
                uint32_t ph = pack_bf2(p0, p1);
                uint32_t pl = pack_bf2(p0 - bf_lo_f32(ph), p1 - bf_hi_f32(ph));
                uint32_t off = (row * SK + cb + 2*j) * 2;
                *reinterpret_cast<uint32_t*>(sm + PHI_O + off) = ph;
                *reinterpret_cast<uint32_t*>(sm + PLO_O + off) = pl;
            }
        }
        __syncthreads();

        {
            float f0 = sfac[wm * 16 + (lane >> 2)];
            float f1 = sfac[wm * 16 + (lane >> 2) + 8];
            #pragma unroll
            for (int i = 0; i < 16; i++) {
                acc[i][0] *= f0; acc[i][1] *= f0;
                acc[i][2] *= f1; acc[i][3] *= f1;
            }
            #pragma unroll
            for (int ks = 0; ks < 4; ks++) {
                uint32_t pH[4], pL[4];
                uint32_t ao = ((wm * 16 + aRow) * SK + ks * 16 + aColH) * 2;
                ldmx4(pH, smb + PHI_O + ao);
                ldmx4(pL, smb + PLO_O + ao);
                #pragma unroll
                for (int np = 0; np < 8; np++) {
                    uint32_t vH[4], vL[4];
                    uint32_t nb = wn * 128 + np * 16;
                    uint32_t bo = ((ks * 16 + vbRow) * SV + nb + vbCol) * 2;
                    ldmx4t(vH, smb + VHI_O + bo);
                    ldmx4t(vL, smb + VLO_O + bo);
                    mma16816(acc[np*2+0], pH, vH);
                    mma16816(acc[np*2+0], pL, vH);
                    mma16816(acc[np*2+0], pH, vL);
                    mma16816(acc[np*2+1], pH, vH + 2);
                    mma16816(acc[np*2+1], pL, vH + 2);
                    mma16816(acc[np*2+1], pH, vL + 2);
                }
            }
        }
    }
    __syncthreads();

    {
        int r0 = wm * 16 + (lane >> 2);
        float invl0 = 1.f / lrow[r0];
        float invl1 = 1.f / lrow[r0 + 8];
        #pragma unroll
        for (int nf = 0; nf < 16; nf++) {
            int cl = wn * 128 + nf * 8 + (lane & 3) * 2;
            int g  = cl >> 6, d = cl & 63;
            size_t ob0 = ((size_t)(b * S_ + q0 + r0)) * HID_ + (g * HKV_ + h) * HD_ + d;
            size_t ob1 = ((size_t)(b * S_ + q0 + r0 + 8)) * HID_ + (g * HKV_ + h) * HD_ + d;
            *reinterpret_cast<float2*>(&Out[ob0]) =
                make_float2(acc[nf][0] * invl0, acc[nf][1] * invl0);
            *reinterpret_cast<float2*>(&Out[ob1]) =
                make_float2(acc[nf][2] * invl1, acc[nf][3] * invl1);
        }
    }
}

// ---------------------------------------------------------------------------
extern "C" void kernel_launch(void* const* d_in, const int* in_sizes, int n_in,
                              void* d_out, int out_size) {
    const float* X   = (const float*)d_in[0];
    const int*   pid = (const int*)  d_in[1];
    const float* Wq  = (const float*)d_in[2];
    const float* Wk  = (const float*)d_in[3];
    const float* Wv  = (const float*)d_in[4];
    float* Out = (float*)d_out;

    float *dQ, *dK, *dV;
    cudaGetSymbolAddress((void**)&dQ, g_Q);
    cudaGetSymbolAddress((void**)&dK, g_K);
    cudaGetSymbolAddress((void**)&dV, g_V);
    uint2 *xh, *xl, *wqh, *wql, *wkh, *wkl, *wvh, *wvl;
    cudaGetSymbolAddress((void**)&xh,  g_Xh);  cudaGetSymbolAddress((void**)&xl,  g_Xl);
    cudaGetSymbolAddress((void**)&wqh, g_Wqh); cudaGetSymbolAddress((void**)&wql, g_Wql);
    cudaGetSymbolAddress((void**)&wkh, g_Wkh); cudaGetSymbolAddress((void**)&wkl, g_Wkl);
    cudaGetSymbolAddress((void**)&wvh, g_Wvh); cudaGetSymbolAddress((void**)&wvl, g_Wvl);

    // Pre-convert operands to bf16 hi/lo
    {
        int nX = M_ * HID_ / 4, nWqk = HID_ * NQK_ / 4, nWv = HID_ * HID_ / 4;
        cvt_hilo_kernel<<<(nX + 255) / 256, 256>>>((const float4*)X, xh, xl, nX);
        cvt_hilo_kernel<<<(nWqk + 255) / 256, 256>>>((const float4*)Wq, wqh, wql, nWqk);
        cvt_hilo_kernel<<<(nWqk + 255) / 256, 256>>>((const float4*)Wk, wkh, wkl, nWqk);
        cvt_hilo_kernel<<<(nWv + 255) / 256, 256>>>((const float4*)Wv, wvh, wvl, nWv);
    }

    // Projections: fused Q/K launch (N=512 -> 2 n-blocks) + V launch
    {
        cudaFuncSetAttribute(gemm_pipe_kernel,
                             cudaFuncAttributeMaxDynamicSharedMemorySize, GEMM_SMEM);
        dim3 blk(256);
        dim3 grdQK(NQK_ / 256, M_ / 128, 2);
        gemm_pipe_kernel<<<grdQK, blk, GEMM_SMEM>>>(xh, xl, wqh, wql, dQ,
                                                    wkh, wkl, dK, NQK_, HID_);
        dim3 grdV(HID_ / 256, M_ / 128, 1);
        gemm_pipe_kernel<<<grdV, blk, GEMM_SMEM>>>(xh, xl, wvh, wvl, dV,
                                                   wvh, wvl, dV, HID_, HID_);
    }
    {
        int total = B_ * S_ * HKV_ * 32;
        rope_kernel<<<(total + 255) / 256, 256>>>(dQ, dK, pid);
    }
    {
        cudaFuncSetAttribute(attn_mma_kernel,
                             cudaFuncAttributeMaxDynamicSharedMemorySize, ATTN_SMEM);
        dim3 grd(S_ / 64, HKV_, B_);
        attn_mma_kernel<<<grd, 256, ATTN_SMEM>>>(dQ, dK, dV, Out);
    }
}

// round 7
// speedup vs baseline: 3.2634x; 1.0866x over previous
#include <cuda_runtime.h>
#include <cuda_bf16.h>
#include <cuda_fp16.h>
#include <math.h>
#include <stdint.h>

#define B_   2
#define S_   2048
#define HID_ 2048
#define NH_  32
#define G_   4
#define HD_  64
#define HKV_ 8
#define NQK_ 512   // HKV_*HD_
#define M_   (B_ * S_)   // 4096

// Scratch (device globals: no allocation allowed)
__device__ float g_Q[(size_t)M_*NQK_];
__device__ float g_K[(size_t)M_*NQK_];
__device__ float g_V[(size_t)M_*HID_];
// fp16 hi/lo pre-converted operands (uint2 = 4 halves)
__device__ uint2 g_Xh[(size_t)M_*HID_/4],  g_Xl[(size_t)M_*HID_/4];
__device__ uint2 g_Wqh[(size_t)HID_*NQK_/4], g_Wql[(size_t)HID_*NQK_/4];
__device__ uint2 g_Wkh[(size_t)HID_*NQK_/4], g_Wkl[(size_t)HID_*NQK_/4];
__device__ uint2 g_Wvh[(size_t)HID_*HID_/4];   // V weights: hi only (2-term split)

// ===========================================================================
// helpers
// ===========================================================================
__device__ __forceinline__ uint32_t smem_to_u32(const void* smem_ptr) {
    uint32_t addr;
    asm("{ .reg .u64 tmp; cvta.to.shared.u64 tmp, %1; cvt.u32.u64 %0, tmp; }"
        : "=r"(addr) : "l"(smem_ptr));
    return addr;
}
// bf16 pack (attention kernel)
__device__ __forceinline__ uint32_t pack_bf2(float a, float b) {
    uint32_t r;
    asm("cvt.rn.bf16x2.f32 %0, %1, %2;" : "=r"(r) : "f"(b), "f"(a));
    return r;
}
__device__ __forceinline__ float bf_lo_f32(uint32_t h) { return __uint_as_float(h << 16); }
__device__ __forceinline__ float bf_hi_f32(uint32_t h) { return __uint_as_float(h & 0xFFFF0000u); }
// fp16 pack: lo = a, hi = b
__device__ __forceinline__ uint32_t pack_hf2(float a, float b) {
    uint32_t r;
    asm("cvt.rn.f16x2.f32 %0, %1, %2;" : "=r"(r) : "f"(b), "f"(a));
    return r;
}
__device__ __forceinline__ float hf_lo_f32(uint32_t h) {
    __half2 v = *reinterpret_cast<__half2*>(&h);
    return __low2float(v);
}
__device__ __forceinline__ float hf_hi_f32(uint32_t h) {
    __half2 v = *reinterpret_cast<__half2*>(&h);
    return __high2float(v);
}

__device__ __forceinline__ void ldmx4(uint32_t r[4], uint32_t addr) {
    asm volatile("ldmatrix.sync.aligned.m8n8.x4.shared.b16 {%0,%1,%2,%3}, [%4];"
        : "=r"(r[0]), "=r"(r[1]), "=r"(r[2]), "=r"(r[3]) : "r"(addr));
}
__device__ __forceinline__ void ldmx4t(uint32_t r[4], uint32_t addr) {
    asm volatile("ldmatrix.sync.aligned.m8n8.x4.trans.shared.b16 {%0,%1,%2,%3}, [%4];"
        : "=r"(r[0]), "=r"(r[1]), "=r"(r[2]), "=r"(r[3]) : "r"(addr));
}
__device__ __forceinline__ void mma16816(float d[4], const uint32_t a[4],
                                         const uint32_t b[2]) {
    asm volatile(
        "mma.sync.aligned.m16n8k16.row.col.f32.bf16.bf16.f32 "
        "{%0,%1,%2,%3}, {%4,%5,%6,%7}, {%8,%9}, {%0,%1,%2,%3};"
        : "+f"(d[0]), "+f"(d[1]), "+f"(d[2]), "+f"(d[3])
        : "r"(a[0]), "r"(a[1]), "r"(a[2]), "r"(a[3]), "r"(b[0]), "r"(b[1]));
}
__device__ __forceinline__ void mma16816h(float d[4], const uint32_t a[4],
                                          const uint32_t b[2]) {
    asm volatile(
        "mma.sync.aligned.m16n8k16.row.col.f32.f16.f16.f32 "
        "{%0,%1,%2,%3}, {%4,%5,%6,%7}, {%8,%9}, {%0,%1,%2,%3};"
        : "+f"(d[0]), "+f"(d[1]), "+f"(d[2]), "+f"(d[3])
        : "r"(a[0]), "r"(a[1]), "r"(a[2]), "r"(a[3]), "r"(b[0]), "r"(b[1]));
}
__device__ __forceinline__ void cp16(uint32_t dst, const void* src) {
    asm volatile("cp.async.cg.shared.global [%0], [%1], 16;"
                 :: "r"(dst), "l"(src));
}
__device__ __forceinline__ void cp_commit() {
    asm volatile("cp.async.commit_group;" ::: "memory");
}
template <int N>
__device__ __forceinline__ void cp_wait() {
    asm volatile("cp.async.wait_group %0;" :: "n"(N) : "memory");
}

// ===========================================================================
// Pre-convert fp32 -> fp16 hi/lo (and hi-only variant)
// ===========================================================================
__global__ void cvt_f16_hilo_kernel(const float4* __restrict__ src,
                                    uint2* __restrict__ hi, uint2* __restrict__ lo,
                                    int n4) {
    int i = blockIdx.x * blockDim.x + threadIdx.x;
    if (i >= n4) return;
    float4 v = src[i];
    uint32_t h0 = pack_hf2(v.x, v.y), h1 = pack_hf2(v.z, v.w);
    uint32_t l0 = pack_hf2(v.x - hf_lo_f32(h0), v.y - hf_hi_f32(h0));
    uint32_t l1 = pack_hf2(v.z - hf_lo_f32(h1), v.w - hf_hi_f32(h1));
    hi[i] = make_uint2(h0, h1);
    lo[i] = make_uint2(l0, l1);
}
__global__ void cvt_f16_hi_kernel(const float4* __restrict__ src,
                                  uint2* __restrict__ hi, int n4) {
    int i = blockIdx.x * blockDim.x + threadIdx.x;
    if (i >= n4) return;
    float4 v = src[i];
    hi[i] = make_uint2(pack_hf2(v.x, v.y), pack_hf2(v.z, v.w));
}

// ===========================================================================
// 4-stage cp.async fp16 GEMM: C[M,N] = A[M,K] @ B[K,N]
// CTA tile 128x256, warp tile 64x64 (8 warps 2m x 4n), K-chunk 32, occ 1.
// SPLIT_B: 3-term (AhBh+AlBh+AhBl) vs 2-term (AhBh+AlBh, B hi only).
// ===========================================================================
#define SAe 40      // A row stride (fp16): 80 B
#define SBe 264     // B row stride (fp16): 528 B
#define ST_AHI 0
#define ST_ALO 10240
#define ST_BHI 20480
#define ST_BLO 37376
#define ST_SZ  54272
#define NSTG 4
#define GEMM_SMEM (NSTG * ST_SZ)   // 217088

template<bool SPLIT_B>
__global__ __launch_bounds__(256, 1)
void gemm_pipe_kernel(const void* __restrict__ Ah, const void* __restrict__ Al,
                      const void* __restrict__ Bh0, const void* __restrict__ Bl0,
                      float* __restrict__ C0,
                      const void* __restrict__ Bh1, const void* __restrict__ Bl1,
                      float* __restrict__ C1,
                      int N, int K) {
    extern __shared__ char sm[];
    const uint32_t smb = smem_to_u32(sm);
    const int tid = threadIdx.x, lane = tid & 31, wid = tid >> 5;
    const int wm = wid >> 2, wn = wid & 3;       // 2m x 4n
    const int m0 = blockIdx.y * 128, n0 = blockIdx.x * 256;

    const char* Bh = (const char*)(blockIdx.z ? Bh1 : Bh0);
    const char* Bl = (const char*)(blockIdx.z ? Bl1 : Bl0);
    float* C = blockIdx.z ? C1 : C0;
    const char* Ahc = (const char*)Ah;
    const char* Alc = (const char*)Al;

    float acc[4][8][4];
    #pragma unroll
    for (int i = 0; i < 4; i++)
        #pragma unroll
        for (int j = 0; j < 8; j++)
            #pragma unroll
            for (int t = 0; t < 4; t++) acc[i][j][t] = 0.f;

    const uint32_t aRow  = lane & 15;
    const uint32_t aColH = (lane >> 4) * 8;
    const uint32_t bRow  = (lane & 7) + ((lane >> 3) & 1) * 8;
    const uint32_t bCol  = ((lane >> 4) & 1) * 8;
    const int nch = K >> 5;

    auto issue = [&](int s, int k0) {
        uint32_t sb = smb + s * ST_SZ;
        #pragma unroll
        for (int i = 0; i < 2; i++) {
            int idx = tid + (i << 8);
            int row = idx >> 2, seg = idx & 3;
            size_t go = ((size_t)(m0 + row) * K + k0 + seg * 8) * 2;
            uint32_t so = row * 80 + seg * 16;
            cp16(sb + ST_AHI + so, Ahc + go);
            cp16(sb + ST_ALO + so, Alc + go);
        }
        #pragma unroll
        for (int i = 0; i < 4; i++) {
            int idx = tid + (i << 8);
            int row = idx >> 5, seg = idx & 31;
            size_t go = ((size_t)(k0 + row) * N + n0 + seg * 8) * 2;
            uint32_t so = row * 528 + seg * 16;
            cp16(sb + ST_BHI + so, Bh + go);
            if (SPLIT_B) cp16(sb + ST_BLO + so, Bl + go);
        }
        cp_commit();
    };

    issue(0, 0);
    issue(1, 32);
    for (int c = 0; c < nch; c++) {
        if (c + 2 < nch) issue((c + 2) & (NSTG - 1), (c + 2) << 5);
        else             cp_commit();
        cp_wait<2>();
        __syncthreads();

        const uint32_t sb = smb + (c & (NSTG - 1)) * ST_SZ;
        #pragma unroll
        for (int ks = 0; ks < 2; ks++) {
            uint32_t aH[4][4], aL[4][4];
            #pragma unroll
            for (int mf = 0; mf < 4; mf++) {
                uint32_t ao = ((wm * 64 + mf * 16 + aRow) * SAe + ks * 16 + aColH) * 2;
                ldmx4(aH[mf], sb + ST_AHI + ao);
                ldmx4(aL[mf], sb + ST_ALO + ao);
            }
            uint32_t bH[4][4], bL[4][4];
            #pragma unroll
            for (int ng = 0; ng < 4; ng++) {
                uint32_t bo = ((ks * 16 + bRow) * SBe + wn * 64 + ng * 16 + bCol) * 2;
                ldmx4t(bH[ng], sb + ST_BHI + bo);
                if (SPLIT_B) ldmx4t(bL[ng], sb + ST_BLO + bo);
            }
            #pragma unroll
            for (int mf = 0; mf < 4; mf++)
                #pragma unroll
                for (int ng = 0; ng < 4; ng++) {
                    mma16816h(acc[mf][ng*2+0], aH[mf], bH[ng]);
                    mma16816h(acc[mf][ng*2+0], aL[mf], bH[ng]);
                    if (SPLIT_B) mma16816h(acc[mf][ng*2+0], aH[mf], bL[ng]);
                    mma16816h(acc[mf][ng*2+1], aH[mf], bH[ng] + 2);
                    mma16816h(acc[mf][ng*2+1], aL[mf], bH[ng] + 2);
                    if (SPLIT_B) mma16816h(acc[mf][ng*2+1], aH[mf], bL[ng] + 2);
                }
        }
    }

    #pragma unroll
    for (int mf = 0; mf < 4; mf++) {
        int row = m0 + wm * 64 + mf * 16 + (lane >> 2);
        #pragma unroll
        for (int nf = 0; nf < 8; nf++) {
            int col = n0 + wn * 64 + nf * 8 + (lane & 3) * 2;
            *reinterpret_cast<float2*>(C + (size_t)row * N + col) =
                make_float2(acc[mf][nf][0], acc[mf][nf][1]);
            *reinterpret_cast<float2*>(C + (size_t)(row + 8) * N + col) =
                make_float2(acc[mf][nf][2], acc[mf][nf][3]);
        }
    }
}

// ---------------------------------------------------------------------------
// RoPE (unchanged)
// ---------------------------------------------------------------------------
__global__ void rope_kernel(float* __restrict__ Q, float* __restrict__ K,
                            const int* __restrict__ pos_ids) {
    int idx = blockIdx.x * blockDim.x + threadIdx.x;
    if (idx >= B_ * S_ * HKV_ * 32) return;
    int d   = idx & 31;
    int h   = (idx >> 5) & (HKV_ - 1);
    int row = idx >> 8;
    float p    = (float)pos_ids[row];
    float invf = powf(10000.0f, -(float)d * (1.0f / 32.0f));
    float a = p * invf;
    float sn, cs;
    sincosf(a, &sn, &cs);
    size_t base = (size_t)row * NQK_ + h * HD_;
    float q0 = Q[base + d], q1 = Q[base + d + 32];
    Q[base + d]      = q0 * cs - q1 * sn;
    Q[base + d + 32] = q1 * cs + q0 * sn;
    float k0 = K[base + d], k1 = K[base + d + 32];
    K[base + d]      = k0 * cs - k1 * sn;
    K[base + d + 32] = k1 * cs + k0 * sn;
}

// ===========================================================================
// Flash attention on mma.sync (unchanged, bf16 3-term)
// ===========================================================================
#define SK   72
#define SV   264
#define PITX 66
#define QHI_O 0
#define QLO_O 9216
#define KHI_O 18432
#define KLO_O 27648
#define VHI_O 36864
#define VLO_O 70656
#define PS_O  104448
#define PHI_O 121344
#define PLO_O 130560
#define MR_O  139776
#define LR_O  140032
#define SF_O  140288
#define ATTN_SMEM 140544

__global__ __launch_bounds__(256, 1)
void attn_mma_kernel(const float* __restrict__ Q, const float* __restrict__ K,
                     const float* __restrict__ V, float* __restrict__ Out) {
    extern __shared__ char sm[];
    const uint32_t smb = smem_to_u32(sm);
    float* Ps   = reinterpret_cast<float*>(sm + PS_O);
    float* mrow = reinterpret_cast<float*>(sm + MR_O);
    float* lrow = reinterpret_cast<float*>(sm + LR_O);
    float* sfac = reinterpret_cast<float*>(sm + SF_O);

    const int tid = threadIdx.x, lane = tid & 31, wid = tid >> 5;
    const int wm = wid >> 1, wn = wid & 1;
    const int b  = blockIdx.z;
    const int h  = blockIdx.y;
    const int qb = blockIdx.x;
    const int q0 = qb * 64;

    #pragma unroll
    for (int i = 0; i < 4; i++) {
        int idx = tid + (i << 8);
        int r = idx >> 4, c4 = idx & 15;
        float4 v = *reinterpret_cast<const float4*>(
            Q + ((size_t)(b * S_ + q0 + r)) * NQK_ + h * HD_ + (c4 << 2));
        v.x *= 0.125f; v.y *= 0.125f; v.z *= 0.125f; v.w *= 0.125f;
        uint32_t h0 = pack_bf2(v.x, v.y), h1 = pack_bf2(v.z, v.w);
        uint32_t l0 = pack_bf2(v.x - bf_lo_f32(h0), v.y - bf_hi_f32(h0));
        uint32_t l1 = pack_bf2(v.z - bf_lo_f32(h1), v.w - bf_hi_f32(h1));
        uint32_t off = (r * SK + (c4 << 2)) * 2;
        *reinterpret_cast<uint2*>(sm + QHI_O + off) = make_uint2(h0, h1);
        *reinterpret_cast<uint2*>(sm + QLO_O + off) = make_uint2(l0, l1);
    }
    if (tid < 64) { mrow[tid] = -INFINITY; lrow[tid] = 0.f; }

    float acc[16][4];
    #pragma unroll
    for (int i = 0; i < 16; i++)
        #pragma unroll
        for (int t = 0; t < 4; t++) acc[i][t] = 0.f;

    const float4* V4 = reinterpret_cast<const float4*>(V);

    const uint32_t aRow  = lane & 15;
    const uint32_t aColH = (lane >> 4) * 8;
    const uint32_t kbRow = (lane & 7) + ((lane >> 4) & 1) * 8;
    const uint32_t kbCol = ((lane >> 3) & 1) * 8;
    const uint32_t vbRow = (lane & 7) + ((lane >> 3) & 1) * 8;
    const uint32_t vbCol = ((lane >> 4) & 1) * 8;

    for (int kt = 0; kt <= qb; kt++) {
        const int k0 = kt * 64;
        __syncthreads();

        #pragma unroll
        for (int i = 0; i < 4; i++) {
            int idx = tid + (i << 8);
            int kk = idx >> 4, c4 = idx & 15;
            float4 v = *reinterpret_cast<const float4*>(
                K + ((size_t)(b * S_ + k0 + kk)) * NQK_ + h * HD_ + (c4 << 2));
            uint32_t h0 = pack_bf2(v.x, v.y), h1 = pack_bf2(v.z, v.w);
            uint32_t l0 = pack_bf2(v.x - bf_lo_f32(h0), v.y - bf_hi_f32(h0));
            uint32_t l1 = pack_bf2(v.z - bf_lo_f32(h1), v.w - bf_hi_f32(h1));
            uint32_t off = (kk * SK + (c4 << 2)) * 2;
            *reinterpret_cast<uint2*>(sm + KHI_O + off) = make_uint2(h0, h1);
            *reinterpret_cast<uint2*>(sm + KLO_O + off) = make_uint2(l0, l1);
        }
        #pragma unroll
        for (int i = 0; i < 16; i++) {
            int idx = tid + (i << 8);
            int kk = idx >> 6;
            int c4 = idx & 63;
            int g  = c4 >> 4, d4 = c4 & 15;
            float4 v = V4[((size_t)(b * S_ + k0 + kk)) * (HID_ / 4)
                          + g * (NQK_ / 4) + h * (HD_ / 4) + d4];
            uint32_t h0 = pack_bf2(v.x, v.y), h1 = pack_bf2(v.z, v.w);
            uint32_t l0 = pack_bf2(v.x - bf_lo_f32(h0), v.y - bf_hi_f32(h0));
            uint32_t l1 = pack_bf2(v.z - bf_lo_f32(h1), v.w - bf_hi_f32(h1));
            uint32_t off = (kk * SV + (c4 << 2)) * 2;
            *reinterpret_cast<uint2*>(sm + VHI_O + off) = make_uint2(h0, h1);
            *reinterpret_cast<uint2*>(sm + VLO_O + off) = make_uint2(l0, l1);
        }
        __syncthreads();

        {
            float sfr[4][4];
            #pragma unroll
            for (int i = 0; i < 4; i++)
                #pragma unroll
                for (int t = 0; t < 4; t++) sfr[i][t] = 0.f;

            #pragma unroll
            for (int ks = 0; ks < 4; ks++) {
                uint32_t aH[4], aL[4];
                uint32_t ao = ((wm * 16 + aRow) * SK + ks * 16 + aColH) * 2;
                ldmx4(aH, smb + QHI_O + ao);
                ldmx4(aL, smb + QLO_O + ao);
                #pragma unroll
                for (int np = 0; np < 2; np++) {
                    uint32_t bH[4], bL[4];
                    uint32_t nb = wn * 32 + np * 16;
                    uint32_t bo = ((nb + kbRow) * SK + ks * 16 + kbCol) * 2;
                    ldmx4(bH, smb + KHI_O + bo);
                    ldmx4(bL, smb + KLO_O + bo);
                    mma16816(sfr[np*2+0], aH, bH);
                    mma16816(sfr[np*2+0], aL, bH);
                    mma16816(sfr[np*2+0], aH, bL);
                    mma16816(sfr[np*2+1], aH, bH + 2);
                    mma16816(sfr[np*2+1], aL, bH + 2);
                    mma16816(sfr[np*2+1], aH, bL + 2);
                }
            }
            int r0 = wm * 16 + (lane >> 2);
            #pragma unroll
            for (int nf = 0; nf < 4; nf++) {
                int cb = wn * 32 + nf * 8 + (lane & 3) * 2;
                *reinterpret_cast<float2*>(&Ps[r0 * PITX + cb]) =
                    make_float2(sfr[nf][0], sfr[nf][1]);
                *reinterpret_cast<float2*>(&Ps[(r0 + 8) * PITX + cb]) =
                    make_float2(sfr[nf][2], sfr[nf][3]);
            }
        }
        __syncthreads();

        if (tid < 64) {
            const int row = tid;
            const int kmax = (kt == qb) ? row : 63;
            float m_old = mrow[row];
            float mx = m_old;
            for (int k = 0; k <= kmax; k++) mx = fmaxf(mx, Ps[row * PITX + k]);
            float sum = 0.f;
            for (int k = 0; k < 64; k++) {
                float p = (k <= kmax) ? expf(Ps[row * PITX + k] - mx) : 0.f;
                Ps[row * PITX + k] = p;
                sum += p;
            }
            float f = expf(m_old - mx);
            sfac[row] = f;
            lrow[row] = lrow[row] * f + sum;
            mrow[row] = mx;
        }
        __syncthreads();

        {
            int row = tid >> 2;
            int cb  = (tid & 3) * 16;
            #pragma unroll
            for (int j = 0; j < 8; j++) {
                float p0 = Ps[row * PITX + cb + 2*j];
                float p1 = Ps[row * PITX + cb + 2*j + 1];
                uint32_t ph = pack_bf2(p0, p1);
                uint32_t pl = pack_bf2(p0 - bf_lo_f32(ph), p1 - bf_hi_f32(ph));
                uint32_t off = (row * SK + cb + 2*j) * 2;
                *reinterpret_cast<uint32_t*>(sm + PHI_O + off) = ph;
                *reinterpret_cast<uint32_t*>(sm + PLO_O + off) = pl;
            }
        }
        __syncthreads();

        {
            float f0 = sfac[wm * 16 + (lane >> 2)];
            float f1 = sfac[wm * 16 + (lane >> 2) + 8];
            #pragma unroll
            for (int i = 0; i < 16; i++) {
                acc[i][0] *= f0; acc[i][1] *= f0;
                acc[i][2] *= f1; acc[i][3] *= f1;
            }
            #pragma unroll
            for (int ks = 0; ks < 4; ks++) {
                uint32_t pH[4], pL[4];
                uint32_t ao = ((wm * 16 + aRow) * SK + ks * 16 + aColH) * 2;
                ldmx4(pH, smb + PHI_O + ao);
                ldmx4(pL, smb + PLO_O + ao);
                #pragma unroll
                for (int np = 0; np < 8; np++) {
                    uint32_t vH[4], vL[4];
                    uint32_t nb = wn * 128 + np * 16;
                    uint32_t bo = ((ks * 16 + vbRow) * SV + nb + vbCol) * 2;
                    ldmx4t(vH, smb + VHI_O + bo);
                    ldmx4t(vL, smb + VLO_O + bo);
                    mma16816(acc[np*2+0], pH, vH);
                    mma16816(acc[np*2+0], pL, vH);
                    mma16816(acc[np*2+0], pH, vL);
                    mma16816(acc[np*2+1], pH, vH + 2);
                    mma16816(acc[np*2+1], pL, vH + 2);
                    mma16816(acc[np*2+1], pH, vL + 2);
                }
            }
        }
    }
    __syncthreads();

    {
        int r0 = wm * 16 + (lane >> 2);
        float invl0 = 1.f / lrow[r0];
        float invl1 = 1.f / lrow[r0 + 8];
        #pragma unroll
        for (int nf = 0; nf < 16; nf++) {
            int cl = wn * 128 + nf * 8 + (lane & 3) * 2;
            int g  = cl >> 6, d = cl & 63;
            size_t ob0 = ((size_t)(b * S_ + q0 + r0)) * HID_ + (g * HKV_ + h) * HD_ + d;
            size_t ob1 = ((size_t)(b * S_ + q0 + r0 + 8)) * HID_ + (g * HKV_ + h) * HD_ + d;
            *reinterpret_cast<float2*>(&Out[ob0]) =
                make_float2(acc[nf][0] * invl0, acc[nf][1] * invl0);
            *reinterpret_cast<float2*>(&Out[ob1]) =
                make_float2(acc[nf][2] * invl1, acc[nf][3] * invl1);
        }
    }
}

// ---------------------------------------------------------------------------
extern "C" void kernel_launch(void* const* d_in, const int* in_sizes, int n_in,
                              void* d_out, int out_size) {
    const float* X   = (const float*)d_in[0];
    const int*   pid = (const int*)  d_in[1];
    const float* Wq  = (const float*)d_in[2];
    const float* Wk  = (const float*)d_in[3];
    const float* Wv  = (const float*)d_in[4];
    float* Out = (float*)d_out;

    float *dQ, *dK, *dV;
    cudaGetSymbolAddress((void**)&dQ, g_Q);
    cudaGetSymbolAddress((void**)&dK, g_K);
    cudaGetSymbolAddress((void**)&dV, g_V);
    uint2 *xh, *xl, *wqh, *wql, *wkh, *wkl, *wvh;
    cudaGetSymbolAddress((void**)&xh,  g_Xh);  cudaGetSymbolAddress((void**)&xl,  g_Xl);
    cudaGetSymbolAddress((void**)&wqh, g_Wqh); cudaGetSymbolAddress((void**)&wql, g_Wql);
    cudaGetSymbolAddress((void**)&wkh, g_Wkh); cudaGetSymbolAddress((void**)&wkl, g_Wkl);
    cudaGetSymbolAddress((void**)&wvh, g_Wvh);

    // Pre-convert operands to fp16 hi/lo (Wv: hi only)
    {
        int nX = M_ * HID_ / 4, nWqk = HID_ * NQK_ / 4, nWv = HID_ * HID_ / 4;
        cvt_f16_hilo_kernel<<<(nX + 255) / 256, 256>>>((const float4*)X, xh, xl, nX);
        cvt_f16_hilo_kernel<<<(nWqk + 255) / 256, 256>>>((const float4*)Wq, wqh, wql, nWqk);
        cvt_f16_hilo_kernel<<<(nWqk + 255) / 256, 256>>>((const float4*)Wk, wkh, wkl, nWqk);
        cvt_f16_hi_kernel<<<(nWv + 255) / 256, 256>>>((const float4*)Wv, wvh, nWv);
    }

    // Projections: fused Q/K (3-term) + V (2-term)
    {
        cudaFuncSetAttribute(gemm_pipe_kernel<true>,
                             cudaFuncAttributeMaxDynamicSharedMemorySize, GEMM_SMEM);
        cudaFuncSetAttribute(gemm_pipe_kernel<false>,
                             cudaFuncAttributeMaxDynamicSharedMemorySize, GEMM_SMEM);
        dim3 blk(256);
        dim3 grdQK(NQK_ / 256, M_ / 128, 2);
        gemm_pipe_kernel<true><<<grdQK, blk, GEMM_SMEM>>>(xh, xl, wqh, wql, dQ,
                                                          wkh, wkl, dK, NQK_, HID_);
        dim3 grdV(HID_ / 256, M_ / 128, 1);
        gemm_pipe_kernel<false><<<grdV, blk, GEMM_SMEM>>>(xh, xl, wvh, wvh, dV,
                                                          wvh, wvh, dV, HID_, HID_);
    }
    {
        int total = B_ * S_ * HKV_ * 32;
        rope_kernel<<<(total + 255) / 256, 256>>>(dQ, dK, pid);
    }
    {
        cudaFuncSetAttribute(attn_mma_kernel,
                             cudaFuncAttributeMaxDynamicSharedMemorySize, ATTN_SMEM);
        dim3 grd(S_ / 64, HKV_, B_);
        attn_mma_kernel<<<grd, 256, ATTN_SMEM>>>(dQ, dK, dV, Out);
    }
}

// round 8
// speedup vs baseline: 4.0072x; 1.2279x over previous
#include <cuda_runtime.h>
#include <cuda_bf16.h>
#include <cuda_fp16.h>
#include <math.h>
#include <stdint.h>

#define B_   2
#define S_   2048
#define HID_ 2048
#define NH_  32
#define G_   4
#define HD_  64
#define HKV_ 8
#define NQK_ 512   // HKV_*HD_
#define M_   (B_ * S_)   // 4096

// Scratch (device globals: no allocation allowed)
__device__ float g_Q[(size_t)M_*NQK_];
__device__ float g_K[(size_t)M_*NQK_];
__device__ float g_V[(size_t)M_*HID_];
// fp16 hi/lo pre-converted operands (uint2 = 4 halves)
__device__ uint2 g_Xh[(size_t)M_*HID_/4],  g_Xl[(size_t)M_*HID_/4];
__device__ uint2 g_Wqh[(size_t)HID_*NQK_/4], g_Wql[(size_t)HID_*NQK_/4];
__device__ uint2 g_Wkh[(size_t)HID_*NQK_/4], g_Wkl[(size_t)HID_*NQK_/4];
__device__ uint2 g_Wvh[(size_t)HID_*HID_/4];   // V weights: hi only (2-term split)

// ===========================================================================
// helpers
// ===========================================================================
__device__ __forceinline__ uint32_t smem_to_u32(const void* smem_ptr) {
    uint32_t addr;
    asm("{ .reg .u64 tmp; cvta.to.shared.u64 tmp, %1; cvt.u32.u64 %0, tmp; }"
        : "=r"(addr) : "l"(smem_ptr));
    return addr;
}
// fp16 pack: lo = a, hi = b
__device__ __forceinline__ uint32_t pack_hf2(float a, float b) {
    uint32_t r;
    asm("cvt.rn.f16x2.f32 %0, %1, %2;" : "=r"(r) : "f"(b), "f"(a));
    return r;
}
__device__ __forceinline__ float hf_lo_f32(uint32_t h) {
    __half2 v = *reinterpret_cast<__half2*>(&h);
    return __low2float(v);
}
__device__ __forceinline__ float hf_hi_f32(uint32_t h) {
    __half2 v = *reinterpret_cast<__half2*>(&h);
    return __high2float(v);
}

__device__ __forceinline__ void ldmx4(uint32_t r[4], uint32_t addr) {
    asm volatile("ldmatrix.sync.aligned.m8n8.x4.shared.b16 {%0,%1,%2,%3}, [%4];"
        : "=r"(r[0]), "=r"(r[1]), "=r"(r[2]), "=r"(r[3]) : "r"(addr));
}
__device__ __forceinline__ void ldmx4t(uint32_t r[4], uint32_t addr) {
    asm volatile("ldmatrix.sync.aligned.m8n8.x4.trans.shared.b16 {%0,%1,%2,%3}, [%4];"
        : "=r"(r[0]), "=r"(r[1]), "=r"(r[2]), "=r"(r[3]) : "r"(addr));
}
__device__ __forceinline__ void mma16816h(float d[4], const uint32_t a[4],
                                          const uint32_t b[2]) {
    asm volatile(
        "mma.sync.aligned.m16n8k16.row.col.f32.f16.f16.f32 "
        "{%0,%1,%2,%3}, {%4,%5,%6,%7}, {%8,%9}, {%0,%1,%2,%3};"
        : "+f"(d[0]), "+f"(d[1]), "+f"(d[2]), "+f"(d[3])
        : "r"(a[0]), "r"(a[1]), "r"(a[2]), "r"(a[3]), "r"(b[0]), "r"(b[1]));
}
__device__ __forceinline__ void cp16(uint32_t dst, const void* src) {
    asm volatile("cp.async.cg.shared.global [%0], [%1], 16;"
                 :: "r"(dst), "l"(src));
}
__device__ __forceinline__ void cp_commit() {
    asm volatile("cp.async.commit_group;" ::: "memory");
}
template <int N>
__device__ __forceinline__ void cp_wait() {
    asm volatile("cp.async.wait_group %0;" :: "n"(N) : "memory");
}

// ===========================================================================
// Pre-convert fp32 -> fp16 hi/lo (and hi-only variant)
// ===========================================================================
__global__ void cvt_f16_hilo_kernel(const float4* __restrict__ src,
                                    uint2* __restrict__ hi, uint2* __restrict__ lo,
                                    int n4) {
    int i = blockIdx.x * blockDim.x + threadIdx.x;
    if (i >= n4) return;
    float4 v = src[i];
    uint32_t h0 = pack_hf2(v.x, v.y), h1 = pack_hf2(v.z, v.w);
    uint32_t l0 = pack_hf2(v.x - hf_lo_f32(h0), v.y - hf_hi_f32(h0));
    uint32_t l1 = pack_hf2(v.z - hf_lo_f32(h1), v.w - hf_hi_f32(h1));
    hi[i] = make_uint2(h0, h1);
    lo[i] = make_uint2(l0, l1);
}
__global__ void cvt_f16_hi_kernel(const float4* __restrict__ src,
                                  uint2* __restrict__ hi, int n4) {
    int i = blockIdx.x * blockDim.x + threadIdx.x;
    if (i >= n4) return;
    float4 v = src[i];
    hi[i] = make_uint2(pack_hf2(v.x, v.y), pack_hf2(v.z, v.w));
}

// ===========================================================================
// 4-stage cp.async fp16 GEMM (unchanged from R7)
// ===========================================================================
#define SAe 40
#define SBe 264
#define ST_AHI 0
#define ST_ALO 10240
#define ST_BHI 20480
#define ST_BLO 37376
#define ST_SZ  54272
#define NSTG 4
#define GEMM_SMEM (NSTG * ST_SZ)

template<bool SPLIT_B>
__global__ __launch_bounds__(256, 1)
void gemm_pipe_kernel(const void* __restrict__ Ah, const void* __restrict__ Al,
                      const void* __restrict__ Bh0, const void* __restrict__ Bl0,
                      float* __restrict__ C0,
                      const void* __restrict__ Bh1, const void* __restrict__ Bl1,
                      float* __restrict__ C1,
                      int N, int K) {
    extern __shared__ char sm[];
    const uint32_t smb = smem_to_u32(sm);
    const int tid = threadIdx.x, lane = tid & 31, wid = tid >> 5;
    const int wm = wid >> 2, wn = wid & 3;
    const int m0 = blockIdx.y * 128, n0 = blockIdx.x * 256;

    const char* Bh = (const char*)(blockIdx.z ? Bh1 : Bh0);
    const char* Bl = (const char*)(blockIdx.z ? Bl1 : Bl0);
    float* C = blockIdx.z ? C1 : C0;
    const char* Ahc = (const char*)Ah;
    const char* Alc = (const char*)Al;

    float acc[4][8][4];
    #pragma unroll
    for (int i = 0; i < 4; i++)
        #pragma unroll
        for (int j = 0; j < 8; j++)
            #pragma unroll
            for (int t = 0; t < 4; t++) acc[i][j][t] = 0.f;

    const uint32_t aRow  = lane & 15;
    const uint32_t aColH = (lane >> 4) * 8;
    const uint32_t bRow  = (lane & 7) + ((lane >> 3) & 1) * 8;
    const uint32_t bCol  = ((lane >> 4) & 1) * 8;
    const int nch = K >> 5;

    auto issue = [&](int s, int k0) {
        uint32_t sb = smb + s * ST_SZ;
        #pragma unroll
        for (int i = 0; i < 2; i++) {
            int idx = tid + (i << 8);
            int row = idx >> 2, seg = idx & 3;
            size_t go = ((size_t)(m0 + row) * K + k0 + seg * 8) * 2;
            uint32_t so = row * 80 + seg * 16;
            cp16(sb + ST_AHI + so, Ahc + go);
            cp16(sb + ST_ALO + so, Alc + go);
        }
        #pragma unroll
        for (int i = 0; i < 4; i++) {
            int idx = tid + (i << 8);
            int row = idx >> 5, seg = idx & 31;
            size_t go = ((size_t)(k0 + row) * N + n0 + seg * 8) * 2;
            uint32_t so = row * 528 + seg * 16;
            cp16(sb + ST_BHI + so, Bh + go);
            if (SPLIT_B) cp16(sb + ST_BLO + so, Bl + go);
        }
        cp_commit();
    };

    issue(0, 0);
    issue(1, 32);
    for (int c = 0; c < nch; c++) {
        if (c + 2 < nch) issue((c + 2) & (NSTG - 1), (c + 2) << 5);
        else             cp_commit();
        cp_wait<2>();
        __syncthreads();

        const uint32_t sb = smb + (c & (NSTG - 1)) * ST_SZ;
        #pragma unroll
        for (int ks = 0; ks < 2; ks++) {
            uint32_t aH[4][4], aL[4][4];
            #pragma unroll
            for (int mf = 0; mf < 4; mf++) {
                uint32_t ao = ((wm * 64 + mf * 16 + aRow) * SAe + ks * 16 + aColH) * 2;
                ldmx4(aH[mf], sb + ST_AHI + ao);
                ldmx4(aL[mf], sb + ST_ALO + ao);
            }
            uint32_t bH[4][4], bL[4][4];
            #pragma unroll
            for (int ng = 0; ng < 4; ng++) {
                uint32_t bo = ((ks * 16 + bRow) * SBe + wn * 64 + ng * 16 + bCol) * 2;
                ldmx4t(bH[ng], sb + ST_BHI + bo);
                if (SPLIT_B) ldmx4t(bL[ng], sb + ST_BLO + bo);
            }
            #pragma unroll
            for (int mf = 0; mf < 4; mf++)
                #pragma unroll
                for (int ng = 0; ng < 4; ng++) {
                    mma16816h(acc[mf][ng*2+0], aH[mf], bH[ng]);
                    mma16816h(acc[mf][ng*2+0], aL[mf], bH[ng]);
                    if (SPLIT_B) mma16816h(acc[mf][ng*2+0], aH[mf], bL[ng]);
                    mma16816h(acc[mf][ng*2+1], aH[mf], bH[ng] + 2);
                    mma16816h(acc[mf][ng*2+1], aL[mf], bH[ng] + 2);
                    if (SPLIT_B) mma16816h(acc[mf][ng*2+1], aH[mf], bL[ng] + 2);
                }
        }
    }

    #pragma unroll
    for (int mf = 0; mf < 4; mf++) {
        int row = m0 + wm * 64 + mf * 16 + (lane >> 2);
        #pragma unroll
        for (int nf = 0; nf < 8; nf++) {
            int col = n0 + wn * 64 + nf * 8 + (lane & 3) * 2;
            *reinterpret_cast<float2*>(C + (size_t)row * N + col) =
                make_float2(acc[mf][nf][0], acc[mf][nf][1]);
            *reinterpret_cast<float2*>(C + (size_t)(row + 8) * N + col) =
                make_float2(acc[mf][nf][2], acc[mf][nf][3]);
        }
    }
}

// ---------------------------------------------------------------------------
// RoPE (unchanged)
// ---------------------------------------------------------------------------
__global__ void rope_kernel(float* __restrict__ Q, float* __restrict__ K,
                            const int* __restrict__ pos_ids) {
    int idx = blockIdx.x * blockDim.x + threadIdx.x;
    if (idx >= B_ * S_ * HKV_ * 32) return;
    int d   = idx & 31;
    int h   = (idx >> 5) & (HKV_ - 1);
    int row = idx >> 8;
    float p    = (float)pos_ids[row];
    float invf = powf(10000.0f, -(float)d * (1.0f / 32.0f));
    float a = p * invf;
    float sn, cs;
    sincosf(a, &sn, &cs);
    size_t base = (size_t)row * NQK_ + h * HD_;
    float q0 = Q[base + d], q1 = Q[base + d + 32];
    Q[base + d]      = q0 * cs - q1 * sn;
    Q[base + d + 32] = q1 * cs + q0 * sn;
    float k0 = K[base + d], k1 = K[base + d + 32];
    K[base + d]      = k0 * cs - k1 * sn;
    K[base + d + 32] = k1 * cs + k0 * sn;
}

// ===========================================================================
// Flash attention, fp16 2-term: QK = (Qh+Ql)·Kh, PV = (Ph+Pl)·Vh.
// smem 97.5 KB -> 2 CTAs/SM.
// ===========================================================================
#define SK   72
#define SV   264
#define PITX 66
#define QHI_O 0
#define QLO_O 9216
#define KHI_O 18432
#define VHI_O 27648
#define PS_O  61440
#define PHI_O 78336
#define PLO_O 87552
#define MR_O  96768
#define LR_O  97024
#define SF_O  97280
#define ATTN_SMEM 97536

__global__ __launch_bounds__(256, 2)
void attn_mma_kernel(const float* __restrict__ Q, const float* __restrict__ K,
                     const float* __restrict__ V, float* __restrict__ Out) {
    extern __shared__ char sm[];
    const uint32_t smb = smem_to_u32(sm);
    float* Ps   = reinterpret_cast<float*>(sm + PS_O);
    float* mrow = reinterpret_cast<float*>(sm + MR_O);
    float* lrow = reinterpret_cast<float*>(sm + LR_O);
    float* sfac = reinterpret_cast<float*>(sm + SF_O);

    const int tid = threadIdx.x, lane = tid & 31, wid = tid >> 5;
    const int wm = wid >> 1, wn = wid & 1;
    const int b  = blockIdx.z;
    const int h  = blockIdx.y;
    const int qb = blockIdx.x;
    const int q0 = qb * 64;

    // ---- load Q tile (scaled 0.125) -> fp16 hi/lo ----
    #pragma unroll
    for (int i = 0; i < 4; i++) {
        int idx = tid + (i << 8);
        int r = idx >> 4, c4 = idx & 15;
        float4 v = *reinterpret_cast<const float4*>(
            Q + ((size_t)(b * S_ + q0 + r)) * NQK_ + h * HD_ + (c4 << 2));
        v.x *= 0.125f; v.y *= 0.125f; v.z *= 0.125f; v.w *= 0.125f;
        uint32_t h0 = pack_hf2(v.x, v.y), h1 = pack_hf2(v.z, v.w);
        uint32_t l0 = pack_hf2(v.x - hf_lo_f32(h0), v.y - hf_hi_f32(h0));
        uint32_t l1 = pack_hf2(v.z - hf_lo_f32(h1), v.w - hf_hi_f32(h1));
        uint32_t off = (r * SK + (c4 << 2)) * 2;
        *reinterpret_cast<uint2*>(sm + QHI_O + off) = make_uint2(h0, h1);
        *reinterpret_cast<uint2*>(sm + QLO_O + off) = make_uint2(l0, l1);
    }
    if (tid < 64) { mrow[tid] = -INFINITY; lrow[tid] = 0.f; }

    float acc[16][4];
    #pragma unroll
    for (int i = 0; i < 16; i++)
        #pragma unroll
        for (int t = 0; t < 4; t++) acc[i][t] = 0.f;

    const float4* V4 = reinterpret_cast<const float4*>(V);

    const uint32_t aRow  = lane & 15;
    const uint32_t aColH = (lane >> 4) * 8;
    const uint32_t kbRow = (lane & 7) + ((lane >> 4) & 1) * 8;
    const uint32_t kbCol = ((lane >> 3) & 1) * 8;
    const uint32_t vbRow = (lane & 7) + ((lane >> 3) & 1) * 8;
    const uint32_t vbCol = ((lane >> 4) & 1) * 8;

    for (int kt = 0; kt <= qb; kt++) {
        const int k0 = kt * 64;
        __syncthreads();

        // ---- load K tile -> fp16 hi only ----
        #pragma unroll
        for (int i = 0; i < 4; i++) {
            int idx = tid + (i << 8);
            int kk = idx >> 4, c4 = idx & 15;
            float4 v = *reinterpret_cast<const float4*>(
                K + ((size_t)(b * S_ + k0 + kk)) * NQK_ + h * HD_ + (c4 << 2));
            uint32_t off = (kk * SK + (c4 << 2)) * 2;
            *reinterpret_cast<uint2*>(sm + KHI_O + off) =
                make_uint2(pack_hf2(v.x, v.y), pack_hf2(v.z, v.w));
        }
        // ---- load V tile -> fp16 hi only [key][256 cols] ----
        #pragma unroll
        for (int i = 0; i < 16; i++) {
            int idx = tid + (i << 8);
            int kk = idx >> 6;
            int c4 = idx & 63;
            int g  = c4 >> 4, d4 = c4 & 15;
            float4 v = V4[((size_t)(b * S_ + k0 + kk)) * (HID_ / 4)
                          + g * (NQK_ / 4) + h * (HD_ / 4) + d4];
            uint32_t off = (kk * SV + (c4 << 2)) * 2;
            *reinterpret_cast<uint2*>(sm + VHI_O + off) =
                make_uint2(pack_hf2(v.x, v.y), pack_hf2(v.z, v.w));
        }
        __syncthreads();

        // ---- QK^T: S[64x64], warp tile 16x32, 2-term ----
        {
            float sfr[4][4];
            #pragma unroll
            for (int i = 0; i < 4; i++)
                #pragma unroll
                for (int t = 0; t < 4; t++) sfr[i][t] = 0.f;

            #pragma unroll
            for (int ks = 0; ks < 4; ks++) {
                uint32_t aH[4], aL[4];
                uint32_t ao = ((wm * 16 + aRow) * SK + ks * 16 + aColH) * 2;
                ldmx4(aH, smb + QHI_O + ao);
                ldmx4(aL, smb + QLO_O + ao);
                #pragma unroll
                for (int np = 0; np < 2; np++) {
                    uint32_t bH[4];
                    uint32_t nb = wn * 32 + np * 16;
                    uint32_t bo = ((nb + kbRow) * SK + ks * 16 + kbCol) * 2;
                    ldmx4(bH, smb + KHI_O + bo);
                    mma16816h(sfr[np*2+0], aH, bH);
                    mma16816h(sfr[np*2+0], aL, bH);
                    mma16816h(sfr[np*2+1], aH, bH + 2);
                    mma16816h(sfr[np*2+1], aL, bH + 2);
                }
            }
            int r0 = wm * 16 + (lane >> 2);
            #pragma unroll
            for (int nf = 0; nf < 4; nf++) {
                int cb = wn * 32 + nf * 8 + (lane & 3) * 2;
                *reinterpret_cast<float2*>(&Ps[r0 * PITX + cb]) =
                    make_float2(sfr[nf][0], sfr[nf][1]);
                *reinterpret_cast<float2*>(&Ps[(r0 + 8) * PITX + cb]) =
                    make_float2(sfr[nf][2], sfr[nf][3]);
            }
        }
        __syncthreads();

        // ---- online softmax (one thread per row) ----
        if (tid < 64) {
            const int row = tid;
            const int kmax = (kt == qb) ? row : 63;
            float m_old = mrow[row];
            float mx = m_old;
            for (int k = 0; k <= kmax; k++) mx = fmaxf(mx, Ps[row * PITX + k]);
            float sum = 0.f;
            for (int k = 0; k < 64; k++) {
                float p = (k <= kmax) ? expf(Ps[row * PITX + k] - mx) : 0.f;
                Ps[row * PITX + k] = p;
                sum += p;
            }
            float f = expf(m_old - mx);
            sfac[row] = f;
            lrow[row] = lrow[row] * f + sum;
            mrow[row] = mx;
        }
        __syncthreads();

        // ---- convert P -> fp16 hi/lo (parallel) ----
        {
            int row = tid >> 2;
            int cb  = (tid & 3) * 16;
            #pragma unroll
            for (int j = 0; j < 8; j++) {
                float p0 = Ps[row * PITX + cb + 2*j];
                float p1 = Ps[row * PITX + cb + 2*j + 1];
                uint32_t ph = pack_hf2(p0, p1);
                uint32_t pl = pack_hf2(p0 - hf_lo_f32(ph), p1 - hf_hi_f32(ph));
                uint32_t off = (row * SK + cb + 2*j) * 2;
                *reinterpret_cast<uint32_t*>(sm + PHI_O + off) = ph;
                *reinterpret_cast<uint32_t*>(sm + PLO_O + off) = pl;
            }
        }
        __syncthreads();

        // ---- PV: acc(16x128 per warp) = rescale + (Ph+Pl) @ Vh ----
        {
            float f0 = sfac[wm * 16 + (lane >> 2)];
            float f1 = sfac[wm * 16 + (lane >> 2) + 8];
            #pragma unroll
            for (int i = 0; i < 16; i++) {
                acc[i][0] *= f0; acc[i][1] *= f0;
                acc[i][2] *= f1; acc[i][3] *= f1;
            }
            #pragma unroll
            for (int ks = 0; ks < 4; ks++) {
                uint32_t pH[4], pL[4];
                uint32_t ao = ((wm * 16 + aRow) * SK + ks * 16 + aColH) * 2;
                ldmx4(pH, smb + PHI_O + ao);
                ldmx4(pL, smb + PLO_O + ao);
                #pragma unroll
                for (int np = 0; np < 8; np++) {
                    uint32_t vH[4];
                    uint32_t nb = wn * 128 + np * 16;
                    uint32_t bo = ((ks * 16 + vbRow) * SV + nb + vbCol) * 2;
                    ldmx4t(vH, smb + VHI_O + bo);
                    mma16816h(acc[np*2+0], pH, vH);
                    mma16816h(acc[np*2+0], pL, vH);
                    mma16816h(acc[np*2+1], pH, vH + 2);
                    mma16816h(acc[np*2+1], pL, vH + 2);
                }
            }
        }
    }
    __syncthreads();

    // ---- normalize + store ----
    {
        int r0 = wm * 16 + (lane >> 2);
        float invl0 = 1.f / lrow[r0];
        float invl1 = 1.f / lrow[r0 + 8];
        #pragma unroll
        for (int nf = 0; nf < 16; nf++) {
            int cl = wn * 128 + nf * 8 + (lane & 3) * 2;
            int g  = cl >> 6, d = cl & 63;
            size_t ob0 = ((size_t)(b * S_ + q0 + r0)) * HID_ + (g * HKV_ + h) * HD_ + d;
            size_t ob1 = ((size_t)(b * S_ + q0 + r0 + 8)) * HID_ + (g * HKV_ + h) * HD_ + d;
            *reinterpret_cast<float2*>(&Out[ob0]) =
                make_float2(acc[nf][0] * invl0, acc[nf][1] * invl0);
            *reinterpret_cast<float2*>(&Out[ob1]) =
                make_float2(acc[nf][2] * invl1, acc[nf][3] * invl1);
        }
    }
}

// ---------------------------------------------------------------------------
extern "C" void kernel_launch(void* const* d_in, const int* in_sizes, int n_in,
                              void* d_out, int out_size) {
    const float* X   = (const float*)d_in[0];
    const int*   pid = (const int*)  d_in[1];
    const float* Wq  = (const float*)d_in[2];
    const float* Wk  = (const float*)d_in[3];
    const float* Wv  = (const float*)d_in[4];
    float* Out = (float*)d_out;

    float *dQ, *dK, *dV;
    cudaGetSymbolAddress((void**)&dQ, g_Q);
    cudaGetSymbolAddress((void**)&dK, g_K);
    cudaGetSymbolAddress((void**)&dV, g_V);
    uint2 *xh, *xl, *wqh, *wql, *wkh, *wkl, *wvh;
    cudaGetSymbolAddress((void**)&xh,  g_Xh);  cudaGetSymbolAddress((void**)&xl,  g_Xl);
    cudaGetSymbolAddress((void**)&wqh, g_Wqh); cudaGetSymbolAddress((void**)&wql, g_Wql);
    cudaGetSymbolAddress((void**)&wkh, g_Wkh); cudaGetSymbolAddress((void**)&wkl, g_Wkl);
    cudaGetSymbolAddress((void**)&wvh, g_Wvh);

    // Pre-convert operands to fp16 hi/lo (Wv: hi only)
    {
        int nX = M_ * HID_ / 4, nWqk = HID_ * NQK_ / 4, nWv = HID_ * HID_ / 4;
        cvt_f16_hilo_kernel<<<(nX + 255) / 256, 256>>>((const float4*)X, xh, xl, nX);
        cvt_f16_hilo_kernel<<<(nWqk + 255) / 256, 256>>>((const float4*)Wq, wqh, wql, nWqk);
        cvt_f16_hilo_kernel<<<(nWqk + 255) / 256, 256>>>((const float4*)Wk, wkh, wkl, nWqk);
        cvt_f16_hi_kernel<<<(nWv + 255) / 256, 256>>>((const float4*)Wv, wvh, nWv);
    }

    // Projections: fused Q/K (3-term) + V (2-term)
    {
        cudaFuncSetAttribute(gemm_pipe_kernel<true>,
                             cudaFuncAttributeMaxDynamicSharedMemorySize, GEMM_SMEM);
        cudaFuncSetAttribute(gemm_pipe_kernel<false>,
                             cudaFuncAttributeMaxDynamicSharedMemorySize, GEMM_SMEM);
        dim3 blk(256);
        dim3 grdQK(NQK_ / 256, M_ / 128, 2);
        gemm_pipe_kernel<true><<<grdQK, blk, GEMM_SMEM>>>(xh, xl, wqh, wql, dQ,
                                                          wkh, wkl, dK, NQK_, HID_);
        dim3 grdV(HID_ / 256, M_ / 128, 1);
        gemm_pipe_kernel<false><<<grdV, blk, GEMM_SMEM>>>(xh, xl, wvh, wvh, dV,
                                                          wvh, wvh, dV, HID_, HID_);
    }
    {
        int total = B_ * S_ * HKV_ * 32;
        rope_kernel<<<(total + 255) / 256, 256>>>(dQ, dK, pid);
    }
    {
        cudaFuncSetAttribute(attn_mma_kernel,
                             cudaFuncAttributeMaxDynamicSharedMemorySize, ATTN_SMEM);
        dim3 grd(S_ / 64, HKV_, B_);
        attn_mma_kernel<<<grd, 256, ATTN_SMEM>>>(dQ, dK, dV, Out);
    }
}

// round 9
// speedup vs baseline: 4.4530x; 1.1112x over previous
#include <cuda_runtime.h>
#include <cuda_fp16.h>
#include <math.h>
#include <stdint.h>

#define B_   2
#define S_   2048
#define HID_ 2048
#define NH_  32
#define G_   4
#define HD_  64
#define HKV_ 8
#define NQK_ 512   // HKV_*HD_
#define M_   (B_ * S_)   // 4096

// Scratch (device globals: no allocation allowed)
__device__ float g_Q[(size_t)M_*NQK_];   // fp32 Q (pre-rope)
__device__ float g_K[(size_t)M_*NQK_];   // fp32 K (pre-rope)
// fp16 post-rope / projected tensors (uint4-typed for 16B alignment)
__device__ uint4 g_Qh[(size_t)M_*NQK_/8], g_Ql[(size_t)M_*NQK_/8];
__device__ uint4 g_Kh[(size_t)M_*NQK_/8];
__device__ uint4 g_Vh[(size_t)M_*HID_/8];
// fp16 pre-converted GEMM operands
__device__ uint2 g_Xh[(size_t)M_*HID_/4],  g_Xl[(size_t)M_*HID_/4];
__device__ uint2 g_Wqh[(size_t)HID_*NQK_/4];
__device__ uint2 g_Wkh[(size_t)HID_*NQK_/4];
__device__ uint2 g_Wvh[(size_t)HID_*HID_/4];

// ===========================================================================
// helpers
// ===========================================================================
__device__ __forceinline__ uint32_t smem_to_u32(const void* smem_ptr) {
    uint32_t addr;
    asm("{ .reg .u64 tmp; cvta.to.shared.u64 tmp, %1; cvt.u32.u64 %0, tmp; }"
        : "=r"(addr) : "l"(smem_ptr));
    return addr;
}
__device__ __forceinline__ uint32_t pack_hf2(float a, float b) {
    uint32_t r;
    asm("cvt.rn.f16x2.f32 %0, %1, %2;" : "=r"(r) : "f"(b), "f"(a));
    return r;
}
__device__ __forceinline__ float hf_lo_f32(uint32_t h) {
    __half2 v = *reinterpret_cast<__half2*>(&h);
    return __low2float(v);
}
__device__ __forceinline__ float hf_hi_f32(uint32_t h) {
    __half2 v = *reinterpret_cast<__half2*>(&h);
    return __high2float(v);
}

__device__ __forceinline__ void ldmx4(uint32_t r[4], uint32_t addr) {
    asm volatile("ldmatrix.sync.aligned.m8n8.x4.shared.b16 {%0,%1,%2,%3}, [%4];"
        : "=r"(r[0]), "=r"(r[1]), "=r"(r[2]), "=r"(r[3]) : "r"(addr));
}
__device__ __forceinline__ void ldmx4t(uint32_t r[4], uint32_t addr) {
    asm volatile("ldmatrix.sync.aligned.m8n8.x4.trans.shared.b16 {%0,%1,%2,%3}, [%4];"
        : "=r"(r[0]), "=r"(r[1]), "=r"(r[2]), "=r"(r[3]) : "r"(addr));
}
__device__ __forceinline__ void mma16816h(float d[4], const uint32_t a[4],
                                          const uint32_t b[2]) {
    asm volatile(
        "mma.sync.aligned.m16n8k16.row.col.f32.f16.f16.f32 "
        "{%0,%1,%2,%3}, {%4,%5,%6,%7}, {%8,%9}, {%0,%1,%2,%3};"
        : "+f"(d[0]), "+f"(d[1]), "+f"(d[2]), "+f"(d[3])
        : "r"(a[0]), "r"(a[1]), "r"(a[2]), "r"(a[3]), "r"(b[0]), "r"(b[1]));
}
__device__ __forceinline__ void cp16(uint32_t dst, const void* src) {
    asm volatile("cp.async.cg.shared.global [%0], [%1], 16;"
                 :: "r"(dst), "l"(src));
}
__device__ __forceinline__ void cp_commit() {
    asm volatile("cp.async.commit_group;" ::: "memory");
}
template <int N>
__device__ __forceinline__ void cp_wait() {
    asm volatile("cp.async.wait_group %0;" :: "n"(N) : "memory");
}

// ===========================================================================
// Pre-convert fp32 -> fp16 hi/lo (and hi-only variant)
// ===========================================================================
__global__ void cvt_f16_hilo_kernel(const float4* __restrict__ src,
                                    uint2* __restrict__ hi, uint2* __restrict__ lo,
                                    int n4) {
    int i = blockIdx.x * blockDim.x + threadIdx.x;
    if (i >= n4) return;
    float4 v = src[i];
    uint32_t h0 = pack_hf2(v.x, v.y), h1 = pack_hf2(v.z, v.w);
    uint32_t l0 = pack_hf2(v.x - hf_lo_f32(h0), v.y - hf_hi_f32(h0));
    uint32_t l1 = pack_hf2(v.z - hf_lo_f32(h1), v.w - hf_hi_f32(h1));
    hi[i] = make_uint2(h0, h1);
    lo[i] = make_uint2(l0, l1);
}
__global__ void cvt_f16_hi_kernel(const float4* __restrict__ src,
                                  uint2* __restrict__ hi, int n4) {
    int i = blockIdx.x * blockDim.x + threadIdx.x;
    if (i >= n4) return;
    float4 v = src[i];
    hi[i] = make_uint2(pack_hf2(v.x, v.y), pack_hf2(v.z, v.w));
}

// ===========================================================================
// 4-stage cp.async fp16 GEMM: C[M,N] = A[M,K] @ B[K,N]
// CTA 128x256, warp 64x64 (2m x 4n), K-chunk 32.
// SPLIT_B: add Ah*Bl term. OUT_HALF: write fp16 C.
// ===========================================================================
#define SAe 40
#define SBe 264
#define ST_AHI 0
#define ST_ALO 10240
#define ST_BHI 20480
#define ST_BLO 37376
#define ST_SZ  54272
#define NSTG 4
#define GEMM_SMEM (NSTG * ST_SZ)

template<bool SPLIT_B, bool OUT_HALF>
__global__ __launch_bounds__(256, 1)
void gemm_pipe_kernel(const void* __restrict__ Ah, const void* __restrict__ Al,
                      const void* __restrict__ Bh0, const void* __restrict__ Bl0,
                      void* __restrict__ C0,
                      const void* __restrict__ Bh1, const void* __restrict__ Bl1,
                      void* __restrict__ C1,
                      int N, int K) {
    extern __shared__ char sm[];
    const uint32_t smb = smem_to_u32(sm);
    const int tid = threadIdx.x, lane = tid & 31, wid = tid >> 5;
    const int wm = wid >> 2, wn = wid & 3;
    const int m0 = blockIdx.y * 128, n0 = blockIdx.x * 256;

    const char* Bh = (const char*)(blockIdx.z ? Bh1 : Bh0);
    const char* Bl = (const char*)(blockIdx.z ? Bl1 : Bl0);
    void* C = blockIdx.z ? C1 : C0;
    const char* Ahc = (const char*)Ah;
    const char* Alc = (const char*)Al;

    float acc[4][8][4];
    #pragma unroll
    for (int i = 0; i < 4; i++)
        #pragma unroll
        for (int j = 0; j < 8; j++)
            #pragma unroll
            for (int t = 0; t < 4; t++) acc[i][j][t] = 0.f;

    const uint32_t aRow  = lane & 15;
    const uint32_t aColH = (lane >> 4) * 8;
    const uint32_t bRow  = (lane & 7) + ((lane >> 3) & 1) * 8;
    const uint32_t bCol  = ((lane >> 4) & 1) * 8;
    const int nch = K >> 5;

    auto issue = [&](int s, int k0) {
        uint32_t sb = smb + s * ST_SZ;
        #pragma unroll
        for (int i = 0; i < 2; i++) {
            int idx = tid + (i << 8);
            int row = idx >> 2, seg = idx & 3;
            size_t go = ((size_t)(m0 + row) * K + k0 + seg * 8) * 2;
            uint32_t so = row * 80 + seg * 16;
            cp16(sb + ST_AHI + so, Ahc + go);
            cp16(sb + ST_ALO + so, Alc + go);
        }
        #pragma unroll
        for (int i = 0; i < 4; i++) {
            int idx = tid + (i << 8);
            int row = idx >> 5, seg = idx & 31;
            size_t go = ((size_t)(k0 + row) * N + n0 + seg * 8) * 2;
            uint32_t so = row * 528 + seg * 16;
            cp16(sb + ST_BHI + so, Bh + go);
            if (SPLIT_B) cp16(sb + ST_BLO + so, Bl + go);
        }
        cp_commit();
    };

    issue(0, 0);
    issue(1, 32);
    for (int c = 0; c < nch; c++) {
        if (c + 2 < nch) issue((c + 2) & (NSTG - 1), (c + 2) << 5);
        else             cp_commit();
        cp_wait<2>();
        __syncthreads();

        const uint32_t sb = smb + (c & (NSTG - 1)) * ST_SZ;
        #pragma unroll
        for (int ks = 0; ks < 2; ks++) {
            uint32_t aH[4][4], aL[4][4];
            #pragma unroll
            for (int mf = 0; mf < 4; mf++) {
                uint32_t ao = ((wm * 64 + mf * 16 + aRow) * SAe + ks * 16 + aColH) * 2;
                ldmx4(aH[mf], sb + ST_AHI + ao);
                ldmx4(aL[mf], sb + ST_ALO + ao);
            }
            uint32_t bH[4][4], bL[4][4];
            #pragma unroll
            for (int ng = 0; ng < 4; ng++) {
                uint32_t bo = ((ks * 16 + bRow) * SBe + wn * 64 + ng * 16 + bCol) * 2;
                ldmx4t(bH[ng], sb + ST_BHI + bo);
                if (SPLIT_B) ldmx4t(bL[ng], sb + ST_BLO + bo);
            }
            #pragma unroll
            for (int mf = 0; mf < 4; mf++)
                #pragma unroll
                for (int ng = 0; ng < 4; ng++) {
                    mma16816h(acc[mf][ng*2+0], aH[mf], bH[ng]);
                    mma16816h(acc[mf][ng*2+0], aL[mf], bH[ng]);
                    if (SPLIT_B) mma16816h(acc[mf][ng*2+0], aH[mf], bL[ng]);
                    mma16816h(acc[mf][ng*2+1], aH[mf], bH[ng] + 2);
                    mma16816h(acc[mf][ng*2+1], aL[mf], bH[ng] + 2);
                    if (SPLIT_B) mma16816h(acc[mf][ng*2+1], aH[mf], bL[ng] + 2);
                }
        }
    }

    #pragma unroll
    for (int mf = 0; mf < 4; mf++) {
        int row = m0 + wm * 64 + mf * 16 + (lane >> 2);
        #pragma unroll
        for (int nf = 0; nf < 8; nf++) {
            int col = n0 + wn * 64 + nf * 8 + (lane & 3) * 2;
            if (OUT_HALF) {
                __half* Ch = reinterpret_cast<__half*>(C);
                *reinterpret_cast<uint32_t*>(Ch + (size_t)row * N + col) =
                    pack_hf2(acc[mf][nf][0], acc[mf][nf][1]);
                *reinterpret_cast<uint32_t*>(Ch + (size_t)(row + 8) * N + col) =
                    pack_hf2(acc[mf][nf][2], acc[mf][nf][3]);
            } else {
                float* Cf = reinterpret_cast<float*>(C);
                *reinterpret_cast<float2*>(Cf + (size_t)row * N + col) =
                    make_float2(acc[mf][nf][0], acc[mf][nf][1]);
                *reinterpret_cast<float2*>(Cf + (size_t)(row + 8) * N + col) =
                    make_float2(acc[mf][nf][2], acc[mf][nf][3]);
            }
        }
    }
}

// ---------------------------------------------------------------------------
// RoPE fused with fp16 conversion: reads fp32 Q/K, writes Qh/Ql (x0.125), Kh.
// ---------------------------------------------------------------------------
__global__ void rope_cvt_kernel(const float* __restrict__ Q, const float* __restrict__ K,
                                const int* __restrict__ pos_ids,
                                __half* __restrict__ Qh, __half* __restrict__ Ql,
                                __half* __restrict__ Kh) {
    int idx = blockIdx.x * blockDim.x + threadIdx.x;
    if (idx >= B_ * S_ * HKV_ * 32) return;
    int d   = idx & 31;
    int h   = (idx >> 5) & (HKV_ - 1);
    int row = idx >> 8;
    float p    = (float)pos_ids[row];
    float invf = powf(10000.0f, -(float)d * (1.0f / 32.0f));
    float a = p * invf;
    float sn, cs;
    sincosf(a, &sn, &cs);
    size_t base = (size_t)row * NQK_ + h * HD_;
    float q0 = Q[base + d], q1 = Q[base + d + 32];
    float qr0 = (q0 * cs - q1 * sn) * 0.125f;
    float qr1 = (q1 * cs + q0 * sn) * 0.125f;
    __half qh0 = __float2half_rn(qr0), qh1 = __float2half_rn(qr1);
    Qh[base + d]      = qh0;
    Qh[base + d + 32] = qh1;
    Ql[base + d]      = __float2half_rn(qr0 - __half2float(qh0));
    Ql[base + d + 32] = __float2half_rn(qr1 - __half2float(qh1));
    float k0 = K[base + d], k1 = K[base + d + 32];
    Kh[base + d]      = __float2half_rn(k0 * cs - k1 * sn);
    Kh[base + d + 32] = __float2half_rn(k1 * cs + k0 * sn);
}

// ===========================================================================
// Flash attention, fp16 2-term, all inputs pre-converted fp16.
// smem 97.5 KB -> 2 CTAs/SM.
// ===========================================================================
#define SK   72
#define SV   264
#define PITX 66
#define QHI_O 0
#define QLO_O 9216
#define KHI_O 18432
#define VHI_O 27648
#define PS_O  61440
#define PHI_O 78336
#define PLO_O 87552
#define MR_O  96768
#define LR_O  97024
#define SF_O  97280
#define ATTN_SMEM 97536

__global__ __launch_bounds__(256, 2)
void attn_mma_kernel(const uint4* __restrict__ Qh, const uint4* __restrict__ Ql,
                     const uint4* __restrict__ Kh, const uint4* __restrict__ Vh,
                     float* __restrict__ Out) {
    extern __shared__ char sm[];
    const uint32_t smb = smem_to_u32(sm);
    float* Ps   = reinterpret_cast<float*>(sm + PS_O);
    float* mrow = reinterpret_cast<float*>(sm + MR_O);
    float* lrow = reinterpret_cast<float*>(sm + LR_O);
    float* sfac = reinterpret_cast<float*>(sm + SF_O);

    const int tid = threadIdx.x, lane = tid & 31, wid = tid >> 5;
    const int wm = wid >> 1, wn = wid & 1;
    const int b  = blockIdx.z;
    const int h  = blockIdx.y;
    const int qb = blockIdx.x;
    const int q0 = qb * 64;

    // ---- load Q tile hi/lo (pre-scaled fp16): 512 uint4 each ----
    #pragma unroll
    for (int i = 0; i < 2; i++) {
        int idx = tid + (i << 8);
        int r = idx >> 3, c8 = idx & 7;
        size_t gi = (size_t)(b * S_ + q0 + r) * 64 + h * 8 + c8;
        uint32_t off = (r * SK + c8 * 8) * 2;
        *reinterpret_cast<uint4*>(sm + QHI_O + off) = Qh[gi];
        *reinterpret_cast<uint4*>(sm + QLO_O + off) = Ql[gi];
    }
    if (tid < 64) { mrow[tid] = -INFINITY; lrow[tid] = 0.f; }

    float acc[16][4];
    #pragma unroll
    for (int i = 0; i < 16; i++)
        #pragma unroll
        for (int t = 0; t < 4; t++) acc[i][t] = 0.f;

    const uint32_t aRow  = lane & 15;
    const uint32_t aColH = (lane >> 4) * 8;
    const uint32_t kbRow = (lane & 7) + ((lane >> 4) & 1) * 8;
    const uint32_t kbCol = ((lane >> 3) & 1) * 8;
    const uint32_t vbRow = (lane & 7) + ((lane >> 3) & 1) * 8;
    const uint32_t vbCol = ((lane >> 4) & 1) * 8;

    for (int kt = 0; kt <= qb; kt++) {
        const int k0 = kt * 64;
        __syncthreads();

        // ---- K tile: 512 uint4 ----
        #pragma unroll
        for (int i = 0; i < 2; i++) {
            int idx = tid + (i << 8);
            int kk = idx >> 3, c8 = idx & 7;
            size_t gi = (size_t)(b * S_ + k0 + kk) * 64 + h * 8 + c8;
            uint32_t off = (kk * SK + c8 * 8) * 2;
            *reinterpret_cast<uint4*>(sm + KHI_O + off) = Kh[gi];
        }
        // ---- V tile: 2048 uint4 [key][256 cols] ----
        #pragma unroll
        for (int i = 0; i < 8; i++) {
            int idx = tid + (i << 8);
            int kk = idx >> 5, c8 = idx & 31;
            int g = c8 >> 3, d8 = c8 & 7;
            size_t gi = (size_t)(b * S_ + k0 + kk) * 256 + g * 64 + h * 8 + d8;
            uint32_t off = (kk * SV + c8 * 8) * 2;
            *reinterpret_cast<uint4*>(sm + VHI_O + off) = Vh[gi];
        }
        __syncthreads();

        // ---- QK^T: S[64x64], warp tile 16x32, 2-term ----
        {
            float sfr[4][4];
            #pragma unroll
            for (int i = 0; i < 4; i++)
                #pragma unroll
                for (int t = 0; t < 4; t++) sfr[i][t] = 0.f;

            #pragma unroll
            for (int ks = 0; ks < 4; ks++) {
                uint32_t aH[4], aL[4];
                uint32_t ao = ((wm * 16 + aRow) * SK + ks * 16 + aColH) * 2;
                ldmx4(aH, smb + QHI_O + ao);
                ldmx4(aL, smb + QLO_O + ao);
                #pragma unroll
                for (int np = 0; np < 2; np++) {
                    uint32_t bH[4];
                    uint32_t nb = wn * 32 + np * 16;
                    uint32_t bo = ((nb + kbRow) * SK + ks * 16 + kbCol) * 2;
                    ldmx4(bH, smb + KHI_O + bo);
                    mma16816h(sfr[np*2+0], aH, bH);
                    mma16816h(sfr[np*2+0], aL, bH);
                    mma16816h(sfr[np*2+1], aH, bH + 2);
                    mma16816h(sfr[np*2+1], aL, bH + 2);
                }
            }
            int r0 = wm * 16 + (lane >> 2);
            #pragma unroll
            for (int nf = 0; nf < 4; nf++) {
                int cb = wn * 32 + nf * 8 + (lane & 3) * 2;
                *reinterpret_cast<float2*>(&Ps[r0 * PITX + cb]) =
                    make_float2(sfr[nf][0], sfr[nf][1]);
                *reinterpret_cast<float2*>(&Ps[(r0 + 8) * PITX + cb]) =
                    make_float2(sfr[nf][2], sfr[nf][3]);
            }
        }
        __syncthreads();

        // ---- online softmax (one thread per row) ----
        if (tid < 64) {
            const int row = tid;
            const int kmax = (kt == qb) ? row : 63;
            float m_old = mrow[row];
            float mx = m_old;
            for (int k = 0; k <= kmax; k++) mx = fmaxf(mx, Ps[row * PITX + k]);
            float sum = 0.f;
            for (int k = 0; k < 64; k++) {
                float p = (k <= kmax) ? expf(Ps[row * PITX + k] - mx) : 0.f;
                Ps[row * PITX + k] = p;
                sum += p;
            }
            float f = expf(m_old - mx);
            sfac[row] = f;
            lrow[row] = lrow[row] * f + sum;
            mrow[row] = mx;
        }
        __syncthreads();

        // ---- convert P -> fp16 hi/lo ----
        {
            int row = tid >> 2;
            int cb  = (tid & 3) * 16;
            #pragma unroll
            for (int j = 0; j < 8; j++) {
                float p0 = Ps[row * PITX + cb + 2*j];
                float p1 = Ps[row * PITX + cb + 2*j + 1];
                uint32_t ph = pack_hf2(p0, p1);
                uint32_t pl = pack_hf2(p0 - hf_lo_f32(ph), p1 - hf_hi_f32(ph));
                uint32_t off = (row * SK + cb + 2*j) * 2;
                *reinterpret_cast<uint32_t*>(sm + PHI_O + off) = ph;
                *reinterpret_cast<uint32_t*>(sm + PLO_O + off) = pl;
            }
        }
        __syncthreads();

        // ---- PV: rescale + (Ph+Pl) @ Vh ----
        {
            float f0 = sfac[wm * 16 + (lane >> 2)];
            float f1 = sfac[wm * 16 + (lane >> 2) + 8];
            #pragma unroll
            for (int i = 0; i < 16; i++) {
                acc[i][0] *= f0; acc[i][1] *= f0;
                acc[i][2] *= f1; acc[i][3] *= f1;
            }
            #pragma unroll
            for (int ks = 0; ks < 4; ks++) {
                uint32_t pH[4], pL[4];
                uint32_t ao = ((wm * 16 + aRow) * SK + ks * 16 + aColH) * 2;
                ldmx4(pH, smb + PHI_O + ao);
                ldmx4(pL, smb + PLO_O + ao);
                #pragma unroll
                for (int np = 0; np < 8; np++) {
                    uint32_t vH[4];
                    uint32_t nb = wn * 128 + np * 16;
                    uint32_t bo = ((ks * 16 + vbRow) * SV + nb + vbCol) * 2;
                    ldmx4t(vH, smb + VHI_O + bo);
                    mma16816h(acc[np*2+0], pH, vH);
                    mma16816h(acc[np*2+0], pL, vH);
                    mma16816h(acc[np*2+1], pH, vH + 2);
                    mma16816h(acc[np*2+1], pL, vH + 2);
                }
            }
        }
    }
    __syncthreads();

    // ---- normalize + store ----
    {
        int r0 = wm * 16 + (lane >> 2);
        float invl0 = 1.f / lrow[r0];
        float invl1 = 1.f / lrow[r0 + 8];
        #pragma unroll
        for (int nf = 0; nf < 16; nf++) {
            int cl = wn * 128 + nf * 8 + (lane & 3) * 2;
            int g  = cl >> 6, d = cl & 63;
            size_t ob0 = ((size_t)(b * S_ + q0 + r0)) * HID_ + (g * HKV_ + h) * HD_ + d;
            size_t ob1 = ((size_t)(b * S_ + q0 + r0 + 8)) * HID_ + (g * HKV_ + h) * HD_ + d;
            *reinterpret_cast<float2*>(&Out[ob0]) =
                make_float2(acc[nf][0] * invl0, acc[nf][1] * invl0);
            *reinterpret_cast<float2*>(&Out[ob1]) =
                make_float2(acc[nf][2] * invl1, acc[nf][3] * invl1);
        }
    }
}

// ---------------------------------------------------------------------------
extern "C" void kernel_launch(void* const* d_in, const int* in_sizes, int n_in,
                              void* d_out, int out_size) {
    const float* X   = (const float*)d_in[0];
    const int*   pid = (const int*)  d_in[1];
    const float* Wq  = (const float*)d_in[2];
    const float* Wk  = (const float*)d_in[3];
    const float* Wv  = (const float*)d_in[4];
    float* Out = (float*)d_out;

    float *dQ, *dK;
    cudaGetSymbolAddress((void**)&dQ, g_Q);
    cudaGetSymbolAddress((void**)&dK, g_K);
    uint4 *qh, *ql, *kh, *vh;
    cudaGetSymbolAddress((void**)&qh, g_Qh); cudaGetSymbolAddress((void**)&ql, g_Ql);
    cudaGetSymbolAddress((void**)&kh, g_Kh); cudaGetSymbolAddress((void**)&vh, g_Vh);
    uint2 *xh, *xl, *wqh, *wkh, *wvh;
    cudaGetSymbolAddress((void**)&xh,  g_Xh);  cudaGetSymbolAddress((void**)&xl,  g_Xl);
    cudaGetSymbolAddress((void**)&wqh, g_Wqh);
    cudaGetSymbolAddress((void**)&wkh, g_Wkh);
    cudaGetSymbolAddress((void**)&wvh, g_Wvh);

    // Pre-convert operands: X hi/lo; weights hi only (all 2-term now)
    {
        int nX = M_ * HID_ / 4, nWqk = HID_ * NQK_ / 4, nWv = HID_ * HID_ / 4;
        cvt_f16_hilo_kernel<<<(nX + 255) / 256, 256>>>((const float4*)X, xh, xl, nX);
        cvt_f16_hi_kernel<<<(nWqk + 255) / 256, 256>>>((const float4*)Wq, wqh, nWqk);
        cvt_f16_hi_kernel<<<(nWqk + 255) / 256, 256>>>((const float4*)Wk, wkh, nWqk);
        cvt_f16_hi_kernel<<<(nWv + 255) / 256, 256>>>((const float4*)Wv, wvh, nWv);
    }

    // Projections: fused Q/K (2-term, fp32 out) + V (2-term, fp16 out)
    {
        cudaFuncSetAttribute(gemm_pipe_kernel<false, false>,
                             cudaFuncAttributeMaxDynamicSharedMemorySize, GEMM_SMEM);
        cudaFuncSetAttribute(gemm_pipe_kernel<false, true>,
                             cudaFuncAttributeMaxDynamicSharedMemorySize, GEMM_SMEM);
        dim3 blk(256);
        dim3 grdQK(NQK_ / 256, M_ / 128, 2);
        gemm_pipe_kernel<false, false><<<grdQK, blk, GEMM_SMEM>>>(
            xh, xl, wqh, wqh, dQ, wkh, wkh, dK, NQK_, HID_);
        dim3 grdV(HID_ / 256, M_ / 128, 1);
        gemm_pipe_kernel<false, true><<<grdV, blk, GEMM_SMEM>>>(
            xh, xl, wvh, wvh, vh, wvh, wvh, vh, HID_, HID_);
    }
    // RoPE + fp16 conversion
    {
        int total = B_ * S_ * HKV_ * 32;
        rope_cvt_kernel<<<(total + 255) / 256, 256>>>(
            dQ, dK, pid, (__half*)qh, (__half*)ql, (__half*)kh);
    }
    // Attention
    {
        cudaFuncSetAttribute(attn_mma_kernel,
                             cudaFuncAttributeMaxDynamicSharedMemorySize, ATTN_SMEM);
        dim3 grd(S_ / 64, HKV_, B_);
        attn_mma_kernel<<<grd, 256, ATTN_SMEM>>>(qh, ql, kh, vh, Out);
    }
}

// round 10
// speedup vs baseline: 5.2639x; 1.1821x over previous
#include <cuda_runtime.h>
#include <cuda_fp16.h>
#include <math.h>
#include <stdint.h>

#define B_   2
#define S_   2048
#define HID_ 2048
#define NH_  32
#define G_   4
#define HD_  64
#define HKV_ 8
#define NQK_ 512   // HKV_*HD_
#define M_   (B_ * S_)   // 4096

// Scratch (device globals: no allocation allowed)
__device__ float g_Q[(size_t)M_*NQK_];   // fp32 Q (pre-rope)
__device__ float g_K[(size_t)M_*NQK_];   // fp32 K (pre-rope)
// fp16 post-rope / projected tensors
__device__ uint4 g_Qh[(size_t)M_*NQK_/8], g_Ql[(size_t)M_*NQK_/8];
__device__ uint4 g_Kh[(size_t)M_*NQK_/8];
__device__ uint4 g_Vh[(size_t)M_*HID_/8];
// fp16 pre-converted GEMM operands
__device__ uint2 g_Xh[(size_t)M_*HID_/4],  g_Xl[(size_t)M_*HID_/4];
__device__ uint2 g_Wqh[(size_t)HID_*NQK_/4];
__device__ uint2 g_Wkh[(size_t)HID_*NQK_/4];
__device__ uint2 g_Wvh[(size_t)HID_*HID_/4];

// ===========================================================================
// helpers
// ===========================================================================
__device__ __forceinline__ uint32_t smem_to_u32(const void* smem_ptr) {
    uint32_t addr;
    asm("{ .reg .u64 tmp; cvta.to.shared.u64 tmp, %1; cvt.u32.u64 %0, tmp; }"
        : "=r"(addr) : "l"(smem_ptr));
    return addr;
}
__device__ __forceinline__ uint32_t pack_hf2(float a, float b) {
    uint32_t r;
    asm("cvt.rn.f16x2.f32 %0, %1, %2;" : "=r"(r) : "f"(b), "f"(a));
    return r;
}
__device__ __forceinline__ float hf_lo_f32(uint32_t h) {
    __half2 v = *reinterpret_cast<__half2*>(&h);
    return __low2float(v);
}
__device__ __forceinline__ float hf_hi_f32(uint32_t h) {
    __half2 v = *reinterpret_cast<__half2*>(&h);
    return __high2float(v);
}

__device__ __forceinline__ void ldmx4(uint32_t r[4], uint32_t addr) {
    asm volatile("ldmatrix.sync.aligned.m8n8.x4.shared.b16 {%0,%1,%2,%3}, [%4];"
        : "=r"(r[0]), "=r"(r[1]), "=r"(r[2]), "=r"(r[3]) : "r"(addr));
}
__device__ __forceinline__ void ldmx4t(uint32_t r[4], uint32_t addr) {
    asm volatile("ldmatrix.sync.aligned.m8n8.x4.trans.shared.b16 {%0,%1,%2,%3}, [%4];"
        : "=r"(r[0]), "=r"(r[1]), "=r"(r[2]), "=r"(r[3]) : "r"(addr));
}
__device__ __forceinline__ void mma16816h(float d[4], const uint32_t a[4],
                                          const uint32_t b[2]) {
    asm volatile(
        "mma.sync.aligned.m16n8k16.row.col.f32.f16.f16.f32 "
        "{%0,%1,%2,%3}, {%4,%5,%6,%7}, {%8,%9}, {%0,%1,%2,%3};"
        : "+f"(d[0]), "+f"(d[1]), "+f"(d[2]), "+f"(d[3])
        : "r"(a[0]), "r"(a[1]), "r"(a[2]), "r"(a[3]), "r"(b[0]), "r"(b[1]));
}
__device__ __forceinline__ void cp16(uint32_t dst, const void* src) {
    asm volatile("cp.async.cg.shared.global [%0], [%1], 16;"
                 :: "r"(dst), "l"(src));
}
__device__ __forceinline__ void cp_commit() {
    asm volatile("cp.async.commit_group;" ::: "memory");
}
template <int N>
__device__ __forceinline__ void cp_wait() {
    asm volatile("cp.async.wait_group %0;" :: "n"(N) : "memory");
}

// ===========================================================================
// Pre-convert fp32 -> fp16 hi/lo (and hi-only variant)
// ===========================================================================
__global__ void cvt_f16_hilo_kernel(const float4* __restrict__ src,
                                    uint2* __restrict__ hi, uint2* __restrict__ lo,
                                    int n4) {
    int i = blockIdx.x * blockDim.x + threadIdx.x;
    if (i >= n4) return;
    float4 v = src[i];
    uint32_t h0 = pack_hf2(v.x, v.y), h1 = pack_hf2(v.z, v.w);
    uint32_t l0 = pack_hf2(v.x - hf_lo_f32(h0), v.y - hf_hi_f32(h0));
    uint32_t l1 = pack_hf2(v.z - hf_lo_f32(h1), v.w - hf_hi_f32(h1));
    hi[i] = make_uint2(h0, h1);
    lo[i] = make_uint2(l0, l1);
}
__global__ void cvt_f16_hi_kernel(const float4* __restrict__ src,
                                  uint2* __restrict__ hi, int n4) {
    int i = blockIdx.x * blockDim.x + threadIdx.x;
    if (i >= n4) return;
    float4 v = src[i];
    hi[i] = make_uint2(pack_hf2(v.x, v.y), pack_hf2(v.z, v.w));
}

// ===========================================================================
// 4-stage cp.async fp16 GEMM: C[M,N] = A[M,K] @ B[K,N]
// CTA 128x256, warp 64x64 (2m x 4n), K-chunk 32.
// SPLIT_A: add Al*Bh term. OUT_HALF: write fp16 C.
// ===========================================================================
#define SAe 40
#define SBe 264
#define ST_AHI 0
#define ST_ALO 10240
#define ST_BHI 20480
#define ST_BLO 37376
#define ST_SZ  54272
#define NSTG 4
#define GEMM_SMEM (NSTG * ST_SZ)

template<bool SPLIT_A, bool OUT_HALF>
__global__ __launch_bounds__(256, 1)
void gemm_pipe_kernel(const void* __restrict__ Ah, const void* __restrict__ Al,
                      const void* __restrict__ Bh0, void* __restrict__ C0,
                      const void* __restrict__ Bh1, void* __restrict__ C1,
                      int N, int K) {
    extern __shared__ char sm[];
    const uint32_t smb = smem_to_u32(sm);
    const int tid = threadIdx.x, lane = tid & 31, wid = tid >> 5;
    const int wm = wid >> 2, wn = wid & 3;
    const int m0 = blockIdx.y * 128, n0 = blockIdx.x * 256;

    const char* Bh = (const char*)(blockIdx.z ? Bh1 : Bh0);
    void* C = blockIdx.z ? C1 : C0;
    const char* Ahc = (const char*)Ah;
    const char* Alc = (const char*)Al;

    float acc[4][8][4];
    #pragma unroll
    for (int i = 0; i < 4; i++)
        #pragma unroll
        for (int j = 0; j < 8; j++)
            #pragma unroll
            for (int t = 0; t < 4; t++) acc[i][j][t] = 0.f;

    const uint32_t aRow  = lane & 15;
    const uint32_t aColH = (lane >> 4) * 8;
    const uint32_t bRow  = (lane & 7) + ((lane >> 3) & 1) * 8;
    const uint32_t bCol  = ((lane >> 4) & 1) * 8;
    const int nch = K >> 5;

    auto issue = [&](int s, int k0) {
        uint32_t sb = smb + s * ST_SZ;
        #pragma unroll
        for (int i = 0; i < 2; i++) {
            int idx = tid + (i << 8);
            int row = idx >> 2, seg = idx & 3;
            size_t go = ((size_t)(m0 + row) * K + k0 + seg * 8) * 2;
            uint32_t so = row * 80 + seg * 16;
            cp16(sb + ST_AHI + so, Ahc + go);
            if (SPLIT_A) cp16(sb + ST_ALO + so, Alc + go);
        }
        #pragma unroll
        for (int i = 0; i < 4; i++) {
            int idx = tid + (i << 8);
            int row = idx >> 5, seg = idx & 31;
            size_t go = ((size_t)(k0 + row) * N + n0 + seg * 8) * 2;
            uint32_t so = row * 528 + seg * 16;
            cp16(sb + ST_BHI + so, Bh + go);
        }
        cp_commit();
    };

    issue(0, 0);
    issue(1, 32);
    for (int c = 0; c < nch; c++) {
        if (c + 2 < nch) issue((c + 2) & (NSTG - 1), (c + 2) << 5);
        else             cp_commit();
        cp_wait<2>();
        __syncthreads();

        const uint32_t sb = smb + (c & (NSTG - 1)) * ST_SZ;
        #pragma unroll
        for (int ks = 0; ks < 2; ks++) {
            uint32_t aH[4][4], aL[4][4];
            #pragma unroll
            for (int mf = 0; mf < 4; mf++) {
                uint32_t ao = ((wm * 64 + mf * 16 + aRow) * SAe + ks * 16 + aColH) * 2;
                ldmx4(aH[mf], sb + ST_AHI + ao);
                if (SPLIT_A) ldmx4(aL[mf], sb + ST_ALO + ao);
            }
            uint32_t bH[4][4];
            #pragma unroll
            for (int ng = 0; ng < 4; ng++) {
                uint32_t bo = ((ks * 16 + bRow) * SBe + wn * 64 + ng * 16 + bCol) * 2;
                ldmx4t(bH[ng], sb + ST_BHI + bo);
            }
            #pragma unroll
            for (int mf = 0; mf < 4; mf++)
                #pragma unroll
                for (int ng = 0; ng < 4; ng++) {
                    mma16816h(acc[mf][ng*2+0], aH[mf], bH[ng]);
                    if (SPLIT_A) mma16816h(acc[mf][ng*2+0], aL[mf], bH[ng]);
                    mma16816h(acc[mf][ng*2+1], aH[mf], bH[ng] + 2);
                    if (SPLIT_A) mma16816h(acc[mf][ng*2+1], aL[mf], bH[ng] + 2);
                }
        }
    }

    #pragma unroll
    for (int mf = 0; mf < 4; mf++) {
        int row = m0 + wm * 64 + mf * 16 + (lane >> 2);
        #pragma unroll
        for (int nf = 0; nf < 8; nf++) {
            int col = n0 + wn * 64 + nf * 8 + (lane & 3) * 2;
            if (OUT_HALF) {
                __half* Ch = reinterpret_cast<__half*>(C);
                *reinterpret_cast<uint32_t*>(Ch + (size_t)row * N + col) =
                    pack_hf2(acc[mf][nf][0], acc[mf][nf][1]);
                *reinterpret_cast<uint32_t*>(Ch + (size_t)(row + 8) * N + col) =
                    pack_hf2(acc[mf][nf][2], acc[mf][nf][3]);
            } else {
                float* Cf = reinterpret_cast<float*>(C);
                *reinterpret_cast<float2*>(Cf + (size_t)row * N + col) =
                    make_float2(acc[mf][nf][0], acc[mf][nf][1]);
                *reinterpret_cast<float2*>(Cf + (size_t)(row + 8) * N + col) =
                    make_float2(acc[mf][nf][2], acc[mf][nf][3]);
            }
        }
    }
}

// ---------------------------------------------------------------------------
// RoPE fused with fp16 conversion
// ---------------------------------------------------------------------------
__global__ void rope_cvt_kernel(const float* __restrict__ Q, const float* __restrict__ K,
                                const int* __restrict__ pos_ids,
                                __half* __restrict__ Qh, __half* __restrict__ Ql,
                                __half* __restrict__ Kh) {
    int idx = blockIdx.x * blockDim.x + threadIdx.x;
    if (idx >= B_ * S_ * HKV_ * 32) return;
    int d   = idx & 31;
    int h   = (idx >> 5) & (HKV_ - 1);
    int row = idx >> 8;
    float p    = (float)pos_ids[row];
    float invf = powf(10000.0f, -(float)d * (1.0f / 32.0f));
    float a = p * invf;
    float sn, cs;
    sincosf(a, &sn, &cs);
    size_t base = (size_t)row * NQK_ + h * HD_;
    float q0 = Q[base + d], q1 = Q[base + d + 32];
    float qr0 = (q0 * cs - q1 * sn) * 0.125f;
    float qr1 = (q1 * cs + q0 * sn) * 0.125f;
    __half qh0 = __float2half_rn(qr0), qh1 = __float2half_rn(qr1);
    Qh[base + d]      = qh0;
    Qh[base + d + 32] = qh1;
    Ql[base + d]      = __float2half_rn(qr0 - __half2float(qh0));
    Ql[base + d + 32] = __float2half_rn(qr1 - __half2float(qh1));
    float k0 = K[base + d], k1 = K[base + d + 32];
    Kh[base + d]      = __float2half_rn(k0 * cs - k1 * sn);
    Kh[base + d + 32] = __float2half_rn(k1 * cs + k0 * sn);
}

// ===========================================================================
// Flash attention: QK 2-term (Qh+Ql)·Kh, PV 1-term Phi·Vh.
// smem 88.3 KB -> 2 CTAs/SM.
// ===========================================================================
#define SK   72
#define SV   264
#define PITX 66
#define QHI_O 0
#define QLO_O 9216
#define KHI_O 18432
#define VHI_O 27648
#define PS_O  61440
#define PHI_O 78336
#define MR_O  87552
#define LR_O  87808
#define SF_O  88064
#define ATTN_SMEM 88320

__global__ __launch_bounds__(256, 2)
void attn_mma_kernel(const uint4* __restrict__ Qh, const uint4* __restrict__ Ql,
                     const uint4* __restrict__ Kh, const uint4* __restrict__ Vh,
                     float* __restrict__ Out) {
    extern __shared__ char sm[];
    const uint32_t smb = smem_to_u32(sm);
    float* Ps   = reinterpret_cast<float*>(sm + PS_O);
    float* mrow = reinterpret_cast<float*>(sm + MR_O);
    float* lrow = reinterpret_cast<float*>(sm + LR_O);
    float* sfac = reinterpret_cast<float*>(sm + SF_O);

    const int tid = threadIdx.x, lane = tid & 31, wid = tid >> 5;
    const int wm = wid >> 1, wn = wid & 1;
    const int b  = blockIdx.z;
    const int h  = blockIdx.y;
    const int qb = blockIdx.x;
    const int q0 = qb * 64;

    // ---- load Q tile hi/lo (pre-scaled fp16) ----
    #pragma unroll
    for (int i = 0; i < 2; i++) {
        int idx = tid + (i << 8);
        int r = idx >> 3, c8 = idx & 7;
        size_t gi = (size_t)(b * S_ + q0 + r) * 64 + h * 8 + c8;
        uint32_t off = (r * SK + c8 * 8) * 2;
        *reinterpret_cast<uint4*>(sm + QHI_O + off) = Qh[gi];
        *reinterpret_cast<uint4*>(sm + QLO_O + off) = Ql[gi];
    }
    if (tid < 64) { mrow[tid] = -INFINITY; lrow[tid] = 0.f; }

    float acc[16][4];
    #pragma unroll
    for (int i = 0; i < 16; i++)
        #pragma unroll
        for (int t = 0; t < 4; t++) acc[i][t] = 0.f;

    const uint32_t aRow  = lane & 15;
    const uint32_t aColH = (lane >> 4) * 8;
    const uint32_t kbRow = (lane & 7) + ((lane >> 4) & 1) * 8;
    const uint32_t kbCol = ((lane >> 3) & 1) * 8;
    const uint32_t vbRow = (lane & 7) + ((lane >> 3) & 1) * 8;
    const uint32_t vbCol = ((lane >> 4) & 1) * 8;

    for (int kt = 0; kt <= qb; kt++) {
        const int k0 = kt * 64;
        __syncthreads();

        // ---- K tile ----
        #pragma unroll
        for (int i = 0; i < 2; i++) {
            int idx = tid + (i << 8);
            int kk = idx >> 3, c8 = idx & 7;
            size_t gi = (size_t)(b * S_ + k0 + kk) * 64 + h * 8 + c8;
            uint32_t off = (kk * SK + c8 * 8) * 2;
            *reinterpret_cast<uint4*>(sm + KHI_O + off) = Kh[gi];
        }
        // ---- V tile [key][256 cols] ----
        #pragma unroll
        for (int i = 0; i < 8; i++) {
            int idx = tid + (i << 8);
            int kk = idx >> 5, c8 = idx & 31;
            int g = c8 >> 3, d8 = c8 & 7;
            size_t gi = (size_t)(b * S_ + k0 + kk) * 256 + g * 64 + h * 8 + d8;
            uint32_t off = (kk * SV + c8 * 8) * 2;
            *reinterpret_cast<uint4*>(sm + VHI_O + off) = Vh[gi];
        }
        __syncthreads();

        // ---- QK^T: 2-term ----
        {
            float sfr[4][4];
            #pragma unroll
            for (int i = 0; i < 4; i++)
                #pragma unroll
                for (int t = 0; t < 4; t++) sfr[i][t] = 0.f;

            #pragma unroll
            for (int ks = 0; ks < 4; ks++) {
                uint32_t aH[4], aL[4];
                uint32_t ao = ((wm * 16 + aRow) * SK + ks * 16 + aColH) * 2;
                ldmx4(aH, smb + QHI_O + ao);
                ldmx4(aL, smb + QLO_O + ao);
                #pragma unroll
                for (int np = 0; np < 2; np++) {
                    uint32_t bH[4];
                    uint32_t nb = wn * 32 + np * 16;
                    uint32_t bo = ((nb + kbRow) * SK + ks * 16 + kbCol) * 2;
                    ldmx4(bH, smb + KHI_O + bo);
                    mma16816h(sfr[np*2+0], aH, bH);
                    mma16816h(sfr[np*2+0], aL, bH);
                    mma16816h(sfr[np*2+1], aH, bH + 2);
                    mma16816h(sfr[np*2+1], aL, bH + 2);
                }
            }
            int r0 = wm * 16 + (lane >> 2);
            #pragma unroll
            for (int nf = 0; nf < 4; nf++) {
                int cb = wn * 32 + nf * 8 + (lane & 3) * 2;
                *reinterpret_cast<float2*>(&Ps[r0 * PITX + cb]) =
                    make_float2(sfr[nf][0], sfr[nf][1]);
                *reinterpret_cast<float2*>(&Ps[(r0 + 8) * PITX + cb]) =
                    make_float2(sfr[nf][2], sfr[nf][3]);
            }
        }
        __syncthreads();

        // ---- online softmax ----
        if (tid < 64) {
            const int row = tid;
            const int kmax = (kt == qb) ? row : 63;
            float m_old = mrow[row];
            float mx = m_old;
            for (int k = 0; k <= kmax; k++) mx = fmaxf(mx, Ps[row * PITX + k]);
            float sum = 0.f;
            for (int k = 0; k < 64; k++) {
                float p = (k <= kmax) ? expf(Ps[row * PITX + k] - mx) : 0.f;
                Ps[row * PITX + k] = p;
                sum += p;
            }
            float f = expf(m_old - mx);
            sfac[row] = f;
            lrow[row] = lrow[row] * f + sum;
            mrow[row] = mx;
        }
        __syncthreads();

        // ---- convert P -> fp16 (hi only) ----
        {
            int row = tid >> 2;
            int cb  = (tid & 3) * 16;
            #pragma unroll
            for (int j = 0; j < 8; j++) {
                float p0 = Ps[row * PITX + cb + 2*j];
                float p1 = Ps[row * PITX + cb + 2*j + 1];
                uint32_t off = (row * SK + cb + 2*j) * 2;
                *reinterpret_cast<uint32_t*>(sm + PHI_O + off) = pack_hf2(p0, p1);
            }
        }
        __syncthreads();

        // ---- PV: rescale + Phi @ Vh ----
        {
            float f0 = sfac[wm * 16 + (lane >> 2)];
            float f1 = sfac[wm * 16 + (lane >> 2) + 8];
            #pragma unroll
            for (int i = 0; i < 16; i++) {
                acc[i][0] *= f0; acc[i][1] *= f0;
                acc[i][2] *= f1; acc[i][3] *= f1;
            }
            #pragma unroll
            for (int ks = 0; ks < 4; ks++) {
                uint32_t pH[4];
                uint32_t ao = ((wm * 16 + aRow) * SK + ks * 16 + aColH) * 2;
                ldmx4(pH, smb + PHI_O + ao);
                #pragma unroll
                for (int np = 0; np < 8; np++) {
                    uint32_t vH[4];
                    uint32_t nb = wn * 128 + np * 16;
                    uint32_t bo = ((ks * 16 + vbRow) * SV + nb + vbCol) * 2;
                    ldmx4t(vH, smb + VHI_O + bo);
                    mma16816h(acc[np*2+0], pH, vH);
                    mma16816h(acc[np*2+1], pH, vH + 2);
                }
            }
        }
    }
    __syncthreads();

    // ---- normalize + store ----
    {
        int r0 = wm * 16 + (lane >> 2);
        float invl0 = 1.f / lrow[r0];
        float invl1 = 1.f / lrow[r0 + 8];
        #pragma unroll
        for (int nf = 0; nf < 16; nf++) {
            int cl = wn * 128 + nf * 8 + (lane & 3) * 2;
            int g  = cl >> 6, d = cl & 63;
            size_t ob0 = ((size_t)(b * S_ + q0 + r0)) * HID_ + (g * HKV_ + h) * HD_ + d;
            size_t ob1 = ((size_t)(b * S_ + q0 + r0 + 8)) * HID_ + (g * HKV_ + h) * HD_ + d;
            *reinterpret_cast<float2*>(&Out[ob0]) =
                make_float2(acc[nf][0] * invl0, acc[nf][1] * invl0);
            *reinterpret_cast<float2*>(&Out[ob1]) =
                make_float2(acc[nf][2] * invl1, acc[nf][3] * invl1);
        }
    }
}

// ---------------------------------------------------------------------------
extern "C" void kernel_launch(void* const* d_in, const int* in_sizes, int n_in,
                              void* d_out, int out_size) {
    const float* X   = (const float*)d_in[0];
    const int*   pid = (const int*)  d_in[1];
    const float* Wq  = (const float*)d_in[2];
    const float* Wk  = (const float*)d_in[3];
    const float* Wv  = (const float*)d_in[4];
    float* Out = (float*)d_out;

    float *dQ, *dK;
    cudaGetSymbolAddress((void**)&dQ, g_Q);
    cudaGetSymbolAddress((void**)&dK, g_K);
    uint4 *qh, *ql, *kh, *vh;
    cudaGetSymbolAddress((void**)&qh, g_Qh); cudaGetSymbolAddress((void**)&ql, g_Ql);
    cudaGetSymbolAddress((void**)&kh, g_Kh); cudaGetSymbolAddress((void**)&vh, g_Vh);
    uint2 *xh, *xl, *wqh, *wkh, *wvh;
    cudaGetSymbolAddress((void**)&xh,  g_Xh);  cudaGetSymbolAddress((void**)&xl,  g_Xl);
    cudaGetSymbolAddress((void**)&wqh, g_Wqh);
    cudaGetSymbolAddress((void**)&wkh, g_Wkh);
    cudaGetSymbolAddress((void**)&wvh, g_Wvh);

    // Pre-convert operands
    {
        int nX = M_ * HID_ / 4, nWqk = HID_ * NQK_ / 4, nWv = HID_ * HID_ / 4;
        cvt_f16_hilo_kernel<<<(nX + 255) / 256, 256>>>((const float4*)X, xh, xl, nX);
        cvt_f16_hi_kernel<<<(nWqk + 255) / 256, 256>>>((const float4*)Wq, wqh, nWqk);
        cvt_f16_hi_kernel<<<(nWqk + 255) / 256, 256>>>((const float4*)Wk, wkh, nWqk);
        cvt_f16_hi_kernel<<<(nWv + 255) / 256, 256>>>((const float4*)Wv, wvh, nWv);
    }

    // Projections: fused Q/K (2-term, fp32 out) + V (1-term, fp16 out)
    {
        cudaFuncSetAttribute(gemm_pipe_kernel<true, false>,
                             cudaFuncAttributeMaxDynamicSharedMemorySize, GEMM_SMEM);
        cudaFuncSetAttribute(gemm_pipe_kernel<false, true>,
                             cudaFuncAttributeMaxDynamicSharedMemorySize, GEMM_SMEM);
        dim3 blk(256);
        dim3 grdQK(NQK_ / 256, M_ / 128, 2);
        gemm_pipe_kernel<true, false><<<grdQK, blk, GEMM_SMEM>>>(
            xh, xl, wqh, dQ, wkh, dK, NQK_, HID_);
        dim3 grdV(HID_ / 256, M_ / 128, 1);
        gemm_pipe_kernel<false, true><<<grdV, blk, GEMM_SMEM>>>(
            xh, xl, wvh, vh, wvh, vh, HID_, HID_);
    }
    // RoPE + fp16 conversion
    {
        int total = B_ * S_ * HKV_ * 32;
        rope_cvt_kernel<<<(total + 255) / 256, 256>>>(
            dQ, dK, pid, (__half*)qh, (__half*)ql, (__half*)kh);
    }
    // Attention
    {
        cudaFuncSetAttribute(attn_mma_kernel,
                             cudaFuncAttributeMaxDynamicSharedMemorySize, ATTN_SMEM);
        dim3 grd(S_ / 64, HKV_, B_);
        attn_mma_kernel<<<grd, 256, ATTN_SMEM>>>(qh, ql, kh, vh, Out);
    }
}

// round 11
// speedup vs baseline: 5.6626x; 1.0757x over previous
#include <cuda_runtime.h>
#include <cuda_fp16.h>
#include <math.h>
#include <stdint.h>

#define B_   2
#define S_   2048
#define HID_ 2048
#define NH_  32
#define G_   4
#define HD_  64
#define HKV_ 8
#define NQK_ 512   // HKV_*HD_
#define M_   (B_ * S_)   // 4096

// Scratch (device globals: no allocation allowed)
__device__ float g_Q[(size_t)M_*NQK_];   // fp32 Q (pre-rope)
__device__ float g_K[(size_t)M_*NQK_];   // fp32 K (pre-rope)
// fp16 post-rope / projected tensors
__device__ uint4 g_Qh[(size_t)M_*NQK_/8], g_Ql[(size_t)M_*NQK_/8];
__device__ uint4 g_Kh[(size_t)M_*NQK_/8];
__device__ uint4 g_Vh[(size_t)M_*HID_/8];
// fp16 pre-converted GEMM operands (hi only — all GEMMs are 1-term now)
__device__ uint2 g_Xh[(size_t)M_*HID_/4];
__device__ uint2 g_Wqh[(size_t)HID_*NQK_/4];
__device__ uint2 g_Wkh[(size_t)HID_*NQK_/4];
__device__ uint2 g_Wvh[(size_t)HID_*HID_/4];

// ===========================================================================
// helpers
// ===========================================================================
__device__ __forceinline__ uint32_t smem_to_u32(const void* smem_ptr) {
    uint32_t addr;
    asm("{ .reg .u64 tmp; cvta.to.shared.u64 tmp, %1; cvt.u32.u64 %0, tmp; }"
        : "=r"(addr) : "l"(smem_ptr));
    return addr;
}
__device__ __forceinline__ uint32_t pack_hf2(float a, float b) {
    uint32_t r;
    asm("cvt.rn.f16x2.f32 %0, %1, %2;" : "=r"(r) : "f"(b), "f"(a));
    return r;
}
__device__ __forceinline__ float hf_lo_f32(uint32_t h) {
    __half2 v = *reinterpret_cast<__half2*>(&h);
    return __low2float(v);
}
__device__ __forceinline__ float hf_hi_f32(uint32_t h) {
    __half2 v = *reinterpret_cast<__half2*>(&h);
    return __high2float(v);
}

__device__ __forceinline__ void ldmx4(uint32_t r[4], uint32_t addr) {
    asm volatile("ldmatrix.sync.aligned.m8n8.x4.shared.b16 {%0,%1,%2,%3}, [%4];"
        : "=r"(r[0]), "=r"(r[1]), "=r"(r[2]), "=r"(r[3]) : "r"(addr));
}
__device__ __forceinline__ void ldmx4t(uint32_t r[4], uint32_t addr) {
    asm volatile("ldmatrix.sync.aligned.m8n8.x4.trans.shared.b16 {%0,%1,%2,%3}, [%4];"
        : "=r"(r[0]), "=r"(r[1]), "=r"(r[2]), "=r"(r[3]) : "r"(addr));
}
__device__ __forceinline__ void mma16816h(float d[4], const uint32_t a[4],
                                          const uint32_t b[2]) {
    asm volatile(
        "mma.sync.aligned.m16n8k16.row.col.f32.f16.f16.f32 "
        "{%0,%1,%2,%3}, {%4,%5,%6,%7}, {%8,%9}, {%0,%1,%2,%3};"
        : "+f"(d[0]), "+f"(d[1]), "+f"(d[2]), "+f"(d[3])
        : "r"(a[0]), "r"(a[1]), "r"(a[2]), "r"(a[3]), "r"(b[0]), "r"(b[1]));
}
__device__ __forceinline__ void cp16(uint32_t dst, const void* src) {
    asm volatile("cp.async.cg.shared.global [%0], [%1], 16;"
                 :: "r"(dst), "l"(src));
}
__device__ __forceinline__ void cp_commit() {
    asm volatile("cp.async.commit_group;" ::: "memory");
}
template <int N>
__device__ __forceinline__ void cp_wait() {
    asm volatile("cp.async.wait_group %0;" :: "n"(N) : "memory");
}

// ===========================================================================
// Fused pre-convert fp32 -> fp16 (X, Wq, Wk, Wv in one launch)
// ===========================================================================
__global__ void cvt_all_kernel(const float4* __restrict__ X,
                               const float4* __restrict__ Wq,
                               const float4* __restrict__ Wk,
                               const float4* __restrict__ Wv,
                               uint2* __restrict__ xh, uint2* __restrict__ wqh,
                               uint2* __restrict__ wkh, uint2* __restrict__ wvh) {
    const float4* src;
    uint2* dst;
    int n4;
    switch (blockIdx.y) {
        case 0: src = X;  dst = xh;  n4 = M_ * HID_ / 4;   break;
        case 1: src = Wq; dst = wqh; n4 = HID_ * NQK_ / 4; break;
        case 2: src = Wk; dst = wkh; n4 = HID_ * NQK_ / 4; break;
        default: src = Wv; dst = wvh; n4 = HID_ * HID_ / 4; break;
    }
    int i = blockIdx.x * blockDim.x + threadIdx.x;
    if (i >= n4) return;
    float4 v = src[i];
    dst[i] = make_uint2(pack_hf2(v.x, v.y), pack_hf2(v.z, v.w));
}

// ===========================================================================
// Fused 1-term fp16 GEMM for all three projections, one launch.
// CTA tile 128x256, warp 64x64 (2m x 4n), K-chunk 32, 4-stage cp.async.
// blockIdx.x: 0-1 -> Wq (fp32 out), 2-3 -> Wk (fp32 out), 4-11 -> Wv (fp16 out)
// ===========================================================================
#define SAe 40
#define SBe 264
#define ST_AHI 0
#define ST_BHI 10240
#define ST_SZ  27136
#define NSTG 4
#define GEMM_SMEM (NSTG * ST_SZ)   // 108544

__global__ __launch_bounds__(256, 1)
void gemm_fused_kernel(const char* __restrict__ Ah,
                       const char* __restrict__ BhQ, float* __restrict__ CQ,
                       const char* __restrict__ BhK, float* __restrict__ CK,
                       const char* __restrict__ BhV, __half* __restrict__ CV) {
    extern __shared__ char sm[];
    const uint32_t smb = smem_to_u32(sm);
    const int tid = threadIdx.x, lane = tid & 31, wid = tid >> 5;
    const int wm = wid >> 2, wn = wid & 3;
    const int m0 = blockIdx.y * 128;
    const int nb = blockIdx.x;

    const char* Bh;
    float* Cf = nullptr;
    __half* Ch = nullptr;
    int N, n0;
    bool outHalf;
    if (nb < 2)      { Bh = BhQ; Cf = CQ; N = NQK_; n0 = nb * 256;       outHalf = false; }
    else if (nb < 4) { Bh = BhK; Cf = CK; N = NQK_; n0 = (nb - 2) * 256; outHalf = false; }
    else             { Bh = BhV; Ch = CV; N = HID_; n0 = (nb - 4) * 256; outHalf = true; }
    const int K = HID_;

    float acc[4][8][4];
    #pragma unroll
    for (int i = 0; i < 4; i++)
        #pragma unroll
        for (int j = 0; j < 8; j++)
            #pragma unroll
            for (int t = 0; t < 4; t++) acc[i][j][t] = 0.f;

    const uint32_t aRow  = lane & 15;
    const uint32_t aColH = (lane >> 4) * 8;
    const uint32_t bRow  = (lane & 7) + ((lane >> 3) & 1) * 8;
    const uint32_t bCol  = ((lane >> 4) & 1) * 8;
    const int nch = K >> 5;   // 64

    auto issue = [&](int s, int k0) {
        uint32_t sb = smb + s * ST_SZ;
        // A: 128x32 fp16 = 512 x 16B, 2 per thread
        #pragma unroll
        for (int i = 0; i < 2; i++) {
            int idx = tid + (i << 8);
            int row = idx >> 2, seg = idx & 3;
            size_t go = ((size_t)(m0 + row) * K + k0 + seg * 8) * 2;
            cp16(sb + ST_AHI + row * 80 + seg * 16, Ah + go);
        }
        // B: 32x256 fp16 = 1024 x 16B, 4 per thread
        #pragma unroll
        for (int i = 0; i < 4; i++) {
            int idx = tid + (i << 8);
            int row = idx >> 5, seg = idx & 31;
            size_t go = ((size_t)(k0 + row) * N + n0 + seg * 8) * 2;
            cp16(sb + ST_BHI + row * 528 + seg * 16, Bh + go);
        }
        cp_commit();
    };

    issue(0, 0);
    issue(1, 32);
    for (int c = 0; c < nch; c++) {
        if (c + 2 < nch) issue((c + 2) & (NSTG - 1), (c + 2) << 5);
        else             cp_commit();
        cp_wait<2>();
        __syncthreads();

        const uint32_t sb = smb + (c & (NSTG - 1)) * ST_SZ;
        #pragma unroll
        for (int ks = 0; ks < 2; ks++) {
            uint32_t aH[4][4];
            #pragma unroll
            for (int mf = 0; mf < 4; mf++) {
                uint32_t ao = ((wm * 64 + mf * 16 + aRow) * SAe + ks * 16 + aColH) * 2;
                ldmx4(aH[mf], sb + ST_AHI + ao);
            }
            uint32_t bH[4][4];
            #pragma unroll
            for (int ng = 0; ng < 4; ng++) {
                uint32_t bo = ((ks * 16 + bRow) * SBe + wn * 64 + ng * 16 + bCol) * 2;
                ldmx4t(bH[ng], sb + ST_BHI + bo);
            }
            #pragma unroll
            for (int mf = 0; mf < 4; mf++)
                #pragma unroll
                for (int ng = 0; ng < 4; ng++) {
                    mma16816h(acc[mf][ng*2+0], aH[mf], bH[ng]);
                    mma16816h(acc[mf][ng*2+1], aH[mf], bH[ng] + 2);
                }
        }
    }

    #pragma unroll
    for (int mf = 0; mf < 4; mf++) {
        int row = m0 + wm * 64 + mf * 16 + (lane >> 2);
        #pragma unroll
        for (int nf = 0; nf < 8; nf++) {
            int col = n0 + wn * 64 + nf * 8 + (lane & 3) * 2;
            if (outHalf) {
                *reinterpret_cast<uint32_t*>(Ch + (size_t)row * N + col) =
                    pack_hf2(acc[mf][nf][0], acc[mf][nf][1]);
                *reinterpret_cast<uint32_t*>(Ch + (size_t)(row + 8) * N + col) =
                    pack_hf2(acc[mf][nf][2], acc[mf][nf][3]);
            } else {
                *reinterpret_cast<float2*>(Cf + (size_t)row * N + col) =
                    make_float2(acc[mf][nf][0], acc[mf][nf][1]);
                *reinterpret_cast<float2*>(Cf + (size_t)(row + 8) * N + col) =
                    make_float2(acc[mf][nf][2], acc[mf][nf][3]);
            }
        }
    }
}

// ---------------------------------------------------------------------------
// RoPE fused with fp16 conversion
// ---------------------------------------------------------------------------
__global__ void rope_cvt_kernel(const float* __restrict__ Q, const float* __restrict__ K,
                                const int* __restrict__ pos_ids,
                                __half* __restrict__ Qh, __half* __restrict__ Ql,
                                __half* __restrict__ Kh) {
    int idx = blockIdx.x * blockDim.x + threadIdx.x;
    if (idx >= B_ * S_ * HKV_ * 32) return;
    int d   = idx & 31;
    int h   = (idx >> 5) & (HKV_ - 1);
    int row = idx >> 8;
    float p    = (float)pos_ids[row];
    float invf = powf(10000.0f, -(float)d * (1.0f / 32.0f));
    float a = p * invf;
    float sn, cs;
    sincosf(a, &sn, &cs);
    size_t base = (size_t)row * NQK_ + h * HD_;
    float q0 = Q[base + d], q1 = Q[base + d + 32];
    float qr0 = (q0 * cs - q1 * sn) * 0.125f;
    float qr1 = (q1 * cs + q0 * sn) * 0.125f;
    __half qh0 = __float2half_rn(qr0), qh1 = __float2half_rn(qr1);
    Qh[base + d]      = qh0;
    Qh[base + d + 32] = qh1;
    Ql[base + d]      = __float2half_rn(qr0 - __half2float(qh0));
    Ql[base + d + 32] = __float2half_rn(qr1 - __half2float(qh1));
    float k0 = K[base + d], k1 = K[base + d + 32];
    Kh[base + d]      = __float2half_rn(k0 * cs - k1 * sn);
    Kh[base + d + 32] = __float2half_rn(k1 * cs + k0 * sn);
}

// ===========================================================================
// Flash attention (unchanged from R10): QK 2-term (Qh+Ql)·Kh, PV 1-term.
// smem 88.3 KB -> 2 CTAs/SM.
// ===========================================================================
#define SK   72
#define SV   264
#define PITX 66
#define QHI_O 0
#define QLO_O 9216
#define KHI_O 18432
#define VHI_O 27648
#define PS_O  61440
#define PHI_O 78336
#define MR_O  87552
#define LR_O  87808
#define SF_O  88064
#define ATTN_SMEM 88320

__global__ __launch_bounds__(256, 2)
void attn_mma_kernel(const uint4* __restrict__ Qh, const uint4* __restrict__ Ql,
                     const uint4* __restrict__ Kh, const uint4* __restrict__ Vh,
                     float* __restrict__ Out) {
    extern __shared__ char sm[];
    const uint32_t smb = smem_to_u32(sm);
    float* Ps   = reinterpret_cast<float*>(sm + PS_O);
    float* mrow = reinterpret_cast<float*>(sm + MR_O);
    float* lrow = reinterpret_cast<float*>(sm + LR_O);
    float* sfac = reinterpret_cast<float*>(sm + SF_O);

    const int tid = threadIdx.x, lane = tid & 31, wid = tid >> 5;
    const int wm = wid >> 1, wn = wid & 1;
    const int b  = blockIdx.z;
    const int h  = blockIdx.y;
    const int qb = blockIdx.x;
    const int q0 = qb * 64;

    #pragma unroll
    for (int i = 0; i < 2; i++) {
        int idx = tid + (i << 8);
        int r = idx >> 3, c8 = idx & 7;
        size_t gi = (size_t)(b * S_ + q0 + r) * 64 + h * 8 + c8;
        uint32_t off = (r * SK + c8 * 8) * 2;
        *reinterpret_cast<uint4*>(sm + QHI_O + off) = Qh[gi];
        *reinterpret_cast<uint4*>(sm + QLO_O + off) = Ql[gi];
    }
    if (tid < 64) { mrow[tid] = -INFINITY; lrow[tid] = 0.f; }

    float acc[16][4];
    #pragma unroll
    for (int i = 0; i < 16; i++)
        #pragma unroll
        for (int t = 0; t < 4; t++) acc[i][t] = 0.f;

    const uint32_t aRow  = lane & 15;
    const uint32_t aColH = (lane >> 4) * 8;
    const uint32_t kbRow = (lane & 7) + ((lane >> 4) & 1) * 8;
    const uint32_t kbCol = ((lane >> 3) & 1) * 8;
    const uint32_t vbRow = (lane & 7) + ((lane >> 3) & 1) * 8;
    const uint32_t vbCol = ((lane >> 4) & 1) * 8;

    for (int kt = 0; kt <= qb; kt++) {
        const int k0 = kt * 64;
        __syncthreads();

        #pragma unroll
        for (int i = 0; i < 2; i++) {
            int idx = tid + (i << 8);
            int kk = idx >> 3, c8 = idx & 7;
            size_t gi = (size_t)(b * S_ + k0 + kk) * 64 + h * 8 + c8;
            uint32_t off = (kk * SK + c8 * 8) * 2;
            *reinterpret_cast<uint4*>(sm + KHI_O + off) = Kh[gi];
        }
        #pragma unroll
        for (int i = 0; i < 8; i++) {
            int idx = tid + (i << 8);
            int kk = idx >> 5, c8 = idx & 31;
            int g = c8 >> 3, d8 = c8 & 7;
            size_t gi = (size_t)(b * S_ + k0 + kk) * 256 + g * 64 + h * 8 + d8;
            uint32_t off = (kk * SV + c8 * 8) * 2;
            *reinterpret_cast<uint4*>(sm + VHI_O + off) = Vh[gi];
        }
        __syncthreads();

        {
            float sfr[4][4];
            #pragma unroll
            for (int i = 0; i < 4; i++)
                #pragma unroll
                for (int t = 0; t < 4; t++) sfr[i][t] = 0.f;

            #pragma unroll
            for (int ks = 0; ks < 4; ks++) {
                uint32_t aH[4], aL[4];
                uint32_t ao = ((wm * 16 + aRow) * SK + ks * 16 + aColH) * 2;
                ldmx4(aH, smb + QHI_O + ao);
                ldmx4(aL, smb + QLO_O + ao);
                #pragma unroll
                for (int np = 0; np < 2; np++) {
                    uint32_t bH[4];
                    uint32_t nb = wn * 32 + np * 16;
                    uint32_t bo = ((nb + kbRow) * SK + ks * 16 + kbCol) * 2;
                    ldmx4(bH, smb + KHI_O + bo);
                    mma16816h(sfr[np*2+0], aH, bH);
                    mma16816h(sfr[np*2+0], aL, bH);
                    mma16816h(sfr[np*2+1], aH, bH + 2);
                    mma16816h(sfr[np*2+1], aL, bH + 2);
                }
            }
            int r0 = wm * 16 + (lane >> 2);
            #pragma unroll
            for (int nf = 0; nf < 4; nf++) {
                int cb = wn * 32 + nf * 8 + (lane & 3) * 2;
                *reinterpret_cast<float2*>(&Ps[r0 * PITX + cb]) =
                    make_float2(sfr[nf][0], sfr[nf][1]);
                *reinterpret_cast<float2*>(&Ps[(r0 + 8) * PITX + cb]) =
                    make_float2(sfr[nf][2], sfr[nf][3]);
            }
        }
        __syncthreads();

        if (tid < 64) {
            const int row = tid;
            const int kmax = (kt == qb) ? row : 63;
            float m_old = mrow[row];
            float mx = m_old;
            for (int k = 0; k <= kmax; k++) mx = fmaxf(mx, Ps[row * PITX + k]);
            float sum = 0.f;
            for (int k = 0; k < 64; k++) {
                float p = (k <= kmax) ? expf(Ps[row * PITX + k] - mx) : 0.f;
                Ps[row * PITX + k] = p;
                sum += p;
            }
            float f = expf(m_old - mx);
            sfac[row] = f;
            lrow[row] = lrow[row] * f + sum;
            mrow[row] = mx;
        }
        __syncthreads();

        {
            int row = tid >> 2;
            int cb  = (tid & 3) * 16;
            #pragma unroll
            for (int j = 0; j < 8; j++) {
                float p0 = Ps[row * PITX + cb + 2*j];
                float p1 = Ps[row * PITX + cb + 2*j + 1];
                uint32_t off = (row * SK + cb + 2*j) * 2;
                *reinterpret_cast<uint32_t*>(sm + PHI_O + off) = pack_hf2(p0, p1);
            }
        }
        __syncthreads();

        {
            float f0 = sfac[wm * 16 + (lane >> 2)];
            float f1 = sfac[wm * 16 + (lane >> 2) + 8];
            #pragma unroll
            for (int i = 0; i < 16; i++) {
                acc[i][0] *= f0; acc[i][1] *= f0;
                acc[i][2] *= f1; acc[i][3] *= f1;
            }
            #pragma unroll
            for (int ks = 0; ks < 4; ks++) {
                uint32_t pH[4];
                uint32_t ao = ((wm * 16 + aRow) * SK + ks * 16 + aColH) * 2;
                ldmx4(pH, smb + PHI_O + ao);
                #pragma unroll
                for (int np = 0; np < 8; np++) {
                    uint32_t vH[4];
                    uint32_t nb = wn * 128 + np * 16;
                    uint32_t bo = ((ks * 16 + vbRow) * SV + nb + vbCol) * 2;
                    ldmx4t(vH, smb + VHI_O + bo);
                    mma16816h(acc[np*2+0], pH, vH);
                    mma16816h(acc[np*2+1], pH, vH + 2);
                }
            }
        }
    }
    __syncthreads();

    {
        int r0 = wm * 16 + (lane >> 2);
        float invl0 = 1.f / lrow[r0];
        float invl1 = 1.f / lrow[r0 + 8];
        #pragma unroll
        for (int nf = 0; nf < 16; nf++) {
            int cl = wn * 128 + nf * 8 + (lane & 3) * 2;
            int g  = cl >> 6, d = cl & 63;
            size_t ob0 = ((size_t)(b * S_ + q0 + r0)) * HID_ + (g * HKV_ + h) * HD_ + d;
            size_t ob1 = ((size_t)(b * S_ + q0 + r0 + 8)) * HID_ + (g * HKV_ + h) * HD_ + d;
            *reinterpret_cast<float2*>(&Out[ob0]) =
                make_float2(acc[nf][0] * invl0, acc[nf][1] * invl0);
            *reinterpret_cast<float2*>(&Out[ob1]) =
                make_float2(acc[nf][2] * invl1, acc[nf][3] * invl1);
        }
    }
}

// ---------------------------------------------------------------------------
extern "C" void kernel_launch(void* const* d_in, const int* in_sizes, int n_in,
                              void* d_out, int out_size) {
    const float* X   = (const float*)d_in[0];
    const int*   pid = (const int*)  d_in[1];
    const float* Wq  = (const float*)d_in[2];
    const float* Wk  = (const float*)d_in[3];
    const float* Wv  = (const float*)d_in[4];
    float* Out = (float*)d_out;

    float *dQ, *dK;
    cudaGetSymbolAddress((void**)&dQ, g_Q);
    cudaGetSymbolAddress((void**)&dK, g_K);
    uint4 *qh, *ql, *kh, *vh;
    cudaGetSymbolAddress((void**)&qh, g_Qh); cudaGetSymbolAddress((void**)&ql, g_Ql);
    cudaGetSymbolAddress((void**)&kh, g_Kh); cudaGetSymbolAddress((void**)&vh, g_Vh);
    uint2 *xh, *wqh, *wkh, *wvh;
    cudaGetSymbolAddress((void**)&xh,  g_Xh);
    cudaGetSymbolAddress((void**)&wqh, g_Wqh);
    cudaGetSymbolAddress((void**)&wkh, g_Wkh);
    cudaGetSymbolAddress((void**)&wvh, g_Wvh);

    // Fused pre-convert (one launch)
    {
        int nX4 = M_ * HID_ / 4;   // largest tensor
        dim3 grd((nX4 + 255) / 256, 4);
        cvt_all_kernel<<<grd, 256>>>((const float4*)X, (const float4*)Wq,
                                     (const float4*)Wk, (const float4*)Wv,
                                     xh, wqh, wkh, wvh);
    }
    // Fused projections (one launch, 384 CTAs)
    {
        cudaFuncSetAttribute(gemm_fused_kernel,
                             cudaFuncAttributeMaxDynamicSharedMemorySize, GEMM_SMEM);
        dim3 grd(12, M_ / 128);
        gemm_fused_kernel<<<grd, 256, GEMM_SMEM>>>(
            (const char*)xh, (const char*)wqh, dQ,
            (const char*)wkh, dK, (const char*)wvh, (__half*)vh);
    }
    // RoPE + fp16 conversion
    {
        int total = B_ * S_ * HKV_ * 32;
        rope_cvt_kernel<<<(total + 255) / 256, 256>>>(
            dQ, dK, pid, (__half*)qh, (__half*)ql, (__half*)kh);
    }
    // Attention
    {
        cudaFuncSetAttribute(attn_mma_kernel,
                             cudaFuncAttributeMaxDynamicSharedMemorySize, ATTN_SMEM);
        dim3 grd(S_ / 64, HKV_, B_);
        attn_mma_kernel<<<grd, 256, ATTN_SMEM>>>(qh, ql, kh, vh, Out);
    }
}

// round 12
// speedup vs baseline: 8.9517x; 1.5809x over previous
#include <cuda_runtime.h>
#include <cuda_fp16.h>
#include <math.h>
#include <stdint.h>

#define B_   2
#define S_   2048
#define HID_ 2048
#define NH_  32
#define G_   4
#define HD_  64
#define HKV_ 8
#define NQK_ 512   // HKV_*HD_
#define M_   (B_ * S_)   // 4096

// Scratch (device globals: no allocation allowed)
__device__ float g_Q[(size_t)M_*NQK_];   // fp32 Q (pre-rope)
__device__ float g_K[(size_t)M_*NQK_];   // fp32 K (pre-rope)
// fp16 post-rope / projected tensors
__device__ uint4 g_Qh[(size_t)M_*NQK_/8], g_Ql[(size_t)M_*NQK_/8];
__device__ uint4 g_Kh[(size_t)M_*NQK_/8];
__device__ uint4 g_Vh[(size_t)M_*HID_/8];
// fp16 pre-converted GEMM operands (hi only)
__device__ uint2 g_Xh[(size_t)M_*HID_/4];
__device__ uint2 g_Wqh[(size_t)HID_*NQK_/4];
__device__ uint2 g_Wkh[(size_t)HID_*NQK_/4];
__device__ uint2 g_Wvh[(size_t)HID_*HID_/4];

// ===========================================================================
// helpers
// ===========================================================================
__device__ __forceinline__ uint32_t smem_to_u32(const void* smem_ptr) {
    uint32_t addr;
    asm("{ .reg .u64 tmp; cvta.to.shared.u64 tmp, %1; cvt.u32.u64 %0, tmp; }"
        : "=r"(addr) : "l"(smem_ptr));
    return addr;
}
__device__ __forceinline__ uint32_t pack_hf2(float a, float b) {
    uint32_t r;
    asm("cvt.rn.f16x2.f32 %0, %1, %2;" : "=r"(r) : "f"(b), "f"(a));
    return r;
}
__device__ __forceinline__ void ldmx4(uint32_t r[4], uint32_t addr) {
    asm volatile("ldmatrix.sync.aligned.m8n8.x4.shared.b16 {%0,%1,%2,%3}, [%4];"
        : "=r"(r[0]), "=r"(r[1]), "=r"(r[2]), "=r"(r[3]) : "r"(addr));
}
__device__ __forceinline__ void ldmx4t(uint32_t r[4], uint32_t addr) {
    asm volatile("ldmatrix.sync.aligned.m8n8.x4.trans.shared.b16 {%0,%1,%2,%3}, [%4];"
        : "=r"(r[0]), "=r"(r[1]), "=r"(r[2]), "=r"(r[3]) : "r"(addr));
}
__device__ __forceinline__ void mma16816h(float d[4], const uint32_t a[4],
                                          const uint32_t b[2]) {
    asm volatile(
        "mma.sync.aligned.m16n8k16.row.col.f32.f16.f16.f32 "
        "{%0,%1,%2,%3}, {%4,%5,%6,%7}, {%8,%9}, {%0,%1,%2,%3};"
        : "+f"(d[0]), "+f"(d[1]), "+f"(d[2]), "+f"(d[3])
        : "r"(a[0]), "r"(a[1]), "r"(a[2]), "r"(a[3]), "r"(b[0]), "r"(b[1]));
}
__device__ __forceinline__ void cp16(uint32_t dst, const void* src) {
    asm volatile("cp.async.cg.shared.global [%0], [%1], 16;"
                 :: "r"(dst), "l"(src));
}
__device__ __forceinline__ void cp_commit() {
    asm volatile("cp.async.commit_group;" ::: "memory");
}
template <int N>
__device__ __forceinline__ void cp_wait() {
    asm volatile("cp.async.wait_group %0;" :: "n"(N) : "memory");
}

// ===========================================================================
// Fused pre-convert fp32 -> fp16 (X, Wq, Wk, Wv in one launch)
// ===========================================================================
__global__ void cvt_all_kernel(const float4* __restrict__ X,
                               const float4* __restrict__ Wq,
                               const float4* __restrict__ Wk,
                               const float4* __restrict__ Wv,
                               uint2* __restrict__ xh, uint2* __restrict__ wqh,
                               uint2* __restrict__ wkh, uint2* __restrict__ wvh) {
    const float4* src;
    uint2* dst;
    int n4;
    switch (blockIdx.y) {
        case 0: src = X;  dst = xh;  n4 = M_ * HID_ / 4;   break;
        case 1: src = Wq; dst = wqh; n4 = HID_ * NQK_ / 4; break;
        case 2: src = Wk; dst = wkh; n4 = HID_ * NQK_ / 4; break;
        default: src = Wv; dst = wvh; n4 = HID_ * HID_ / 4; break;
    }
    int i = blockIdx.x * blockDim.x + threadIdx.x;
    if (i >= n4) return;
    float4 v = src[i];
    dst[i] = make_uint2(pack_hf2(v.x, v.y), pack_hf2(v.z, v.w));
}

// ===========================================================================
// Fused 1-term fp16 GEMM for all three projections (unchanged from R11)
// ===========================================================================
#define SAe 40
#define SBe 264
#define ST_AHI 0
#define ST_BHI 10240
#define ST_SZ  27136
#define NSTG 4
#define GEMM_SMEM (NSTG * ST_SZ)

__global__ __launch_bounds__(256, 1)
void gemm_fused_kernel(const char* __restrict__ Ah,
                       const char* __restrict__ BhQ, float* __restrict__ CQ,
                       const char* __restrict__ BhK, float* __restrict__ CK,
                       const char* __restrict__ BhV, __half* __restrict__ CV) {
    extern __shared__ char sm[];
    const uint32_t smb = smem_to_u32(sm);
    const int tid = threadIdx.x, lane = tid & 31, wid = tid >> 5;
    const int wm = wid >> 2, wn = wid & 3;
    const int m0 = blockIdx.y * 128;
    const int nb = blockIdx.x;

    const char* Bh;
    float* Cf = nullptr;
    __half* Ch = nullptr;
    int N, n0;
    bool outHalf;
    if (nb < 2)      { Bh = BhQ; Cf = CQ; N = NQK_; n0 = nb * 256;       outHalf = false; }
    else if (nb < 4) { Bh = BhK; Cf = CK; N = NQK_; n0 = (nb - 2) * 256; outHalf = false; }
    else             { Bh = BhV; Ch = CV; N = HID_; n0 = (nb - 4) * 256; outHalf = true; }
    const int K = HID_;

    float acc[4][8][4];
    #pragma unroll
    for (int i = 0; i < 4; i++)
        #pragma unroll
        for (int j = 0; j < 8; j++)
            #pragma unroll
            for (int t = 0; t < 4; t++) acc[i][j][t] = 0.f;

    const uint32_t aRow  = lane & 15;
    const uint32_t aColH = (lane >> 4) * 8;
    const uint32_t bRow  = (lane & 7) + ((lane >> 3) & 1) * 8;
    const uint32_t bCol  = ((lane >> 4) & 1) * 8;
    const int nch = K >> 5;

    auto issue = [&](int s, int k0) {
        uint32_t sb = smb + s * ST_SZ;
        #pragma unroll
        for (int i = 0; i < 2; i++) {
            int idx = tid + (i << 8);
            int row = idx >> 2, seg = idx & 3;
            size_t go = ((size_t)(m0 + row) * K + k0 + seg * 8) * 2;
            cp16(sb + ST_AHI + row * 80 + seg * 16, Ah + go);
        }
        #pragma unroll
        for (int i = 0; i < 4; i++) {
            int idx = tid + (i << 8);
            int row = idx >> 5, seg = idx & 31;
            size_t go = ((size_t)(k0 + row) * N + n0 + seg * 8) * 2;
            cp16(sb + ST_BHI + row * 528 + seg * 16, Bh + go);
        }
        cp_commit();
    };

    issue(0, 0);
    issue(1, 32);
    for (int c = 0; c < nch; c++) {
        if (c + 2 < nch) issue((c + 2) & (NSTG - 1), (c + 2) << 5);
        else             cp_commit();
        cp_wait<2>();
        __syncthreads();

        const uint32_t sb = smb + (c & (NSTG - 1)) * ST_SZ;
        #pragma unroll
        for (int ks = 0; ks < 2; ks++) {
            uint32_t aH[4][4];
            #pragma unroll
            for (int mf = 0; mf < 4; mf++) {
                uint32_t ao = ((wm * 64 + mf * 16 + aRow) * SAe + ks * 16 + aColH) * 2;
                ldmx4(aH[mf], sb + ST_AHI + ao);
            }
            uint32_t bH[4][4];
            #pragma unroll
            for (int ng = 0; ng < 4; ng++) {
                uint32_t bo = ((ks * 16 + bRow) * SBe + wn * 64 + ng * 16 + bCol) * 2;
                ldmx4t(bH[ng], sb + ST_BHI + bo);
            }
            #pragma unroll
            for (int mf = 0; mf < 4; mf++)
                #pragma unroll
                for (int ng = 0; ng < 4; ng++) {
                    mma16816h(acc[mf][ng*2+0], aH[mf], bH[ng]);
                    mma16816h(acc[mf][ng*2+1], aH[mf], bH[ng] + 2);
                }
        }
    }

    #pragma unroll
    for (int mf = 0; mf < 4; mf++) {
        int row = m0 + wm * 64 + mf * 16 + (lane >> 2);
        #pragma unroll
        for (int nf = 0; nf < 8; nf++) {
            int col = n0 + wn * 64 + nf * 8 + (lane & 3) * 2;
            if (outHalf) {
                *reinterpret_cast<uint32_t*>(Ch + (size_t)row * N + col) =
                    pack_hf2(acc[mf][nf][0], acc[mf][nf][1]);
                *reinterpret_cast<uint32_t*>(Ch + (size_t)(row + 8) * N + col) =
                    pack_hf2(acc[mf][nf][2], acc[mf][nf][3]);
            } else {
                *reinterpret_cast<float2*>(Cf + (size_t)row * N + col) =
                    make_float2(acc[mf][nf][0], acc[mf][nf][1]);
                *reinterpret_cast<float2*>(Cf + (size_t)(row + 8) * N + col) =
                    make_float2(acc[mf][nf][2], acc[mf][nf][3]);
            }
        }
    }
}

// ---------------------------------------------------------------------------
// RoPE fused with fp16 conversion (unchanged)
// ---------------------------------------------------------------------------
__global__ void rope_cvt_kernel(const float* __restrict__ Q, const float* __restrict__ K,
                                const int* __restrict__ pos_ids,
                                __half* __restrict__ Qh, __half* __restrict__ Ql,
                                __half* __restrict__ Kh) {
    int idx = blockIdx.x * blockDim.x + threadIdx.x;
    if (idx >= B_ * S_ * HKV_ * 32) return;
    int d   = idx & 31;
    int h   = (idx >> 5) & (HKV_ - 1);
    int row = idx >> 8;
    float p    = (float)pos_ids[row];
    float invf = powf(10000.0f, -(float)d * (1.0f / 32.0f));
    float a = p * invf;
    float sn, cs;
    sincosf(a, &sn, &cs);
    size_t base = (size_t)row * NQK_ + h * HD_;
    float q0 = Q[base + d], q1 = Q[base + d + 32];
    float qr0 = (q0 * cs - q1 * sn) * 0.125f;
    float qr1 = (q1 * cs + q0 * sn) * 0.125f;
    __half qh0 = __float2half_rn(qr0), qh1 = __float2half_rn(qr1);
    Qh[base + d]      = qh0;
    Qh[base + d + 32] = qh1;
    Ql[base + d]      = __float2half_rn(qr0 - __half2float(qh0));
    Ql[base + d + 32] = __float2half_rn(qr1 - __half2float(qh1));
    float k0 = K[base + d], k1 = K[base + d + 32];
    Kh[base + d]      = __float2half_rn(k0 * cs - k1 * sn);
    Kh[base + d + 32] = __float2half_rn(k1 * cs + k0 * sn);
}

// ===========================================================================
// FA2-style flash attention: Q-tile 128 rows, warp owns 16 rows x all 64 keys.
// In-register softmax (quad shuffles), register P repack, 2 barriers/tile.
// QK 2-term (Qh+Ql)·Kh, PV 1-term. smem ~78 KB, 1 CTA/SM, 8 warps.
// ===========================================================================
#define SK   72
#define SV   264
#define QHI_O 0
#define QLO_O 18432
#define KHI_O 36864
#define VHI_O 46080
#define ATTN_SMEM 79872
#define QT_ROWS 128

__global__ __launch_bounds__(256, 1)
void attn_mma_kernel(const uint4* __restrict__ Qh, const uint4* __restrict__ Ql,
                     const uint4* __restrict__ Kh, const uint4* __restrict__ Vh,
                     float* __restrict__ Out) {
    extern __shared__ char sm[];
    const uint32_t smb = smem_to_u32(sm);
    const int tid = threadIdx.x, lane = tid & 31, wid = tid >> 5;
    const int b  = blockIdx.z;
    const int h  = blockIdx.y;
    const int qt = (S_ / QT_ROWS - 1) - blockIdx.x;   // heavy tiles first
    const int q0 = qt * QT_ROWS;

    // ---- load Q tile (128 rows, hi/lo): 1024 uint4 each, 4/thread ----
    #pragma unroll
    for (int i = 0; i < 4; i++) {
        int idx = tid + (i << 8);
        int r = idx >> 3, c8 = idx & 7;
        size_t gi = (size_t)(b * S_ + q0 + r) * 64 + h * 8 + c8;
        uint32_t off = (r * SK + c8 * 8) * 2;
        *reinterpret_cast<uint4*>(sm + QHI_O + off) = Qh[gi];
        *reinterpret_cast<uint4*>(sm + QLO_O + off) = Ql[gi];
    }

    float acc[32][4];
    #pragma unroll
    for (int i = 0; i < 32; i++)
        #pragma unroll
        for (int t = 0; t < 4; t++) acc[i][t] = 0.f;
    float m0 = -INFINITY, m1 = -INFINITY, l0 = 0.f, l1 = 0.f;

    const int rmin = q0 + wid * 16;        // warp's first global row
    const int rmax = rmin + 15;
    const int r0l  = lane >> 2;            // row within 8-group
    const int cql  = (lane & 3) * 2;       // col pair within 8

    const uint32_t aRow  = lane & 15;
    const uint32_t aColH = (lane >> 4) * 8;
    const uint32_t kbRow = (lane & 7) + ((lane >> 4) & 1) * 8;
    const uint32_t kbCol = ((lane >> 3) & 1) * 8;
    const uint32_t vbRow = (lane & 7) + ((lane >> 3) & 1) * 8;
    const uint32_t vbCol = ((lane >> 4) & 1) * 8;

    const int nkt = 2 * qt + 2;
    for (int kt = 0; kt < nkt; kt++) {
        const int k0 = kt * 64;
        __syncthreads();   // prior-tile K/V consumers done

        // ---- K tile: 512 uint4, 2/thread ----
        #pragma unroll
        for (int i = 0; i < 2; i++) {
            int idx = tid + (i << 8);
            int kk = idx >> 3, c8 = idx & 7;
            size_t gi = (size_t)(b * S_ + k0 + kk) * 64 + h * 8 + c8;
            *reinterpret_cast<uint4*>(sm + KHI_O + (kk * SK + c8 * 8) * 2) = Kh[gi];
        }
        // ---- V tile: 2048 uint4, 8/thread ----
        #pragma unroll
        for (int i = 0; i < 8; i++) {
            int idx = tid + (i << 8);
            int kk = idx >> 5, c8 = idx & 31;
            int g = c8 >> 3, d8 = c8 & 7;
            size_t gi = (size_t)(b * S_ + k0 + kk) * 256 + g * 64 + h * 8 + d8;
            *reinterpret_cast<uint4*>(sm + VHI_O + (kk * SV + c8 * 8) * 2) = Vh[gi];
        }
        __syncthreads();

        if (k0 > rmax) continue;   // fully masked for this warp (barriers stay uniform)

        // ---- QK^T: S(16x64) in registers, 2-term ----
        float sfr[8][4];
        #pragma unroll
        for (int i = 0; i < 8; i++)
            #pragma unroll
            for (int t = 0; t < 4; t++) sfr[i][t] = 0.f;

        #pragma unroll
        for (int ks = 0; ks < 4; ks++) {
            uint32_t aH[4], aL[4];
            uint32_t ao = ((wid * 16 + aRow) * SK + ks * 16 + aColH) * 2;
            ldmx4(aH, smb + QHI_O + ao);
            ldmx4(aL, smb + QLO_O + ao);
            #pragma unroll
            for (int g4 = 0; g4 < 4; g4++) {
                uint32_t bH[4];
                uint32_t bo = ((g4 * 16 + kbRow) * SK + ks * 16 + kbCol) * 2;
                ldmx4(bH, smb + KHI_O + bo);
                mma16816h(sfr[g4*2+0], aH, bH);
                mma16816h(sfr[g4*2+0], aL, bH);
                mma16816h(sfr[g4*2+1], aH, bH + 2);
                mma16816h(sfr[g4*2+1], aL, bH + 2);
            }
        }

        // ---- causal mask (diagonal tiles only; warp-uniform branch) ----
        if (k0 + 63 > rmin) {
            int grow0 = rmin + r0l, grow1 = grow0 + 8;
            #pragma unroll
            for (int nf = 0; nf < 8; nf++) {
                int c = k0 + nf * 8 + cql;
                if (c     > grow0) sfr[nf][0] = -INFINITY;
                if (c + 1 > grow0) sfr[nf][1] = -INFINITY;
                if (c     > grow1) sfr[nf][2] = -INFINITY;
                if (c + 1 > grow1) sfr[nf][3] = -INFINITY;
            }
        }

        // ---- in-register online softmax ----
        float mx0 = -INFINITY, mx1 = -INFINITY;
        #pragma unroll
        for (int nf = 0; nf < 8; nf++) {
            mx0 = fmaxf(mx0, fmaxf(sfr[nf][0], sfr[nf][1]));
            mx1 = fmaxf(mx1, fmaxf(sfr[nf][2], sfr[nf][3]));
        }
        mx0 = fmaxf(mx0, __shfl_xor_sync(0xffffffffu, mx0, 1));
        mx0 = fmaxf(mx0, __shfl_xor_sync(0xffffffffu, mx0, 2));
        mx1 = fmaxf(mx1, __shfl_xor_sync(0xffffffffu, mx1, 1));
        mx1 = fmaxf(mx1, __shfl_xor_sync(0xffffffffu, mx1, 2));
        float mn0 = fmaxf(m0, mx0), mn1 = fmaxf(m1, mx1);
        float sc0 = __expf(m0 - mn0), sc1 = __expf(m1 - mn1);

        float sum0 = 0.f, sum1 = 0.f;
        uint32_t pa[4][4];
        #pragma unroll
        for (int nf = 0; nf < 8; nf++) {
            float p0 = __expf(sfr[nf][0] - mn0);
            float p1 = __expf(sfr[nf][1] - mn0);
            float p2 = __expf(sfr[nf][2] - mn1);
            float p3 = __expf(sfr[nf][3] - mn1);
            sum0 += p0 + p1;
            sum1 += p2 + p3;
            pa[nf >> 1][(nf & 1) * 2 + 0] = pack_hf2(p0, p1);
            pa[nf >> 1][(nf & 1) * 2 + 1] = pack_hf2(p2, p3);
        }
        sum0 += __shfl_xor_sync(0xffffffffu, sum0, 1);
        sum0 += __shfl_xor_sync(0xffffffffu, sum0, 2);
        sum1 += __shfl_xor_sync(0xffffffffu, sum1, 1);
        sum1 += __shfl_xor_sync(0xffffffffu, sum1, 2);
        l0 = l0 * sc0 + sum0;
        l1 = l1 * sc1 + sum1;
        m0 = mn0; m1 = mn1;

        // ---- rescale + PV: acc(16x256) += P(16x64) @ V(64x256) ----
        #pragma unroll
        for (int i = 0; i < 32; i++) {
            acc[i][0] *= sc0; acc[i][1] *= sc0;
            acc[i][2] *= sc1; acc[i][3] *= sc1;
        }
        #pragma unroll
        for (int ks = 0; ks < 4; ks++) {
            #pragma unroll
            for (int g = 0; g < 16; g++) {
                uint32_t vH[4];
                uint32_t bo = ((ks * 16 + vbRow) * SV + g * 16 + vbCol) * 2;
                ldmx4t(vH, smb + VHI_O + bo);
                mma16816h(acc[g*2+0], pa[ks], vH);
                mma16816h(acc[g*2+1], pa[ks], vH + 2);
            }
        }
    }

    // ---- normalize + store ----
    {
        float invl0 = 1.f / l0;
        float invl1 = 1.f / l1;
        int row0 = q0 + wid * 16 + r0l;
        int row1 = row0 + 8;
        #pragma unroll
        for (int nf = 0; nf < 32; nf++) {
            int cl = nf * 8 + cql;           // 0..255
            int g  = cl >> 6, d = cl & 63;
            size_t ob0 = ((size_t)(b * S_ + row0)) * HID_ + (g * HKV_ + h) * HD_ + d;
            size_t ob1 = ((size_t)(b * S_ + row1)) * HID_ + (g * HKV_ + h) * HD_ + d;
            *reinterpret_cast<float2*>(&Out[ob0]) =
                make_float2(acc[nf][0] * invl0, acc[nf][1] * invl0);
            *reinterpret_cast<float2*>(&Out[ob1]) =
                make_float2(acc[nf][2] * invl1, acc[nf][3] * invl1);
        }
    }
}

// ---------------------------------------------------------------------------
extern "C" void kernel_launch(void* const* d_in, const int* in_sizes, int n_in,
                              void* d_out, int out_size) {
    const float* X   = (const float*)d_in[0];
    const int*   pid = (const int*)  d_in[1];
    const float* Wq  = (const float*)d_in[2];
    const float* Wk  = (const float*)d_in[3];
    const float* Wv  = (const float*)d_in[4];
    float* Out = (float*)d_out;

    float *dQ, *dK;
    cudaGetSymbolAddress((void**)&dQ, g_Q);
    cudaGetSymbolAddress((void**)&dK, g_K);
    uint4 *qh, *ql, *kh, *vh;
    cudaGetSymbolAddress((void**)&qh, g_Qh); cudaGetSymbolAddress((void**)&ql, g_Ql);
    cudaGetSymbolAddress((void**)&kh, g_Kh); cudaGetSymbolAddress((void**)&vh, g_Vh);
    uint2 *xh, *wqh, *wkh, *wvh;
    cudaGetSymbolAddress((void**)&xh,  g_Xh);
    cudaGetSymbolAddress((void**)&wqh, g_Wqh);
    cudaGetSymbolAddress((void**)&wkh, g_Wkh);
    cudaGetSymbolAddress((void**)&wvh, g_Wvh);

    // Fused pre-convert
    {
        int nX4 = M_ * HID_ / 4;
        dim3 grd((nX4 + 255) / 256, 4);
        cvt_all_kernel<<<grd, 256>>>((const float4*)X, (const float4*)Wq,
                                     (const float4*)Wk, (const float4*)Wv,
                                     xh, wqh, wkh, wvh);
    }
    // Fused projections
    {
        cudaFuncSetAttribute(gemm_fused_kernel,
                             cudaFuncAttributeMaxDynamicSharedMemorySize, GEMM_SMEM);
        dim3 grd(12, M_ / 128);
        gemm_fused_kernel<<<grd, 256, GEMM_SMEM>>>(
            (const char*)xh, (const char*)wqh, dQ,
            (const char*)wkh, dK, (const char*)wvh, (__half*)vh);
    }
    // RoPE + fp16 conversion
    {
        int total = B_ * S_ * HKV_ * 32;
        rope_cvt_kernel<<<(total + 255) / 256, 256>>>(
            dQ, dK, pid, (__half*)qh, (__half*)ql, (__half*)kh);
    }
    // Attention (FA2-style)
    {
        cudaFuncSetAttribute(attn_mma_kernel,
                             cudaFuncAttributeMaxDynamicSharedMemorySize, ATTN_SMEM);
        dim3 grd(S_ / QT_ROWS, HKV_, B_);
        attn_mma_kernel<<<grd, 256, ATTN_SMEM>>>(qh, ql, kh, vh, Out);
    }
}

// round 13
// speedup vs baseline: 9.4608x; 1.0569x over previous
#include <cuda_runtime.h>
#include <cuda_fp16.h>
#include <math.h>
#include <stdint.h>

#define B_   2
#define S_   2048
#define HID_ 2048
#define NH_  32
#define G_   4
#define HD_  64
#define HKV_ 8
#define NQK_ 512   // HKV_*HD_
#define M_   (B_ * S_)   // 4096

// Scratch (device globals: no allocation allowed)
__device__ float g_Q[(size_t)M_*NQK_];   // fp32 Q (pre-rope)
__device__ float g_K[(size_t)M_*NQK_];   // fp32 K (pre-rope)
// fp16 post-rope / projected tensors
__device__ uint4 g_Qh[(size_t)M_*NQK_/8];
__device__ uint4 g_Kh[(size_t)M_*NQK_/8];
__device__ uint4 g_Vh[(size_t)M_*HID_/8];
// fp16 pre-converted GEMM operands (hi only)
__device__ uint2 g_Xh[(size_t)M_*HID_/4];
__device__ uint2 g_Wqh[(size_t)HID_*NQK_/4];
__device__ uint2 g_Wkh[(size_t)HID_*NQK_/4];
__device__ uint2 g_Wvh[(size_t)HID_*HID_/4];

// ===========================================================================
// helpers
// ===========================================================================
__device__ __forceinline__ uint32_t smem_to_u32(const void* smem_ptr) {
    uint32_t addr;
    asm("{ .reg .u64 tmp; cvta.to.shared.u64 tmp, %1; cvt.u32.u64 %0, tmp; }"
        : "=r"(addr) : "l"(smem_ptr));
    return addr;
}
__device__ __forceinline__ uint32_t pack_hf2(float a, float b) {
    uint32_t r;
    asm("cvt.rn.f16x2.f32 %0, %1, %2;" : "=r"(r) : "f"(b), "f"(a));
    return r;
}
__device__ __forceinline__ void ldmx4(uint32_t r[4], uint32_t addr) {
    asm volatile("ldmatrix.sync.aligned.m8n8.x4.shared.b16 {%0,%1,%2,%3}, [%4];"
        : "=r"(r[0]), "=r"(r[1]), "=r"(r[2]), "=r"(r[3]) : "r"(addr));
}
__device__ __forceinline__ void ldmx4t(uint32_t r[4], uint32_t addr) {
    asm volatile("ldmatrix.sync.aligned.m8n8.x4.trans.shared.b16 {%0,%1,%2,%3}, [%4];"
        : "=r"(r[0]), "=r"(r[1]), "=r"(r[2]), "=r"(r[3]) : "r"(addr));
}
__device__ __forceinline__ void mma16816h(float d[4], const uint32_t a[4],
                                          const uint32_t b[2]) {
    asm volatile(
        "mma.sync.aligned.m16n8k16.row.col.f32.f16.f16.f32 "
        "{%0,%1,%2,%3}, {%4,%5,%6,%7}, {%8,%9}, {%0,%1,%2,%3};"
        : "+f"(d[0]), "+f"(d[1]), "+f"(d[2]), "+f"(d[3])
        : "r"(a[0]), "r"(a[1]), "r"(a[2]), "r"(a[3]), "r"(b[0]), "r"(b[1]));
}
__device__ __forceinline__ void cp16(uint32_t dst, const void* src) {
    asm volatile("cp.async.cg.shared.global [%0], [%1], 16;"
                 :: "r"(dst), "l"(src));
}
__device__ __forceinline__ void cp_commit() {
    asm volatile("cp.async.commit_group;" ::: "memory");
}
template <int N>
__device__ __forceinline__ void cp_wait() {
    asm volatile("cp.async.wait_group %0;" :: "n"(N) : "memory");
}

// ===========================================================================
// Fused pre-convert fp32 -> fp16 (X, Wq, Wk, Wv in one launch)
// ===========================================================================
__global__ void cvt_all_kernel(const float4* __restrict__ X,
                               const float4* __restrict__ Wq,
                               const float4* __restrict__ Wk,
                               const float4* __restrict__ Wv,
                               uint2* __restrict__ xh, uint2* __restrict__ wqh,
                               uint2* __restrict__ wkh, uint2* __restrict__ wvh) {
    const float4* src;
    uint2* dst;
    int n4;
    switch (blockIdx.y) {
        case 0: src = X;  dst = xh;  n4 = M_ * HID_ / 4;   break;
        case 1: src = Wq; dst = wqh; n4 = HID_ * NQK_ / 4; break;
        case 2: src = Wk; dst = wkh; n4 = HID_ * NQK_ / 4; break;
        default: src = Wv; dst = wvh; n4 = HID_ * HID_ / 4; break;
    }
    int i = blockIdx.x * blockDim.x + threadIdx.x;
    if (i >= n4) return;
    float4 v = src[i];
    dst[i] = make_uint2(pack_hf2(v.x, v.y), pack_hf2(v.z, v.w));
}

// ===========================================================================
// Fused 1-term fp16 GEMM for all three projections (unchanged)
// ===========================================================================
#define SAe 40
#define SBe 264
#define ST_AHI 0
#define ST_BHI 10240
#define ST_SZ  27136
#define NSTG 4
#define GEMM_SMEM (NSTG * ST_SZ)

__global__ __launch_bounds__(256, 1)
void gemm_fused_kernel(const char* __restrict__ Ah,
                       const char* __restrict__ BhQ, float* __restrict__ CQ,
                       const char* __restrict__ BhK, float* __restrict__ CK,
                       const char* __restrict__ BhV, __half* __restrict__ CV) {
    extern __shared__ char sm[];
    const uint32_t smb = smem_to_u32(sm);
    const int tid = threadIdx.x, lane = tid & 31, wid = tid >> 5;
    const int wm = wid >> 2, wn = wid & 3;
    const int m0 = blockIdx.y * 128;
    const int nb = blockIdx.x;

    const char* Bh;
    float* Cf = nullptr;
    __half* Ch = nullptr;
    int N, n0;
    bool outHalf;
    if (nb < 2)      { Bh = BhQ; Cf = CQ; N = NQK_; n0 = nb * 256;       outHalf = false; }
    else if (nb < 4) { Bh = BhK; Cf = CK; N = NQK_; n0 = (nb - 2) * 256; outHalf = false; }
    else             { Bh = BhV; Ch = CV; N = HID_; n0 = (nb - 4) * 256; outHalf = true; }
    const int K = HID_;

    float acc[4][8][4];
    #pragma unroll
    for (int i = 0; i < 4; i++)
        #pragma unroll
        for (int j = 0; j < 8; j++)
            #pragma unroll
            for (int t = 0; t < 4; t++) acc[i][j][t] = 0.f;

    const uint32_t aRow  = lane & 15;
    const uint32_t aColH = (lane >> 4) * 8;
    const uint32_t bRow  = (lane & 7) + ((lane >> 3) & 1) * 8;
    const uint32_t bCol  = ((lane >> 4) & 1) * 8;
    const int nch = K >> 5;

    auto issue = [&](int s, int k0) {
        uint32_t sb = smb + s * ST_SZ;
        #pragma unroll
        for (int i = 0; i < 2; i++) {
            int idx = tid + (i << 8);
            int row = idx >> 2, seg = idx & 3;
            size_t go = ((size_t)(m0 + row) * K + k0 + seg * 8) * 2;
            cp16(sb + ST_AHI + row * 80 + seg * 16, Ah + go);
        }
        #pragma unroll
        for (int i = 0; i < 4; i++) {
            int idx = tid + (i << 8);
            int row = idx >> 5, seg = idx & 31;
            size_t go = ((size_t)(k0 + row) * N + n0 + seg * 8) * 2;
            cp16(sb + ST_BHI + row * 528 + seg * 16, Bh + go);
        }
        cp_commit();
    };

    issue(0, 0);
    issue(1, 32);
    for (int c = 0; c < nch; c++) {
        if (c + 2 < nch) issue((c + 2) & (NSTG - 1), (c + 2) << 5);
        else             cp_commit();
        cp_wait<2>();
        __syncthreads();

        const uint32_t sb = smb + (c & (NSTG - 1)) * ST_SZ;
        #pragma unroll
        for (int ks = 0; ks < 2; ks++) {
            uint32_t aH[4][4];
            #pragma unroll
            for (int mf = 0; mf < 4; mf++) {
                uint32_t ao = ((wm * 64 + mf * 16 + aRow) * SAe + ks * 16 + aColH) * 2;
                ldmx4(aH[mf], sb + ST_AHI + ao);
            }
            uint32_t bH[4][4];
            #pragma unroll
            for (int ng = 0; ng < 4; ng++) {
                uint32_t bo = ((ks * 16 + bRow) * SBe + wn * 64 + ng * 16 + bCol) * 2;
                ldmx4t(bH[ng], sb + ST_BHI + bo);
            }
            #pragma unroll
            for (int mf = 0; mf < 4; mf++)
                #pragma unroll
                for (int ng = 0; ng < 4; ng++) {
                    mma16816h(acc[mf][ng*2+0], aH[mf], bH[ng]);
                    mma16816h(acc[mf][ng*2+1], aH[mf], bH[ng] + 2);
                }
        }
    }

    #pragma unroll
    for (int mf = 0; mf < 4; mf++) {
        int row = m0 + wm * 64 + mf * 16 + (lane >> 2);
        #pragma unroll
        for (int nf = 0; nf < 8; nf++) {
            int col = n0 + wn * 64 + nf * 8 + (lane & 3) * 2;
            if (outHalf) {
                *reinterpret_cast<uint32_t*>(Ch + (size_t)row * N + col) =
                    pack_hf2(acc[mf][nf][0], acc[mf][nf][1]);
                *reinterpret_cast<uint32_t*>(Ch + (size_t)(row + 8) * N + col) =
                    pack_hf2(acc[mf][nf][2], acc[mf][nf][3]);
            } else {
                *reinterpret_cast<float2*>(Cf + (size_t)row * N + col) =
                    make_float2(acc[mf][nf][0], acc[mf][nf][1]);
                *reinterpret_cast<float2*>(Cf + (size_t)(row + 8) * N + col) =
                    make_float2(acc[mf][nf][2], acc[mf][nf][3]);
            }
        }
    }
}

// ---------------------------------------------------------------------------
// RoPE fused with fp16 conversion (Q-lo no longer needed)
// ---------------------------------------------------------------------------
__global__ void rope_cvt_kernel(const float* __restrict__ Q, const float* __restrict__ K,
                                const int* __restrict__ pos_ids,
                                __half* __restrict__ Qh, __half* __restrict__ Kh) {
    int idx = blockIdx.x * blockDim.x + threadIdx.x;
    if (idx >= B_ * S_ * HKV_ * 32) return;
    int d   = idx & 31;
    int h   = (idx >> 5) & (HKV_ - 1);
    int row = idx >> 8;
    float p    = (float)pos_ids[row];
    float invf = powf(10000.0f, -(float)d * (1.0f / 32.0f));
    float a = p * invf;
    float sn, cs;
    sincosf(a, &sn, &cs);
    size_t base = (size_t)row * NQK_ + h * HD_;
    float q0 = Q[base + d], q1 = Q[base + d + 32];
    Qh[base + d]      = __float2half_rn((q0 * cs - q1 * sn) * 0.125f);
    Qh[base + d + 32] = __float2half_rn((q1 * cs + q0 * sn) * 0.125f);
    float k0 = K[base + d], k1 = K[base + d + 32];
    Kh[base + d]      = __float2half_rn(k0 * cs - k1 * sn);
    Kh[base + d + 32] = __float2half_rn(k1 * cs + k0 * sn);
}

// ===========================================================================
// FA2-style flash attention, 1-term QK + 1-term PV, cp.async K/V pipeline.
// Q-tile 128 rows, warp owns 16 rows x all 64 keys. smem ~102 KB, 1 CTA/SM.
// ===========================================================================
#define SK   72
#define SV   264
#define QHI_O 0
#define KST_SZ 9216
#define VST_SZ 33792
#define KHI_O 18432
#define VHI_O (18432 + 2 * KST_SZ)               // 36864
#define ATTN_SMEM (VHI_O + 2 * VST_SZ)           // 104448
#define QT_ROWS 128

__global__ __launch_bounds__(256, 1)
void attn_mma_kernel(const uint4* __restrict__ Qh,
                     const uint4* __restrict__ Kh, const uint4* __restrict__ Vh,
                     float* __restrict__ Out) {
    extern __shared__ char sm[];
    const uint32_t smb = smem_to_u32(sm);
    const int tid = threadIdx.x, lane = tid & 31, wid = tid >> 5;
    const int b  = blockIdx.z;
    const int h  = blockIdx.y;
    const int qt = (S_ / QT_ROWS - 1) - blockIdx.x;   // heavy tiles first
    const int q0 = qt * QT_ROWS;

    // ---- load Q tile (128 rows): 1024 uint4, 4/thread ----
    #pragma unroll
    for (int i = 0; i < 4; i++) {
        int idx = tid + (i << 8);
        int r = idx >> 3, c8 = idx & 7;
        size_t gi = (size_t)(b * S_ + q0 + r) * 64 + h * 8 + c8;
        *reinterpret_cast<uint4*>(sm + QHI_O + (r * SK + c8 * 8) * 2) = Qh[gi];
    }

    float acc[32][4];
    #pragma unroll
    for (int i = 0; i < 32; i++)
        #pragma unroll
        for (int t = 0; t < 4; t++) acc[i][t] = 0.f;
    float m0 = -INFINITY, m1 = -INFINITY, l0 = 0.f, l1 = 0.f;

    const int rmin = q0 + wid * 16;
    const int rmax = rmin + 15;
    const int r0l  = lane >> 2;
    const int cql  = (lane & 3) * 2;

    const uint32_t aRow  = lane & 15;
    const uint32_t aColH = (lane >> 4) * 8;
    const uint32_t kbRow = (lane & 7) + ((lane >> 4) & 1) * 8;
    const uint32_t kbCol = ((lane >> 3) & 1) * 8;
    const uint32_t vbRow = (lane & 7) + ((lane >> 3) & 1) * 8;
    const uint32_t vbCol = ((lane >> 4) & 1) * 8;

    const int nkt = 2 * qt + 2;

    // cp.async K/V stage issue
    auto issueKV = [&](int kt) {
        const int s  = kt & 1;
        const int k0 = kt * 64;
        const uint32_t kb = smb + KHI_O + s * KST_SZ;
        const uint32_t vb = smb + VHI_O + s * VST_SZ;
        #pragma unroll
        for (int i = 0; i < 2; i++) {
            int idx = tid + (i << 8);
            int kk = idx >> 3, c8 = idx & 7;
            size_t gi = (size_t)(b * S_ + k0 + kk) * 64 + h * 8 + c8;
            cp16(kb + (kk * SK + c8 * 8) * 2, Kh + gi);
        }
        #pragma unroll
        for (int i = 0; i < 8; i++) {
            int idx = tid + (i << 8);
            int kk = idx >> 5, c8 = idx & 31;
            int g = c8 >> 3, d8 = c8 & 7;
            size_t gi = (size_t)(b * S_ + k0 + kk) * 256 + g * 64 + h * 8 + d8;
            cp16(vb + (kk * SV + c8 * 8) * 2, Vh + gi);
        }
        cp_commit();
    };

    issueKV(0);
    for (int kt = 0; kt < nkt; kt++) {
        const int k0 = kt * 64;
        __syncthreads();   // all warps done with buffer (kt+1)&1 (last read at kt-1)
        if (kt + 1 < nkt) issueKV(kt + 1);
        else              cp_commit();
        cp_wait<1>();      // tile kt's group complete (kt+1 stays in flight)
        __syncthreads();   // cross-thread visibility of tile kt's K/V

        if (k0 > rmax) continue;   // fully masked for this warp

        const uint32_t kb = smb + KHI_O + (kt & 1) * KST_SZ;
        const uint32_t vb = smb + VHI_O + (kt & 1) * VST_SZ;

        // ---- QK^T: S(16x64) in registers, 1-term ----
        float sfr[8][4];
        #pragma unroll
        for (int i = 0; i < 8; i++)
            #pragma unroll
            for (int t = 0; t < 4; t++) sfr[i][t] = 0.f;

        #pragma unroll
        for (int ks = 0; ks < 4; ks++) {
            uint32_t aH[4];
            uint32_t ao = ((wid * 16 + aRow) * SK + ks * 16 + aColH) * 2;
            ldmx4(aH, smb + QHI_O + ao);
            #pragma unroll
            for (int g4 = 0; g4 < 4; g4++) {
                uint32_t bH[4];
                uint32_t bo = ((g4 * 16 + kbRow) * SK + ks * 16 + kbCol) * 2;
                ldmx4(bH, kb + bo);
                mma16816h(sfr[g4*2+0], aH, bH);
                mma16816h(sfr[g4*2+1], aH, bH + 2);
            }
        }

        // ---- causal mask (diagonal tiles only) ----
        if (k0 + 63 > rmin) {
            int grow0 = rmin + r0l, grow1 = grow0 + 8;
            #pragma unroll
            for (int nf = 0; nf < 8; nf++) {
                int c = k0 + nf * 8 + cql;
                if (c     > grow0) sfr[nf][0] = -INFINITY;
                if (c + 1 > grow0) sfr[nf][1] = -INFINITY;
                if (c     > grow1) sfr[nf][2] = -INFINITY;
                if (c + 1 > grow1) sfr[nf][3] = -INFINITY;
            }
        }

        // ---- in-register online softmax ----
        float mx0 = -INFINITY, mx1 = -INFINITY;
        #pragma unroll
        for (int nf = 0; nf < 8; nf++) {
            mx0 = fmaxf(mx0, fmaxf(sfr[nf][0], sfr[nf][1]));
            mx1 = fmaxf(mx1, fmaxf(sfr[nf][2], sfr[nf][3]));
        }
        mx0 = fmaxf(mx0, __shfl_xor_sync(0xffffffffu, mx0, 1));
        mx0 = fmaxf(mx0, __shfl_xor_sync(0xffffffffu, mx0, 2));
        mx1 = fmaxf(mx1, __shfl_xor_sync(0xffffffffu, mx1, 1));
        mx1 = fmaxf(mx1, __shfl_xor_sync(0xffffffffu, mx1, 2));
        float mn0 = fmaxf(m0, mx0), mn1 = fmaxf(m1, mx1);
        float sc0 = __expf(m0 - mn0), sc1 = __expf(m1 - mn1);

        float sum0 = 0.f, sum1 = 0.f;
        uint32_t pa[4][4];
        #pragma unroll
        for (int nf = 0; nf < 8; nf++) {
            float p0 = __expf(sfr[nf][0] - mn0);
            float p1 = __expf(sfr[nf][1] - mn0);
            float p2 = __expf(sfr[nf][2] - mn1);
            float p3 = __expf(sfr[nf][3] - mn1);
            sum0 += p0 + p1;
            sum1 += p2 + p3;
            pa[nf >> 1][(nf & 1) * 2 + 0] = pack_hf2(p0, p1);
            pa[nf >> 1][(nf & 1) * 2 + 1] = pack_hf2(p2, p3);
        }
        sum0 += __shfl_xor_sync(0xffffffffu, sum0, 1);
        sum0 += __shfl_xor_sync(0xffffffffu, sum0, 2);
        sum1 += __shfl_xor_sync(0xffffffffu, sum1, 1);
        sum1 += __shfl_xor_sync(0xffffffffu, sum1, 2);
        l0 = l0 * sc0 + sum0;
        l1 = l1 * sc1 + sum1;
        m0 = mn0; m1 = mn1;

        // ---- rescale + PV ----
        #pragma unroll
        for (int i = 0; i < 32; i++) {
            acc[i][0] *= sc0; acc[i][1] *= sc0;
            acc[i][2] *= sc1; acc[i][3] *= sc1;
        }
        #pragma unroll
        for (int ks = 0; ks < 4; ks++) {
            #pragma unroll
            for (int g = 0; g < 16; g++) {
                uint32_t vH[4];
                uint32_t bo = ((ks * 16 + vbRow) * SV + g * 16 + vbCol) * 2;
                ldmx4t(vH, vb + bo);
                mma16816h(acc[g*2+0], pa[ks], vH);
                mma16816h(acc[g*2+1], pa[ks], vH + 2);
            }
        }
    }

    // ---- normalize + store ----
    {
        float invl0 = 1.f / l0;
        float invl1 = 1.f / l1;
        int row0 = q0 + wid * 16 + r0l;
        int row1 = row0 + 8;
        #pragma unroll
        for (int nf = 0; nf < 32; nf++) {
            int cl = nf * 8 + cql;
            int g  = cl >> 6, d = cl & 63;
            size_t ob0 = ((size_t)(b * S_ + row0)) * HID_ + (g * HKV_ + h) * HD_ + d;
            size_t ob1 = ((size_t)(b * S_ + row1)) * HID_ + (g * HKV_ + h) * HD_ + d;
            *reinterpret_cast<float2*>(&Out[ob0]) =
                make_float2(acc[nf][0] * invl0, acc[nf][1] * invl0);
            *reinterpret_cast<float2*>(&Out[ob1]) =
                make_float2(acc[nf][2] * invl1, acc[nf][3] * invl1);
        }
    }
}

// ---------------------------------------------------------------------------
extern "C" void kernel_launch(void* const* d_in, const int* in_sizes, int n_in,
                              void* d_out, int out_size) {
    const float* X   = (const float*)d_in[0];
    const int*   pid = (const int*)  d_in[1];
    const float* Wq  = (const float*)d_in[2];
    const float* Wk  = (const float*)d_in[3];
    const float* Wv  = (const float*)d_in[4];
    float* Out = (float*)d_out;

    float *dQ, *dK;
    cudaGetSymbolAddress((void**)&dQ, g_Q);
    cudaGetSymbolAddress((void**)&dK, g_K);
    uint4 *qh, *kh, *vh;
    cudaGetSymbolAddress((void**)&qh, g_Qh);
    cudaGetSymbolAddress((void**)&kh, g_Kh);
    cudaGetSymbolAddress((void**)&vh, g_Vh);
    uint2 *xh, *wqh, *wkh, *wvh;
    cudaGetSymbolAddress((void**)&xh,  g_Xh);
    cudaGetSymbolAddress((void**)&wqh, g_Wqh);
    cudaGetSymbolAddress((void**)&wkh, g_Wkh);
    cudaGetSymbolAddress((void**)&wvh, g_Wvh);

    // Fused pre-convert
    {
        int nX4 = M_ * HID_ / 4;
        dim3 grd((nX4 + 255) / 256, 4);
        cvt_all_kernel<<<grd, 256>>>((const float4*)X, (const float4*)Wq,
                                     (const float4*)Wk, (const float4*)Wv,
                                     xh, wqh, wkh, wvh);
    }
    // Fused projections
    {
        cudaFuncSetAttribute(gemm_fused_kernel,
                             cudaFuncAttributeMaxDynamicSharedMemorySize, GEMM_SMEM);
        dim3 grd(12, M_ / 128);
        gemm_fused_kernel<<<grd, 256, GEMM_SMEM>>>(
            (const char*)xh, (const char*)wqh, dQ,
            (const char*)wkh, dK, (const char*)wvh, (__half*)vh);
    }
    // RoPE + fp16 conversion
    {
        int total = B_ * S_ * HKV_ * 32;
        rope_cvt_kernel<<<(total + 255) / 256, 256>>>(
            dQ, dK, pid, (__half*)qh, (__half*)kh);
    }
    // Attention (FA2-style, pipelined K/V)
    {
        cudaFuncSetAttribute(attn_mma_kernel,
                             cudaFuncAttributeMaxDynamicSharedMemorySize, ATTN_SMEM);
        dim3 grd(S_ / QT_ROWS, HKV_, B_);
        attn_mma_kernel<<<grd, 256, ATTN_SMEM>>>(qh, kh, vh, Out);
    }
}

// round 14
// speedup vs baseline: 10.1823x; 1.0763x over previous
#include <cuda_runtime.h>
#include <cuda_fp16.h>
#include <math.h>
#include <stdint.h>

#define B_   2
#define S_   2048
#define HID_ 2048
#define NH_  32
#define G_   4
#define HD_  64
#define HKV_ 8
#define NQK_ 512   // HKV_*HD_
#define M_   (B_ * S_)   // 4096

// fp16 post-rope / projected tensors
__device__ uint4 g_Qh[(size_t)M_*NQK_/8];
__device__ uint4 g_Kh[(size_t)M_*NQK_/8];
__device__ uint4 g_Vh[(size_t)M_*HID_/8];
// fp16 pre-converted GEMM operands
__device__ uint2 g_Xh[(size_t)M_*HID_/4];
__device__ uint2 g_Wqh[(size_t)HID_*NQK_/4];
__device__ uint2 g_Wkh[(size_t)HID_*NQK_/4];
__device__ uint2 g_Wvh[(size_t)HID_*HID_/4];

// ===========================================================================
// helpers
// ===========================================================================
__device__ __forceinline__ uint32_t smem_to_u32(const void* smem_ptr) {
    uint32_t addr;
    asm("{ .reg .u64 tmp; cvta.to.shared.u64 tmp, %1; cvt.u32.u64 %0, tmp; }"
        : "=r"(addr) : "l"(smem_ptr));
    return addr;
}
__device__ __forceinline__ uint32_t pack_hf2(float a, float b) {
    uint32_t r;
    asm("cvt.rn.f16x2.f32 %0, %1, %2;" : "=r"(r) : "f"(b), "f"(a));
    return r;
}
__device__ __forceinline__ void ldmx4(uint32_t r[4], uint32_t addr) {
    asm volatile("ldmatrix.sync.aligned.m8n8.x4.shared.b16 {%0,%1,%2,%3}, [%4];"
        : "=r"(r[0]), "=r"(r[1]), "=r"(r[2]), "=r"(r[3]) : "r"(addr));
}
__device__ __forceinline__ void ldmx4t(uint32_t r[4], uint32_t addr) {
    asm volatile("ldmatrix.sync.aligned.m8n8.x4.trans.shared.b16 {%0,%1,%2,%3}, [%4];"
        : "=r"(r[0]), "=r"(r[1]), "=r"(r[2]), "=r"(r[3]) : "r"(addr));
}
__device__ __forceinline__ void mma16816h(float d[4], const uint32_t a[4],
                                          const uint32_t b[2]) {
    asm volatile(
        "mma.sync.aligned.m16n8k16.row.col.f32.f16.f16.f32 "
        "{%0,%1,%2,%3}, {%4,%5,%6,%7}, {%8,%9}, {%0,%1,%2,%3};"
        : "+f"(d[0]), "+f"(d[1]), "+f"(d[2]), "+f"(d[3])
        : "r"(a[0]), "r"(a[1]), "r"(a[2]), "r"(a[3]), "r"(b[0]), "r"(b[1]));
}
__device__ __forceinline__ void cp16(uint32_t dst, const void* src) {
    asm volatile("cp.async.cg.shared.global [%0], [%1], 16;"
                 :: "r"(dst), "l"(src));
}
__device__ __forceinline__ void cp_commit() {
    asm volatile("cp.async.commit_group;" ::: "memory");
}
template <int N>
__device__ __forceinline__ void cp_wait() {
    asm volatile("cp.async.wait_group %0;" :: "n"(N) : "memory");
}

// ===========================================================================
// Fused pre-convert fp32 -> fp16 (X, Wq, Wk, Wv in one launch)
// ===========================================================================
__global__ void cvt_all_kernel(const float4* __restrict__ X,
                               const float4* __restrict__ Wq,
                               const float4* __restrict__ Wk,
                               const float4* __restrict__ Wv,
                               uint2* __restrict__ xh, uint2* __restrict__ wqh,
                               uint2* __restrict__ wkh, uint2* __restrict__ wvh) {
    const float4* src;
    uint2* dst;
    int n4;
    switch (blockIdx.y) {
        case 0: src = X;  dst = xh;  n4 = M_ * HID_ / 4;   break;
        case 1: src = Wq; dst = wqh; n4 = HID_ * NQK_ / 4; break;
        case 2: src = Wk; dst = wkh; n4 = HID_ * NQK_ / 4; break;
        default: src = Wv; dst = wvh; n4 = HID_ * HID_ / 4; break;
    }
    int i = blockIdx.x * blockDim.x + threadIdx.x;
    if (i >= n4) return;
    float4 v = src[i];
    dst[i] = make_uint2(pack_hf2(v.x, v.y), pack_hf2(v.z, v.w));
}

// ===========================================================================
// Fused 1-term fp16 GEMM for all three projections + in-epilogue RoPE for Q/K.
// blockIdx.x: 0-1 -> Q (rope+scale, fp16 Qh out), 2-3 -> K (rope, fp16 Kh out),
//             4-11 -> V (plain fp16 out)
// ===========================================================================
#define SAe 40
#define SBe 264
#define ST_AHI 0
#define ST_BHI 10240
#define ST_SZ  27136
#define NSTG 4
#define GEMM_SMEM (NSTG * ST_SZ)

__global__ __launch_bounds__(256, 1)
void gemm_fused_kernel(const char* __restrict__ Ah,
                       const char* __restrict__ BhQ, __half* __restrict__ CQ,
                       const char* __restrict__ BhK, __half* __restrict__ CK,
                       const char* __restrict__ BhV, __half* __restrict__ CV,
                       const int* __restrict__ pid) {
    extern __shared__ char sm[];
    const uint32_t smb = smem_to_u32(sm);
    const int tid = threadIdx.x, lane = tid & 31, wid = tid >> 5;
    const int wm = wid >> 2, wn = wid & 3;
    const int m0 = blockIdx.y * 128;
    const int nb = blockIdx.x;

    const char* Bh;
    __half* C;
    int N, n0;
    if (nb < 2)      { Bh = BhQ; C = CQ; N = NQK_; n0 = nb * 256; }
    else if (nb < 4) { Bh = BhK; C = CK; N = NQK_; n0 = (nb - 2) * 256; }
    else             { Bh = BhV; C = CV; N = HID_; n0 = (nb - 4) * 256; }
    const int K = HID_;

    float acc[4][8][4];
    #pragma unroll
    for (int i = 0; i < 4; i++)
        #pragma unroll
        for (int j = 0; j < 8; j++)
            #pragma unroll
            for (int t = 0; t < 4; t++) acc[i][j][t] = 0.f;

    const uint32_t aRow  = lane & 15;
    const uint32_t aColH = (lane >> 4) * 8;
    const uint32_t bRow  = (lane & 7) + ((lane >> 3) & 1) * 8;
    const uint32_t bCol  = ((lane >> 4) & 1) * 8;
    const int nch = K >> 5;

    auto issue = [&](int s, int k0) {
        uint32_t sb = smb + s * ST_SZ;
        #pragma unroll
        for (int i = 0; i < 2; i++) {
            int idx = tid + (i << 8);
            int row = idx >> 2, seg = idx & 3;
            size_t go = ((size_t)(m0 + row) * K + k0 + seg * 8) * 2;
            cp16(sb + ST_AHI + row * 80 + seg * 16, Ah + go);
        }
        #pragma unroll
        for (int i = 0; i < 4; i++) {
            int idx = tid + (i << 8);
            int row = idx >> 5, seg = idx & 31;
            size_t go = ((size_t)(k0 + row) * N + n0 + seg * 8) * 2;
            cp16(sb + ST_BHI + row * 528 + seg * 16, Bh + go);
        }
        cp_commit();
    };

    issue(0, 0);
    issue(1, 32);
    for (int c = 0; c < nch; c++) {
        if (c + 2 < nch) issue((c + 2) & (NSTG - 1), (c + 2) << 5);
        else             cp_commit();
        cp_wait<2>();
        __syncthreads();

        const uint32_t sb = smb + (c & (NSTG - 1)) * ST_SZ;
        #pragma unroll
        for (int ks = 0; ks < 2; ks++) {
            uint32_t aH[4][4];
            #pragma unroll
            for (int mf = 0; mf < 4; mf++) {
                uint32_t ao = ((wm * 64 + mf * 16 + aRow) * SAe + ks * 16 + aColH) * 2;
                ldmx4(aH[mf], sb + ST_AHI + ao);
            }
            uint32_t bH[4][4];
            #pragma unroll
            for (int ng = 0; ng < 4; ng++) {
                uint32_t bo = ((ks * 16 + bRow) * SBe + wn * 64 + ng * 16 + bCol) * 2;
                ldmx4t(bH[ng], sb + ST_BHI + bo);
            }
            #pragma unroll
            for (int mf = 0; mf < 4; mf++)
                #pragma unroll
                for (int ng = 0; ng < 4; ng++) {
                    mma16816h(acc[mf][ng*2+0], aH[mf], bH[ng]);
                    mma16816h(acc[mf][ng*2+1], aH[mf], bH[ng] + 2);
                }
        }
    }

    if (nb >= 4) {
        // V: plain fp16 store
        #pragma unroll
        for (int mf = 0; mf < 4; mf++) {
            int row = m0 + wm * 64 + mf * 16 + (lane >> 2);
            #pragma unroll
            for (int nf = 0; nf < 8; nf++) {
                int col = n0 + wn * 64 + nf * 8 + (lane & 3) * 2;
                *reinterpret_cast<uint32_t*>(C + (size_t)row * N + col) =
                    pack_hf2(acc[mf][nf][0], acc[mf][nf][1]);
                *reinterpret_cast<uint32_t*>(C + (size_t)(row + 8) * N + col) =
                    pack_hf2(acc[mf][nf][2], acc[mf][nf][3]);
            }
        }
    } else {
        // Q/K: in-register RoPE, then fp16 store.
        // Warp n-tile (64 wide) == one head; partners (d, d+32) are
        // acc[mf][nf] and acc[mf][nf+4] of the SAME thread.
        const float qscale = (nb < 2) ? 0.125f : 1.0f;
        // invf per (nf, sub-col): d = nf*8 + (lane&3)*2 (+0/+1), all < 32
        float inv0[4], inv1[4];
        #pragma unroll
        for (int nf = 0; nf < 4; nf++) {
            int d = nf * 8 + (lane & 3) * 2;
            inv0[nf] = powf(10000.0f, -(float)d       * (1.0f / 32.0f));
            inv1[nf] = powf(10000.0f, -(float)(d + 1) * (1.0f / 32.0f));
        }
        #pragma unroll
        for (int mf = 0; mf < 4; mf++) {
            int row = m0 + wm * 64 + mf * 16 + (lane >> 2);
            float pos0 = (float)pid[row];
            float pos1 = (float)pid[row + 8];
            #pragma unroll
            for (int nf = 0; nf < 4; nf++) {
                int col = n0 + wn * 64 + nf * 8 + (lane & 3) * 2;
                float s00, c00, s01, c01, s10, c10, s11, c11;
                sincosf(pos0 * inv0[nf], &s00, &c00);
                sincosf(pos0 * inv1[nf], &s01, &c01);
                sincosf(pos1 * inv0[nf], &s10, &c10);
                sincosf(pos1 * inv1[nf], &s11, &c11);
                float x0a = acc[mf][nf][0],   x0b = acc[mf][nf][1];
                float x1a = acc[mf][nf][2],   x1b = acc[mf][nf][3];
                float y0a = acc[mf][nf+4][0], y0b = acc[mf][nf+4][1];
                float y1a = acc[mf][nf+4][2], y1b = acc[mf][nf+4][3];
                float r0a = (x0a * c00 - y0a * s00) * qscale;
                float r0b = (x0b * c01 - y0b * s01) * qscale;
                float u0a = (y0a * c00 + x0a * s00) * qscale;
                float u0b = (y0b * c01 + x0b * s01) * qscale;
                float r1a = (x1a * c10 - y1a * s10) * qscale;
                float r1b = (x1b * c11 - y1b * s11) * qscale;
                float u1a = (y1a * c10 + x1a * s10) * qscale;
                float u1b = (y1b * c11 + x1b * s11) * qscale;
                __half* Cr0 = C + (size_t)row * N;
                __half* Cr1 = C + (size_t)(row + 8) * N;
                *reinterpret_cast<uint32_t*>(Cr0 + col)      = pack_hf2(r0a, r0b);
                *reinterpret_cast<uint32_t*>(Cr0 + col + 32) = pack_hf2(u0a, u0b);
                *reinterpret_cast<uint32_t*>(Cr1 + col)      = pack_hf2(r1a, r1b);
                *reinterpret_cast<uint32_t*>(Cr1 + col + 32) = pack_hf2(u1a, u1b);
            }
        }
    }
}

// ===========================================================================
// FA2-style flash attention, paired scheduling: each CTA does qt=15-bx then
// qt=bx (constant 34 tile-units per CTA, single balanced wave of 128 CTAs).
// 1-term QK + 1-term PV, cp.async K/V double buffer. smem ~102 KB, 1 CTA/SM.
// ===========================================================================
#define SK   72
#define SV   264
#define QHI_O 0
#define KST_SZ 9216
#define VST_SZ 33792
#define KHI_O 18432
#define VHI_O (18432 + 2 * KST_SZ)               // 36864
#define ATTN_SMEM (VHI_O + 2 * VST_SZ)           // 104448
#define QT_ROWS 128
#define NQT (S_ / QT_ROWS)                       // 16

__global__ __launch_bounds__(256, 1)
void attn_mma_kernel(const uint4* __restrict__ Qh,
                     const uint4* __restrict__ Kh, const uint4* __restrict__ Vh,
                     float* __restrict__ Out) {
    extern __shared__ char sm[];
    const uint32_t smb = smem_to_u32(sm);
    const int tid = threadIdx.x, lane = tid & 31, wid = tid >> 5;
    const int b  = blockIdx.z;
    const int h  = blockIdx.y;
    const int bx = blockIdx.x;   // 0..7

    const int r0l = lane >> 2;
    const int cql = (lane & 3) * 2;
    const uint32_t aRow  = lane & 15;
    const uint32_t aColH = (lane >> 4) * 8;
    const uint32_t kbRow = (lane & 7) + ((lane >> 4) & 1) * 8;
    const uint32_t kbCol = ((lane >> 3) & 1) * 8;
    const uint32_t vbRow = (lane & 7) + ((lane >> 3) & 1) * 8;
    const uint32_t vbCol = ((lane >> 4) & 1) * 8;

    for (int half = 0; half < 2; half++) {
        const int qt = half ? bx : (NQT - 1 - bx);
        const int q0 = qt * QT_ROWS;
        const int nkt = 2 * qt + 2;

        __syncthreads();   // prior half fully done with all smem

        // ---- load Q tile (128 rows): 1024 uint4, 4/thread ----
        #pragma unroll
        for (int i = 0; i < 4; i++) {
            int idx = tid + (i << 8);
            int r = idx >> 3, c8 = idx & 7;
            size_t gi = (size_t)(b * S_ + q0 + r) * 64 + h * 8 + c8;
            *reinterpret_cast<uint4*>(sm + QHI_O + (r * SK + c8 * 8) * 2) = Qh[gi];
        }

        float acc[32][4];
        #pragma unroll
        for (int i = 0; i < 32; i++)
            #pragma unroll
            for (int t = 0; t < 4; t++) acc[i][t] = 0.f;
        float m0 = -INFINITY, m1 = -INFINITY, l0 = 0.f, l1 = 0.f;

        const int rmin = q0 + wid * 16;
        const int rmax = rmin + 15;

        auto issueKV = [&](int kt) {
            const int s  = kt & 1;
            const int k0 = kt * 64;
            const uint32_t kb = smb + KHI_O + s * KST_SZ;
            const uint32_t vb = smb + VHI_O + s * VST_SZ;
            #pragma unroll
            for (int i = 0; i < 2; i++) {
                int idx = tid + (i << 8);
                int kk = idx >> 3, c8 = idx & 7;
                size_t gi = (size_t)(b * S_ + k0 + kk) * 64 + h * 8 + c8;
                cp16(kb + (kk * SK + c8 * 8) * 2, Kh + gi);
            }
            #pragma unroll
            for (int i = 0; i < 8; i++) {
                int idx = tid + (i << 8);
                int kk = idx >> 5, c8 = idx & 31;
                int g = c8 >> 3, d8 = c8 & 7;
                size_t gi = (size_t)(b * S_ + k0 + kk) * 256 + g * 64 + h * 8 + d8;
                cp16(vb + (kk * SV + c8 * 8) * 2, Vh + gi);
            }
            cp_commit();
        };

        issueKV(0);
        for (int kt = 0; kt < nkt; kt++) {
            const int k0 = kt * 64;
            __syncthreads();
            if (kt + 1 < nkt) issueKV(kt + 1);
            else              cp_commit();
            cp_wait<1>();
            __syncthreads();

            if (k0 > rmax) continue;

            const uint32_t kb = smb + KHI_O + (kt & 1) * KST_SZ;
            const uint32_t vb = smb + VHI_O + (kt & 1) * VST_SZ;

            // ---- QK^T: S(16x64) in registers ----
            float sfr[8][4];
            #pragma unroll
            for (int i = 0; i < 8; i++)
                #pragma unroll
                for (int t = 0; t < 4; t++) sfr[i][t] = 0.f;

            #pragma unroll
            for (int ks = 0; ks < 4; ks++) {
                uint32_t aH[4];
                uint32_t ao = ((wid * 16 + aRow) * SK + ks * 16 + aColH) * 2;
                ldmx4(aH, smb + QHI_O + ao);
                #pragma unroll
                for (int g4 = 0; g4 < 4; g4++) {
                    uint32_t bH[4];
                    uint32_t bo = ((g4 * 16 + kbRow) * SK + ks * 16 + kbCol) * 2;
                    ldmx4(bH, kb + bo);
                    mma16816h(sfr[g4*2+0], aH, bH);
                    mma16816h(sfr[g4*2+1], aH, bH + 2);
                }
            }

            // ---- causal mask (diagonal tiles only) ----
            if (k0 + 63 > rmin) {
                int grow0 = rmin + r0l, grow1 = grow0 + 8;
                #pragma unroll
                for (int nf = 0; nf < 8; nf++) {
                    int c = k0 + nf * 8 + cql;
                    if (c     > grow0) sfr[nf][0] = -INFINITY;
                    if (c + 1 > grow0) sfr[nf][1] = -INFINITY;
                    if (c     > grow1) sfr[nf][2] = -INFINITY;
                    if (c + 1 > grow1) sfr[nf][3] = -INFINITY;
                }
            }

            // ---- in-register online softmax ----
            float mx0 = -INFINITY, mx1 = -INFINITY;
            #pragma unroll
            for (int nf = 0; nf < 8; nf++) {
                mx0 = fmaxf(mx0, fmaxf(sfr[nf][0], sfr[nf][1]));
                mx1 = fmaxf(mx1, fmaxf(sfr[nf][2], sfr[nf][3]));
            }
            mx0 = fmaxf(mx0, __shfl_xor_sync(0xffffffffu, mx0, 1));
            mx0 = fmaxf(mx0, __shfl_xor_sync(0xffffffffu, mx0, 2));
            mx1 = fmaxf(mx1, __shfl_xor_sync(0xffffffffu, mx1, 1));
            mx1 = fmaxf(mx1, __shfl_xor_sync(0xffffffffu, mx1, 2));
            float mn0 = fmaxf(m0, mx0), mn1 = fmaxf(m1, mx1);
            float sc0 = __expf(m0 - mn0), sc1 = __expf(m1 - mn1);

            float sum0 = 0.f, sum1 = 0.f;
            uint32_t pa[4][4];
            #pragma unroll
            for (int nf = 0; nf < 8; nf++) {
                float p0 = __expf(sfr[nf][0] - mn0);
                float p1 = __expf(sfr[nf][1] - mn0);
                float p2 = __expf(sfr[nf][2] - mn1);
                float p3 = __expf(sfr[nf][3] - mn1);
                sum0 += p0 + p1;
                sum1 += p2 + p3;
                pa[nf >> 1][(nf & 1) * 2 + 0] = pack_hf2(p0, p1);
                pa[nf >> 1][(nf & 1) * 2 + 1] = pack_hf2(p2, p3);
            }
            sum0 += __shfl_xor_sync(0xffffffffu, sum0, 1);
            sum0 += __shfl_xor_sync(0xffffffffu, sum0, 2);
            sum1 += __shfl_xor_sync(0xffffffffu, sum1, 1);
            sum1 += __shfl_xor_sync(0xffffffffu, sum1, 2);
            l0 = l0 * sc0 + sum0;
            l1 = l1 * sc1 + sum1;
            m0 = mn0; m1 = mn1;

            // ---- rescale + PV ----
            #pragma unroll
            for (int i = 0; i < 32; i++) {
                acc[i][0] *= sc0; acc[i][1] *= sc0;
                acc[i][2] *= sc1; acc[i][3] *= sc1;
            }
            #pragma unroll
            for (int ks = 0; ks < 4; ks++) {
                #pragma unroll
                for (int g = 0; g < 16; g++) {
                    uint32_t vH[4];
                    uint32_t bo = ((ks * 16 + vbRow) * SV + g * 16 + vbCol) * 2;
                    ldmx4t(vH, vb + bo);
                    mma16816h(acc[g*2+0], pa[ks], vH);
                    mma16816h(acc[g*2+1], pa[ks], vH + 2);
                }
            }
        }

        // ---- normalize + store ----
        {
            float invl0 = 1.f / l0;
            float invl1 = 1.f / l1;
            int row0 = q0 + wid * 16 + r0l;
            int row1 = row0 + 8;
            #pragma unroll
            for (int nf = 0; nf < 32; nf++) {
                int cl = nf * 8 + cql;
                int g  = cl >> 6, d = cl & 63;
                size_t ob0 = ((size_t)(b * S_ + row0)) * HID_ + (g * HKV_ + h) * HD_ + d;
                size_t ob1 = ((size_t)(b * S_ + row1)) * HID_ + (g * HKV_ + h) * HD_ + d;
                *reinterpret_cast<float2*>(&Out[ob0]) =
                    make_float2(acc[nf][0] * invl0, acc[nf][1] * invl0);
                *reinterpret_cast<float2*>(&Out[ob1]) =
                    make_float2(acc[nf][2] * invl1, acc[nf][3] * invl1);
            }
        }
    }
}

// ---------------------------------------------------------------------------
extern "C" void kernel_launch(void* const* d_in, const int* in_sizes, int n_in,
                              void* d_out, int out_size) {
    const float* X   = (const float*)d_in[0];
    const int*   pid = (const int*)  d_in[1];
    const float* Wq  = (const float*)d_in[2];
    const float* Wk  = (const float*)d_in[3];
    const float* Wv  = (const float*)d_in[4];
    float* Out = (float*)d_out;

    uint4 *qh, *kh, *vh;
    cudaGetSymbolAddress((void**)&qh, g_Qh);
    cudaGetSymbolAddress((void**)&kh, g_Kh);
    cudaGetSymbolAddress((void**)&vh, g_Vh);
    uint2 *xh, *wqh, *wkh, *wvh;
    cudaGetSymbolAddress((void**)&xh,  g_Xh);
    cudaGetSymbolAddress((void**)&wqh, g_Wqh);
    cudaGetSymbolAddress((void**)&wkh, g_Wkh);
    cudaGetSymbolAddress((void**)&wvh, g_Wvh);

    // Fused pre-convert
    {
        int nX4 = M_ * HID_ / 4;
        dim3 grd((nX4 + 255) / 256, 4);
        cvt_all_kernel<<<grd, 256>>>((const float4*)X, (const float4*)Wq,
                                     (const float4*)Wk, (const float4*)Wv,
                                     xh, wqh, wkh, wvh);
    }
    // Fused projections + in-epilogue RoPE (Q/K) and fp16 outputs
    {
        cudaFuncSetAttribute(gemm_fused_kernel,
                             cudaFuncAttributeMaxDynamicSharedMemorySize, GEMM_SMEM);
        dim3 grd(12, M_ / 128);
        gemm_fused_kernel<<<grd, 256, GEMM_SMEM>>>(
            (const char*)xh, (const char*)wqh, (__half*)qh,
            (const char*)wkh, (__half*)kh, (const char*)wvh, (__half*)vh, pid);
    }
    // Attention (FA2-style, paired-balanced scheduling)
    {
        cudaFuncSetAttribute(attn_mma_kernel,
                             cudaFuncAttributeMaxDynamicSharedMemorySize, ATTN_SMEM);
        dim3 grd(NQT / 2, HKV_, B_);
        attn_mma_kernel<<<grd, 256, ATTN_SMEM>>>(qh, kh, vh, Out);
    }
}

// round 15
// speedup vs baseline: 11.1976x; 1.0997x over previous
#include <cuda_runtime.h>
#include <cuda_fp16.h>
#include <math.h>
#include <stdint.h>

#define B_   2
#define S_   2048
#define HID_ 2048
#define NH_  32
#define G_   4
#define HD_  64
#define HKV_ 8
#define NQK_ 512   // HKV_*HD_
#define M_   (B_ * S_)   // 4096

// fp16 post-rope / projected tensors
__device__ uint4 g_Qh[(size_t)M_*NQK_/8];
__device__ uint4 g_Kh[(size_t)M_*NQK_/8];
__device__ uint4 g_Vh[(size_t)M_*HID_/8];
// fp16 pre-converted GEMM operands
__device__ uint2 g_Xh[(size_t)M_*HID_/4];
__device__ uint2 g_Wqh[(size_t)HID_*NQK_/4];
__device__ uint2 g_Wkh[(size_t)HID_*NQK_/4];
__device__ uint2 g_Wvh[(size_t)HID_*HID_/4];

// ===========================================================================
// helpers
// ===========================================================================
__device__ __forceinline__ uint32_t smem_to_u32(const void* smem_ptr) {
    uint32_t addr;
    asm("{ .reg .u64 tmp; cvta.to.shared.u64 tmp, %1; cvt.u32.u64 %0, tmp; }"
        : "=r"(addr) : "l"(smem_ptr));
    return addr;
}
__device__ __forceinline__ uint32_t pack_hf2(float a, float b) {
    uint32_t r;
    asm("cvt.rn.f16x2.f32 %0, %1, %2;" : "=r"(r) : "f"(b), "f"(a));
    return r;
}
__device__ __forceinline__ void ldmx4(uint32_t r[4], uint32_t addr) {
    asm volatile("ldmatrix.sync.aligned.m8n8.x4.shared.b16 {%0,%1,%2,%3}, [%4];"
        : "=r"(r[0]), "=r"(r[1]), "=r"(r[2]), "=r"(r[3]) : "r"(addr));
}
__device__ __forceinline__ void ldmx4t(uint32_t r[4], uint32_t addr) {
    asm volatile("ldmatrix.sync.aligned.m8n8.x4.trans.shared.b16 {%0,%1,%2,%3}, [%4];"
        : "=r"(r[0]), "=r"(r[1]), "=r"(r[2]), "=r"(r[3]) : "r"(addr));
}
__device__ __forceinline__ void mma16816h(float d[4], const uint32_t a[4],
                                          const uint32_t b[2]) {
    asm volatile(
        "mma.sync.aligned.m16n8k16.row.col.f32.f16.f16.f32 "
        "{%0,%1,%2,%3}, {%4,%5,%6,%7}, {%8,%9}, {%0,%1,%2,%3};"
        : "+f"(d[0]), "+f"(d[1]), "+f"(d[2]), "+f"(d[3])
        : "r"(a[0]), "r"(a[1]), "r"(a[2]), "r"(a[3]), "r"(b[0]), "r"(b[1]));
}
__device__ __forceinline__ void cp16(uint32_t dst, const void* src) {
    asm volatile("cp.async.cg.shared.global [%0], [%1], 16;"
                 :: "r"(dst), "l"(src));
}
__device__ __forceinline__ void cp_commit() {
    asm volatile("cp.async.commit_group;" ::: "memory");
}
template <int N>
__device__ __forceinline__ void cp_wait() {
    asm volatile("cp.async.wait_group %0;" :: "n"(N) : "memory");
}

// ===========================================================================
// Fused pre-convert fp32 -> fp16 (X, Wq, Wk, Wv in one launch, 2 f4/thread)
// ===========================================================================
__global__ __launch_bounds__(256)
void cvt_all_kernel(const float4* __restrict__ X,
                    const float4* __restrict__ Wq,
                    const float4* __restrict__ Wk,
                    const float4* __restrict__ Wv,
                    uint2* __restrict__ xh, uint2* __restrict__ wqh,
                    uint2* __restrict__ wkh, uint2* __restrict__ wvh) {
    const float4* src;
    uint2* dst;
    int n4;
    switch (blockIdx.y) {
        case 0: src = X;  dst = xh;  n4 = M_ * HID_ / 4;   break;
        case 1: src = Wq; dst = wqh; n4 = HID_ * NQK_ / 4; break;
        case 2: src = Wk; dst = wkh; n4 = HID_ * NQK_ / 4; break;
        default: src = Wv; dst = wvh; n4 = HID_ * HID_ / 4; break;
    }
    int i = (blockIdx.x * blockDim.x + threadIdx.x) * 2;
    if (i >= n4) return;
    float4 v0 = src[i];
    float4 v1 = src[i + 1];   // n4 always even here
    dst[i]     = make_uint2(pack_hf2(v0.x, v0.y), pack_hf2(v0.z, v0.w));
    dst[i + 1] = make_uint2(pack_hf2(v1.x, v1.y), pack_hf2(v1.z, v1.w));
}

// ===========================================================================
// Fused 1-term fp16 GEMM, CTA tile 128x128, warp 32x64 (4m x 2n), occ 2.
// blockIdx.x: 0-3 -> Q (rope+scale out), 4-7 -> K (rope out), 8-23 -> V.
// ===========================================================================
#define SAe 40
#define SBe2 136
#define ST_AHI 0
#define ST_BHI 10240
#define ST_SZ  18944          // 10240 (A) + 8704 (B: 32 x 272B)
#define NSTG 4
#define GEMM_SMEM (NSTG * ST_SZ)   // 75776

__global__ __launch_bounds__(256, 2)
void gemm_fused_kernel(const char* __restrict__ Ah,
                       const char* __restrict__ BhQ, __half* __restrict__ CQ,
                       const char* __restrict__ BhK, __half* __restrict__ CK,
                       const char* __restrict__ BhV, __half* __restrict__ CV,
                       const int* __restrict__ pid) {
    extern __shared__ char sm[];
    const uint32_t smb = smem_to_u32(sm);
    const int tid = threadIdx.x, lane = tid & 31, wid = tid >> 5;
    const int wm = wid >> 1, wn = wid & 1;   // 4m x 2n
    const int m0 = blockIdx.y * 128;
    const int nb = blockIdx.x;

    const char* Bh;
    __half* C;
    int N, n0;
    if (nb < 4)       { Bh = BhQ; C = CQ; N = NQK_; n0 = nb * 128; }
    else if (nb < 8)  { Bh = BhK; C = CK; N = NQK_; n0 = (nb - 4) * 128; }
    else              { Bh = BhV; C = CV; N = HID_; n0 = (nb - 8) * 128; }
    const int K = HID_;

    float acc[2][8][4];
    #pragma unroll
    for (int i = 0; i < 2; i++)
        #pragma unroll
        for (int j = 0; j < 8; j++)
            #pragma unroll
            for (int t = 0; t < 4; t++) acc[i][j][t] = 0.f;

    const uint32_t aRow  = lane & 15;
    const uint32_t aColH = (lane >> 4) * 8;
    const uint32_t bRow  = (lane & 7) + ((lane >> 3) & 1) * 8;
    const uint32_t bCol  = ((lane >> 4) & 1) * 8;
    const int nch = K >> 5;

    auto issue = [&](int s, int k0) {
        uint32_t sb = smb + s * ST_SZ;
        // A: 128x32 fp16 = 512 x 16B, 2/thread
        #pragma unroll
        for (int i = 0; i < 2; i++) {
            int idx = tid + (i << 8);
            int row = idx >> 2, seg = idx & 3;
            size_t go = ((size_t)(m0 + row) * K + k0 + seg * 8) * 2;
            cp16(sb + ST_AHI + row * 80 + seg * 16, Ah + go);
        }
        // B: 32x128 fp16 = 512 x 16B, 2/thread
        #pragma unroll
        for (int i = 0; i < 2; i++) {
            int idx = tid + (i << 8);
            int row = idx >> 4, seg = idx & 15;
            size_t go = ((size_t)(k0 + row) * N + n0 + seg * 8) * 2;
            cp16(sb + ST_BHI + row * 272 + seg * 16, Bh + go);
        }
        cp_commit();
    };

    issue(0, 0);
    issue(1, 32);
    for (int c = 0; c < nch; c++) {
        if (c + 2 < nch) issue((c + 2) & (NSTG - 1), (c + 2) << 5);
        else             cp_commit();
        cp_wait<2>();
        __syncthreads();

        const uint32_t sb = smb + (c & (NSTG - 1)) * ST_SZ;
        #pragma unroll
        for (int ks = 0; ks < 2; ks++) {
            uint32_t aH[2][4];
            #pragma unroll
            for (int mf = 0; mf < 2; mf++) {
                uint32_t ao = ((wm * 32 + mf * 16 + aRow) * SAe + ks * 16 + aColH) * 2;
                ldmx4(aH[mf], sb + ST_AHI + ao);
            }
            uint32_t bH[4][4];
            #pragma unroll
            for (int ng = 0; ng < 4; ng++) {
                uint32_t bo = ((ks * 16 + bRow) * SBe2 + wn * 64 + ng * 16 + bCol) * 2;
                ldmx4t(bH[ng], sb + ST_BHI + bo);
            }
            #pragma unroll
            for (int mf = 0; mf < 2; mf++)
                #pragma unroll
                for (int ng = 0; ng < 4; ng++) {
                    mma16816h(acc[mf][ng*2+0], aH[mf], bH[ng]);
                    mma16816h(acc[mf][ng*2+1], aH[mf], bH[ng] + 2);
                }
        }
    }

    if (nb >= 8) {
        // V: plain fp16 store
        #pragma unroll
        for (int mf = 0; mf < 2; mf++) {
            int row = m0 + wm * 32 + mf * 16 + (lane >> 2);
            #pragma unroll
            for (int nf = 0; nf < 8; nf++) {
                int col = n0 + wn * 64 + nf * 8 + (lane & 3) * 2;
                *reinterpret_cast<uint32_t*>(C + (size_t)row * N + col) =
                    pack_hf2(acc[mf][nf][0], acc[mf][nf][1]);
                *reinterpret_cast<uint32_t*>(C + (size_t)(row + 8) * N + col) =
                    pack_hf2(acc[mf][nf][2], acc[mf][nf][3]);
            }
        }
    } else {
        // Q/K: in-register RoPE (warp n-tile 64 == one head; (d,d+32) partners
        // are acc[mf][nf] / acc[mf][nf+4] of the same thread), then fp16 store.
        const float qscale = (nb < 4) ? 0.125f : 1.0f;
        float inv0[4], inv1[4];
        #pragma unroll
        for (int nf = 0; nf < 4; nf++) {
            int d = nf * 8 + (lane & 3) * 2;
            inv0[nf] = powf(10000.0f, -(float)d       * (1.0f / 32.0f));
            inv1[nf] = powf(10000.0f, -(float)(d + 1) * (1.0f / 32.0f));
        }
        #pragma unroll
        for (int mf = 0; mf < 2; mf++) {
            int row = m0 + wm * 32 + mf * 16 + (lane >> 2);
            float pos0 = (float)pid[row];
            float pos1 = (float)pid[row + 8];
            #pragma unroll
            for (int nf = 0; nf < 4; nf++) {
                int col = n0 + wn * 64 + nf * 8 + (lane & 3) * 2;
                float s00, c00, s01, c01, s10, c10, s11, c11;
                sincosf(pos0 * inv0[nf], &s00, &c00);
                sincosf(pos0 * inv1[nf], &s01, &c01);
                sincosf(pos1 * inv0[nf], &s10, &c10);
                sincosf(pos1 * inv1[nf], &s11, &c11);
                float x0a = acc[mf][nf][0],   x0b = acc[mf][nf][1];
                float x1a = acc[mf][nf][2],   x1b = acc[mf][nf][3];
                float y0a = acc[mf][nf+4][0], y0b = acc[mf][nf+4][1];
                float y1a = acc[mf][nf+4][2], y1b = acc[mf][nf+4][3];
                float r0a = (x0a * c00 - y0a * s00) * qscale;
                float r0b = (x0b * c01 - y0b * s01) * qscale;
                float u0a = (y0a * c00 + x0a * s00) * qscale;
                float u0b = (y0b * c01 + x0b * s01) * qscale;
                float r1a = (x1a * c10 - y1a * s10) * qscale;
                float r1b = (x1b * c11 - y1b * s11) * qscale;
                float u1a = (y1a * c10 + x1a * s10) * qscale;
                float u1b = (y1b * c11 + x1b * s11) * qscale;
                __half* Cr0 = C + (size_t)row * N;
                __half* Cr1 = C + (size_t)(row + 8) * N;
                *reinterpret_cast<uint32_t*>(Cr0 + col)      = pack_hf2(r0a, r0b);
                *reinterpret_cast<uint32_t*>(Cr0 + col + 32) = pack_hf2(u0a, u0b);
                *reinterpret_cast<uint32_t*>(Cr1 + col)      = pack_hf2(r1a, r1b);
                *reinterpret_cast<uint32_t*>(Cr1 + col + 32) = pack_hf2(u1a, u1b);
            }
        }
    }
}

// ===========================================================================
// FA2-style flash attention, paired scheduling (unchanged from R14).
// 1-term QK + 1-term PV, cp.async K/V double buffer. smem ~102 KB, 1 CTA/SM.
// ===========================================================================
#define SK   72
#define SV   264
#define QHI_O 0
#define KST_SZ 9216
#define VST_SZ 33792
#define KHI_O 18432
#define VHI_O (18432 + 2 * KST_SZ)               // 36864
#define ATTN_SMEM (VHI_O + 2 * VST_SZ)           // 104448
#define QT_ROWS 128
#define NQT (S_ / QT_ROWS)                       // 16

__global__ __launch_bounds__(256, 1)
void attn_mma_kernel(const uint4* __restrict__ Qh,
                     const uint4* __restrict__ Kh, const uint4* __restrict__ Vh,
                     float* __restrict__ Out) {
    extern __shared__ char sm[];
    const uint32_t smb = smem_to_u32(sm);
    const int tid = threadIdx.x, lane = tid & 31, wid = tid >> 5;
    const int b  = blockIdx.z;
    const int h  = blockIdx.y;
    const int bx = blockIdx.x;   // 0..7

    const int r0l = lane >> 2;
    const int cql = (lane & 3) * 2;
    const uint32_t aRow  = lane & 15;
    const uint32_t aColH = (lane >> 4) * 8;
    const uint32_t kbRow = (lane & 7) + ((lane >> 4) & 1) * 8;
    const uint32_t kbCol = ((lane >> 3) & 1) * 8;
    const uint32_t vbRow = (lane & 7) + ((lane >> 3) & 1) * 8;
    const uint32_t vbCol = ((lane >> 4) & 1) * 8;

    for (int half = 0; half < 2; half++) {
        const int qt = half ? bx : (NQT - 1 - bx);
        const int q0 = qt * QT_ROWS;
        const int nkt = 2 * qt + 2;

        __syncthreads();   // prior half fully done with all smem

        #pragma unroll
        for (int i = 0; i < 4; i++) {
            int idx = tid + (i << 8);
            int r = idx >> 3, c8 = idx & 7;
            size_t gi = (size_t)(b * S_ + q0 + r) * 64 + h * 8 + c8;
            *reinterpret_cast<uint4*>(sm + QHI_O + (r * SK + c8 * 8) * 2) = Qh[gi];
        }

        float acc[32][4];
        #pragma unroll
        for (int i = 0; i < 32; i++)
            #pragma unroll
            for (int t = 0; t < 4; t++) acc[i][t] = 0.f;
        float m0 = -INFINITY, m1 = -INFINITY, l0 = 0.f, l1 = 0.f;

        const int rmin = q0 + wid * 16;
        const int rmax = rmin + 15;

        auto issueKV = [&](int kt) {
            const int s  = kt & 1;
            const int k0 = kt * 64;
            const uint32_t kb = smb + KHI_O + s * KST_SZ;
            const uint32_t vb = smb + VHI_O + s * VST_SZ;
            #pragma unroll
            for (int i = 0; i < 2; i++) {
                int idx = tid + (i << 8);
                int kk = idx >> 3, c8 = idx & 7;
                size_t gi = (size_t)(b * S_ + k0 + kk) * 64 + h * 8 + c8;
                cp16(kb + (kk * SK + c8 * 8) * 2, Kh + gi);
            }
            #pragma unroll
            for (int i = 0; i < 8; i++) {
                int idx = tid + (i << 8);
                int kk = idx >> 5, c8 = idx & 31;
                int g = c8 >> 3, d8 = c8 & 7;
                size_t gi = (size_t)(b * S_ + k0 + kk) * 256 + g * 64 + h * 8 + d8;
                cp16(vb + (kk * SV + c8 * 8) * 2, Vh + gi);
            }
            cp_commit();
        };

        issueKV(0);
        for (int kt = 0; kt < nkt; kt++) {
            const int k0 = kt * 64;
            __syncthreads();
            if (kt + 1 < nkt) issueKV(kt + 1);
            else              cp_commit();
            cp_wait<1>();
            __syncthreads();

            if (k0 > rmax) continue;

            const uint32_t kb = smb + KHI_O + (kt & 1) * KST_SZ;
            const uint32_t vb = smb + VHI_O + (kt & 1) * VST_SZ;

            float sfr[8][4];
            #pragma unroll
            for (int i = 0; i < 8; i++)
                #pragma unroll
                for (int t = 0; t < 4; t++) sfr[i][t] = 0.f;

            #pragma unroll
            for (int ks = 0; ks < 4; ks++) {
                uint32_t aH[4];
                uint32_t ao = ((wid * 16 + aRow) * SK + ks * 16 + aColH) * 2;
                ldmx4(aH, smb + QHI_O + ao);
                #pragma unroll
                for (int g4 = 0; g4 < 4; g4++) {
                    uint32_t bH[4];
                    uint32_t bo = ((g4 * 16 + kbRow) * SK + ks * 16 + kbCol) * 2;
                    ldmx4(bH, kb + bo);
                    mma16816h(sfr[g4*2+0], aH, bH);
                    mma16816h(sfr[g4*2+1], aH, bH + 2);
                }
            }

            if (k0 + 63 > rmin) {
                int grow0 = rmin + r0l, grow1 = grow0 + 8;
                #pragma unroll
                for (int nf = 0; nf < 8; nf++) {
                    int c = k0 + nf * 8 + cql;
                    if (c     > grow0) sfr[nf][0] = -INFINITY;
                    if (c + 1 > grow0) sfr[nf][1] = -INFINITY;
                    if (c     > grow1) sfr[nf][2] = -INFINITY;
                    if (c + 1 > grow1) sfr[nf][3] = -INFINITY;
                }
            }

            float mx0 = -INFINITY, mx1 = -INFINITY;
            #pragma unroll
            for (int nf = 0; nf < 8; nf++) {
                mx0 = fmaxf(mx0, fmaxf(sfr[nf][0], sfr[nf][1]));
                mx1 = fmaxf(mx1, fmaxf(sfr[nf][2], sfr[nf][3]));
            }
            mx0 = fmaxf(mx0, __shfl_xor_sync(0xffffffffu, mx0, 1));
            mx0 = fmaxf(mx0, __shfl_xor_sync(0xffffffffu, mx0, 2));
            mx1 = fmaxf(mx1, __shfl_xor_sync(0xffffffffu, mx1, 1));
            mx1 = fmaxf(mx1, __shfl_xor_sync(0xffffffffu, mx1, 2));
            float mn0 = fmaxf(m0, mx0), mn1 = fmaxf(m1, mx1);
            float sc0 = __expf(m0 - mn0), sc1 = __expf(m1 - mn1);

            float sum0 = 0.f, sum1 = 0.f;
            uint32_t pa[4][4];
            #pragma unroll
            for (int nf = 0; nf < 8; nf++) {
                float p0 = __expf(sfr[nf][0] - mn0);
                float p1 = __expf(sfr[nf][1] - mn0);
                float p2 = __expf(sfr[nf][2] - mn1);
                float p3 = __expf(sfr[nf][3] - mn1);
                sum0 += p0 + p1;
                sum1 += p2 + p3;
                pa[nf >> 1][(nf & 1) * 2 + 0] = pack_hf2(p0, p1);
                pa[nf >> 1][(nf & 1) * 2 + 1] = pack_hf2(p2, p3);
            }
            sum0 += __shfl_xor_sync(0xffffffffu, sum0, 1);
            sum0 += __shfl_xor_sync(0xffffffffu, sum0, 2);
            sum1 += __shfl_xor_sync(0xffffffffu, sum1, 1);
            sum1 += __shfl_xor_sync(0xffffffffu, sum1, 2);
            l0 = l0 * sc0 + sum0;
            l1 = l1 * sc1 + sum1;
            m0 = mn0; m1 = mn1;

            #pragma unroll
            for (int i = 0; i < 32; i++) {
                acc[i][0] *= sc0; acc[i][1] *= sc0;
                acc[i][2] *= sc1; acc[i][3] *= sc1;
            }
            #pragma unroll
            for (int ks = 0; ks < 4; ks++) {
                #pragma unroll
                for (int g = 0; g < 16; g++) {
                    uint32_t vH[4];
                    uint32_t bo = ((ks * 16 + vbRow) * SV + g * 16 + vbCol) * 2;
                    ldmx4t(vH, vb + bo);
                    mma16816h(acc[g*2+0], pa[ks], vH);
                    mma16816h(acc[g*2+1], pa[ks], vH + 2);
                }
            }
        }

        {
            float invl0 = 1.f / l0;
            float invl1 = 1.f / l1;
            int row0 = q0 + wid * 16 + r0l;
            int row1 = row0 + 8;
            #pragma unroll
            for (int nf = 0; nf < 32; nf++) {
                int cl = nf * 8 + cql;
                int g  = cl >> 6, d = cl & 63;
                size_t ob0 = ((size_t)(b * S_ + row0)) * HID_ + (g * HKV_ + h) * HD_ + d;
                size_t ob1 = ((size_t)(b * S_ + row1)) * HID_ + (g * HKV_ + h) * HD_ + d;
                *reinterpret_cast<float2*>(&Out[ob0]) =
                    make_float2(acc[nf][0] * invl0, acc[nf][1] * invl0);
                *reinterpret_cast<float2*>(&Out[ob1]) =
                    make_float2(acc[nf][2] * invl1, acc[nf][3] * invl1);
            }
        }
    }
}

// ---------------------------------------------------------------------------
extern "C" void kernel_launch(void* const* d_in, const int* in_sizes, int n_in,
                              void* d_out, int out_size) {
    const float* X   = (const float*)d_in[0];
    const int*   pid = (const int*)  d_in[1];
    const float* Wq  = (const float*)d_in[2];
    const float* Wk  = (const float*)d_in[3];
    const float* Wv  = (const float*)d_in[4];
    float* Out = (float*)d_out;

    uint4 *qh, *kh, *vh;
    cudaGetSymbolAddress((void**)&qh, g_Qh);
    cudaGetSymbolAddress((void**)&kh, g_Kh);
    cudaGetSymbolAddress((void**)&vh, g_Vh);
    uint2 *xh, *wqh, *wkh, *wvh;
    cudaGetSymbolAddress((void**)&xh,  g_Xh);
    cudaGetSymbolAddress((void**)&wqh, g_Wqh);
    cudaGetSymbolAddress((void**)&wkh, g_Wkh);
    cudaGetSymbolAddress((void**)&wvh, g_Wvh);

    // Fused pre-convert (2 float4 per thread)
    {
        int nX4 = M_ * HID_ / 4;
        dim3 grd((nX4 / 2 + 255) / 256, 4);
        cvt_all_kernel<<<grd, 256>>>((const float4*)X, (const float4*)Wq,
                                     (const float4*)Wk, (const float4*)Wv,
                                     xh, wqh, wkh, wvh);
    }
    // Fused projections + in-epilogue RoPE, CTA 128x128 occ-2
    {
        cudaFuncSetAttribute(gemm_fused_kernel,
                             cudaFuncAttributeMaxDynamicSharedMemorySize, GEMM_SMEM);
        dim3 grd(24, M_ / 128);
        gemm_fused_kernel<<<grd, 256, GEMM_SMEM>>>(
            (const char*)xh, (const char*)wqh, (__half*)qh,
            (const char*)wkh, (__half*)kh, (const char*)wvh, (__half*)vh, pid);
    }
    // Attention (FA2-style, paired-balanced scheduling)
    {
        cudaFuncSetAttribute(attn_mma_kernel,
                             cudaFuncAttributeMaxDynamicSharedMemorySize, ATTN_SMEM);
        dim3 grd(NQT / 2, HKV_, B_);
        attn_mma_kernel<<<grd, 256, ATTN_SMEM>>>(qh, kh, vh, Out);
    }
}